// round 1
// baseline (speedup 1.0000x reference)
#include <cuda_runtime.h>
#include <math.h>
#include <stdint.h>

// ---------------- problem constants ----------------
#define Bsz 2048
#define Ssz 64
#define Cin 142
#define Dm  256
#define NH  8
#define DHd 32
#define FFd 512
#define NL  3
#define Ed  128
#define Kcb 1024
#define Tt  65          // S+1
#define MTOK (Bsz*Tt)   // 133120
#define LN_EPS 1e-5f

// ---------------- scratch (device globals; no allocation allowed) ----------------
__device__ float g_h   [(size_t)Bsz*Tt*Dm];      // 136 MB
__device__ float g_qkv [(size_t)Bsz*Tt*3*Dm];    // 409 MB
__device__ float g_attn[(size_t)Bsz*Tt*Dm];      // 136 MB
__device__ float g_tmp [(size_t)Bsz*Tt*Dm];      // 136 MB
__device__ float g_ff  [(size_t)Bsz*Tt*FFd];     // 272 MB
__device__ float g_ze  [(size_t)Bsz*Ed];
__device__ int   g_idx [Bsz];
__device__ float g_cnorm[Kcb];
__device__ int   g_hist[Kcb];
__device__ float g_losspart[Bsz];

// ---------------- helpers ----------------
__device__ __forceinline__ float gelu_exact(float x) {
    return 0.5f * x * (1.0f + erff(x * 0.7071067811865475f));
}

// block-wide sum for 256 threads, result broadcast to all threads
__device__ __forceinline__ float bred256(float v, float* sm) {
    int tid = threadIdx.x;
    #pragma unroll
    for (int o = 16; o > 0; o >>= 1) v += __shfl_down_sync(0xffffffffu, v, o);
    if ((tid & 31) == 0) sm[tid >> 5] = v;
    __syncthreads();
    if (tid == 0) {
        float t = 0.f;
        #pragma unroll
        for (int i = 0; i < 8; i++) t += sm[i];
        sm[0] = t;
    }
    __syncthreads();
    float r = sm[0];
    __syncthreads();
    return r;
}

__device__ __forceinline__ float pe_val(int s, int c) {
    int j = c >> 1;
    // div = exp(2j * (-ln(10000)/256))
    float freq = expf(-(float)(2 * j) * (9.210340371976184f / 256.0f));
    float ang = (float)s * freq;
    return (c & 1) ? cosf(ang) : sinf(ang);
}

// ---------------- GEMM: C[M,N] = A[M,K] @ W[N,K]^T + bias ----------------
// EPI: 0 = none, 1 = exact gelu, 2 = +positional-encoding and remap rows
//      (input projection: in-row m = b*64+s  ->  out-row b*65 + 1 + s, N must be 256)
#define BM 64
#define BN 64
#define BK 16
template <int EPI>
__global__ __launch_bounds__(256) void gemm_k(
    const float* __restrict__ A, const float* __restrict__ W,
    const float* __restrict__ bias, float* __restrict__ C,
    int M, int N, int K)
{
    __shared__ float As[BK][BM];
    __shared__ float Bs[BK][BN];

    const int tid  = threadIdx.x;
    const int row0 = blockIdx.y * BM;
    const int col0 = blockIdx.x * BN;
    const int tx = tid & 15;
    const int ty = tid >> 4;

    float acc[4][4];
    #pragma unroll
    for (int i = 0; i < 4; i++)
        #pragma unroll
        for (int j = 0; j < 4; j++) acc[i][j] = 0.f;

    for (int k0 = 0; k0 < K; k0 += BK) {
        #pragma unroll
        for (int i = 0; i < 4; i++) {
            int idx = tid + i * 256;
            int r  = idx >> 4;
            int kk = idx & 15;
            int kg = k0 + kk;
            float av = 0.f, bv = 0.f;
            if (kg < K) {
                av = A[(size_t)(row0 + r) * K + kg];
                bv = W[(size_t)(col0 + r) * K + kg];
            }
            As[kk][r] = av;
            Bs[kk][r] = bv;
        }
        __syncthreads();

        #pragma unroll
        for (int kk = 0; kk < BK; kk++) {
            float4 a4 = *reinterpret_cast<const float4*>(&As[kk][ty << 2]);
            float4 b4 = *reinterpret_cast<const float4*>(&Bs[kk][tx << 2]);
            float a[4] = {a4.x, a4.y, a4.z, a4.w};
            float b[4] = {b4.x, b4.y, b4.z, b4.w};
            #pragma unroll
            for (int i = 0; i < 4; i++)
                #pragma unroll
                for (int j = 0; j < 4; j++) acc[i][j] += a[i] * b[j];
        }
        __syncthreads();
    }

    #pragma unroll
    for (int i = 0; i < 4; i++) {
        int r = row0 + (ty << 2) + i;
        #pragma unroll
        for (int j = 0; j < 4; j++) {
            int c = col0 + (tx << 2) + j;
            float v = acc[i][j] + bias[c];
            if (EPI == 1) v = gelu_exact(v);
            size_t out;
            if (EPI == 2) {
                int s  = r & 63;
                int bb = r >> 6;
                v += pe_val(s, c);
                out = ((size_t)bb * Tt + 1 + s) * Dm + c;
            } else {
                out = (size_t)r * N + c;
            }
            C[out] = v;
        }
    }
}

// ---------------- cls token fill ----------------
__global__ __launch_bounds__(256) void cls_fill_k(const float* __restrict__ cls) {
    g_h[(size_t)blockIdx.x * Tt * Dm + threadIdx.x] = cls[threadIdx.x];
}

// ---------------- attention: one block per (batch, head) ----------------
__global__ __launch_bounds__(128) void attn_k(
    const float* __restrict__ qkv, float* __restrict__ outp)
{
    const int b  = blockIdx.x >> 3;
    const int hh = blockIdx.x & 7;
    const float* base = qkv + (size_t)b * Tt * (3 * Dm) + hh * DHd;

    __shared__ float q [Tt][33];
    __shared__ float kt[Tt][33];
    __shared__ float vt[Tt][33];
    __shared__ float sc[Tt * Tt];

    const int tid = threadIdx.x;

    for (int idx = tid; idx < Tt * DHd; idx += 128) {
        int t = idx >> 5, d = idx & 31;
        const float* r = base + (size_t)t * (3 * Dm);
        q [t][d] = r[d];
        kt[t][d] = r[Dm + d];
        vt[t][d] = r[2 * Dm + d];
    }
    __syncthreads();

    const float scale = 0.17677669529663689f; // 1/sqrt(32)
    for (int idx = tid; idx < Tt * Tt; idx += 128) {
        int i = idx / Tt, j = idx - i * Tt;
        float s = 0.f;
        #pragma unroll
        for (int d = 0; d < DHd; d++) s += q[i][d] * kt[j][d];
        sc[idx] = s * scale;
    }
    __syncthreads();

    if (tid < Tt) {
        float m = -3.4e38f;
        for (int j = 0; j < Tt; j++) m = fmaxf(m, sc[tid * Tt + j]);
        float ssum = 0.f;
        for (int j = 0; j < Tt; j++) {
            float e = expf(sc[tid * Tt + j] - m);
            sc[tid * Tt + j] = e;
            ssum += e;
        }
        float inv = 1.0f / ssum;
        for (int j = 0; j < Tt; j++) sc[tid * Tt + j] *= inv;
    }
    __syncthreads();

    for (int idx = tid; idx < Tt * DHd; idx += 128) {
        int i = idx >> 5, d = idx & 31;
        float o = 0.f;
        for (int j = 0; j < Tt; j++) o += sc[i * Tt + j] * vt[j][d];
        outp[((size_t)b * Tt + i) * Dm + hh * DHd + d] = o;
    }
}

// ---------------- residual add + LayerNorm (in place on g_h) ----------------
__global__ __launch_bounds__(256) void add_ln_k(
    float* __restrict__ h, const float* __restrict__ t,
    const float* __restrict__ g, const float* __restrict__ bb)
{
    __shared__ float sm[32];
    const int tid = threadIdx.x;
    const size_t base = (size_t)blockIdx.x * Dm;
    float v = h[base + tid] + t[base + tid];
    float mean = bred256(v, sm) * (1.0f / Dm);
    float d = v - mean;
    float var = bred256(d * d, sm) * (1.0f / Dm);
    h[base + tid] = d * rsqrtf(var + LN_EPS) * g[tid] + bb[tid];
}

// ---------------- final head: LN(cls) @ W_out^T + b_out -> g_ze ----------------
__global__ __launch_bounds__(256) void final_head_k(
    const float* __restrict__ lnfg, const float* __restrict__ lnfb,
    const float* __restrict__ Wout, const float* __restrict__ bout)
{
    __shared__ float xn[Dm];
    __shared__ float sm[32];
    const int tid = threadIdx.x;
    const int b = blockIdx.x;
    float v = g_h[(size_t)b * Tt * Dm + tid];          // row t=0 (cls)
    float mean = bred256(v, sm) * (1.0f / Dm);
    float d = v - mean;
    float var = bred256(d * d, sm) * (1.0f / Dm);
    xn[tid] = d * rsqrtf(var + LN_EPS) * lnfg[tid] + lnfb[tid];
    __syncthreads();
    if (tid < Ed) {
        const float* w = Wout + (size_t)tid * Dm;
        float a = bout[tid];
        #pragma unroll 8
        for (int t = 0; t < Dm; t++) a += xn[t] * w[t];
        g_ze[(size_t)b * Ed + tid] = a;
    }
}

// ---------------- codebook squared norms ----------------
__global__ __launch_bounds__(128) void cnorm_k(const float* __restrict__ cb) {
    __shared__ float sm[4];
    const int tid = threadIdx.x;
    float v = cb[(size_t)blockIdx.x * Ed + tid];
    v *= v;
    #pragma unroll
    for (int o = 16; o > 0; o >>= 1) v += __shfl_down_sync(0xffffffffu, v, o);
    if ((tid & 31) == 0) sm[tid >> 5] = v;
    __syncthreads();
    if (tid == 0) g_cnorm[blockIdx.x] = sm[0] + sm[1] + sm[2] + sm[3];
}

// ---------------- VQ: argmin + histogram + per-row commitment partial ----------------
__global__ __launch_bounds__(256) void vq_k(const float* __restrict__ cb) {
    __shared__ float ze[Ed];
    __shared__ float bm[256];
    __shared__ int   bi[256];
    __shared__ int   chosen;
    __shared__ float sm[32];
    const int tid = threadIdx.x;
    const int b = blockIdx.x;
    if (tid < Ed) ze[tid] = g_ze[(size_t)b * Ed + tid];
    __syncthreads();

    float best = 3.4e38f;
    int besti = 0x7fffffff;
    for (int k = tid; k < Kcb; k += 256) {
        const float* c = cb + (size_t)k * Ed;
        float dot = 0.f;
        #pragma unroll 4
        for (int e = 0; e < Ed; e++) dot += ze[e] * c[e];
        float dd = g_cnorm[k] - 2.0f * dot;
        if (dd < best || (dd == best && k < besti)) { best = dd; besti = k; }
    }
    bm[tid] = best; bi[tid] = besti;
    __syncthreads();
    for (int off = 128; off > 0; off >>= 1) {
        if (tid < off) {
            float ob = bm[tid + off]; int oi = bi[tid + off];
            if (ob < bm[tid] || (ob == bm[tid] && oi < bi[tid])) { bm[tid] = ob; bi[tid] = oi; }
        }
        __syncthreads();
    }
    if (tid == 0) {
        chosen = bi[0];
        g_idx[b] = bi[0];
        atomicAdd(&g_hist[bi[0]], 1);
    }
    __syncthreads();

    const int kk = chosen;
    float part = 0.f;
    if (tid < Ed) {
        float diff = cb[(size_t)kk * Ed + tid] - ze[tid];
        part = diff * diff;
    }
    float tot = bred256(part, sm);
    if (tid == 0) g_losspart[b] = tot;
}

// ---------------- decoder MLP + output writes ----------------
__global__ __launch_bounds__(256) void decoder_k(
    const float* __restrict__ cb,
    const float* __restrict__ Wd1, const float* __restrict__ bd1,
    const float* __restrict__ lndg, const float* __restrict__ lndb,
    const float* __restrict__ Wd2, const float* __restrict__ bd2,
    const float* __restrict__ Wd3, const float* __restrict__ bd3,
    float* __restrict__ outp)
{
    __shared__ float zq[Ed];
    __shared__ float d1[Dm];
    __shared__ float d2s[Ed];
    __shared__ float sm[32];
    const int tid = threadIdx.x;
    const int b = blockIdx.x;
    const int ci = g_idx[b];
    if (tid < Ed) zq[tid] = cb[(size_t)ci * Ed + tid];
    __syncthreads();

    float t1 = bd1[tid];
    {
        const float* w = Wd1 + (size_t)tid * Ed;
        #pragma unroll 4
        for (int e = 0; e < Ed; e++) t1 += zq[e] * w[e];
    }
    float mean = bred256(t1, sm) * (1.0f / Dm);
    float dd = t1 - mean;
    float var = bred256(dd * dd, sm) * (1.0f / Dm);
    float xg = dd * rsqrtf(var + LN_EPS) * lndg[tid] + lndb[tid];
    d1[tid] = gelu_exact(xg);
    __syncthreads();

    if (tid < Ed) {
        const float* w2 = Wd2 + (size_t)tid * Dm;
        float t2 = bd2[tid];
        #pragma unroll 8
        for (int t = 0; t < Dm; t++) t2 += d1[t] * w2[t];
        d2s[tid] = gelu_exact(t2);
    }
    __syncthreads();

    if (tid < 2) {
        const float* w3 = Wd3 + (size_t)tid * Ed;
        float vv = bd3[tid];
        #pragma unroll 4
        for (int e = 0; e < Ed; e++) vv += d2s[e] * w3[e];
        outp[(size_t)b * 2 + tid] = vv;                 // velocity_pred
    }
    if (tid == 2) outp[(size_t)Bsz * 2 + b] = (float)ci; // indices as float
}

// ---------------- scalars: commitment loss + perplexity ----------------
__global__ __launch_bounds__(1024) void scalars_k(float* __restrict__ outp) {
    __shared__ float sm[32];
    const int tid = threadIdx.x;

    // entropy term over K=1024 bins (one per thread)
    float p = (float)g_hist[tid] * (1.0f / (float)Bsz);
    float term = p * logf(p + 1e-10f);
    float v = term;
    #pragma unroll
    for (int o = 16; o > 0; o >>= 1) v += __shfl_down_sync(0xffffffffu, v, o);
    if ((tid & 31) == 0) sm[tid >> 5] = v;
    __syncthreads();
    float ent = 0.f;
    if (tid == 0) {
        for (int i = 0; i < 32; i++) ent += sm[i];
        sm[0] = ent;
    }
    __syncthreads();
    ent = sm[0];
    __syncthreads();

    // commitment loss: deterministic reduce of 2048 per-row partials
    float lp = g_losspart[tid] + g_losspart[tid + 1024];
    #pragma unroll
    for (int o = 16; o > 0; o >>= 1) lp += __shfl_down_sync(0xffffffffu, lp, o);
    if ((tid & 31) == 0) sm[tid >> 5] = lp;
    __syncthreads();
    if (tid == 0) {
        float tot = 0.f;
        for (int i = 0; i < 32; i++) tot += sm[i];
        outp[(size_t)Bsz * 2 + Bsz + 0] = 0.1f * tot / ((float)Bsz * (float)Ed);
        outp[(size_t)Bsz * 2 + Bsz + 1] = expf(-ent);
    }
}

// ---------------- zero histogram ----------------
__global__ __launch_bounds__(1024) void zero_k() {
    g_hist[threadIdx.x] = 0;
}

// ---------------- host ----------------
template <typename T>
static T* sym_addr(const void* sym) {
    void* p = nullptr;
    cudaGetSymbolAddress(&p, sym);
    return (T*)p;
}

extern "C" void kernel_launch(void* const* d_in, const int* in_sizes, int n_in,
                              void* d_out, int out_size)
{
    (void)in_sizes; (void)n_in; (void)out_size;
    const float* x     = (const float*)d_in[0];
    const float* W_in  = (const float*)d_in[1];
    const float* b_in  = (const float*)d_in[2];
    const float* cls   = (const float*)d_in[3];
    const float* Wqkv  = (const float*)d_in[4];
    const float* bqkv  = (const float*)d_in[5];
    const float* Wo    = (const float*)d_in[6];
    const float* bo    = (const float*)d_in[7];
    const float* W1    = (const float*)d_in[8];
    const float* b1    = (const float*)d_in[9];
    const float* W2    = (const float*)d_in[10];
    const float* b2    = (const float*)d_in[11];
    const float* ln1g  = (const float*)d_in[12];
    const float* ln1b  = (const float*)d_in[13];
    const float* ln2g  = (const float*)d_in[14];
    const float* ln2b  = (const float*)d_in[15];
    const float* lnfg  = (const float*)d_in[16];
    const float* lnfb  = (const float*)d_in[17];
    const float* Wout  = (const float*)d_in[18];
    const float* bout  = (const float*)d_in[19];
    const float* cb    = (const float*)d_in[20];
    const float* Wd1   = (const float*)d_in[21];
    const float* bd1   = (const float*)d_in[22];
    const float* lndg  = (const float*)d_in[23];
    const float* lndb  = (const float*)d_in[24];
    const float* Wd2   = (const float*)d_in[25];
    const float* bd2   = (const float*)d_in[26];
    const float* Wd3   = (const float*)d_in[27];
    const float* bd3   = (const float*)d_in[28];
    float* outp = (float*)d_out;

    float* pH    = sym_addr<float>(g_h);
    float* pQkv  = sym_addr<float>(g_qkv);
    float* pAttn = sym_addr<float>(g_attn);
    float* pTmp  = sym_addr<float>(g_tmp);
    float* pFF   = sym_addr<float>(g_ff);

    zero_k<<<1, 1024>>>();
    cnorm_k<<<Kcb, 128>>>(cb);
    cls_fill_k<<<Bsz, 256>>>(cls);

    // input projection + positional encoding (rows remapped into g_h[:,1:,:])
    gemm_k<2><<<dim3(Dm / BN, (Bsz * Ssz) / BM), 256>>>(x, W_in, b_in, pH, Bsz * Ssz, Dm, Cin);

    for (int i = 0; i < NL; i++) {
        gemm_k<0><<<dim3((3 * Dm) / BN, MTOK / BM), 256>>>(
            pH, Wqkv + (size_t)i * 3 * Dm * Dm, bqkv + (size_t)i * 3 * Dm, pQkv, MTOK, 3 * Dm, Dm);
        attn_k<<<Bsz * NH, 128>>>(pQkv, pAttn);
        gemm_k<0><<<dim3(Dm / BN, MTOK / BM), 256>>>(
            pAttn, Wo + (size_t)i * Dm * Dm, bo + (size_t)i * Dm, pTmp, MTOK, Dm, Dm);
        add_ln_k<<<MTOK, 256>>>(pH, pTmp, ln1g + (size_t)i * Dm, ln1b + (size_t)i * Dm);
        gemm_k<1><<<dim3(FFd / BN, MTOK / BM), 256>>>(
            pH, W1 + (size_t)i * FFd * Dm, b1 + (size_t)i * FFd, pFF, MTOK, FFd, Dm);
        gemm_k<0><<<dim3(Dm / BN, MTOK / BM), 256>>>(
            pFF, W2 + (size_t)i * Dm * FFd, b2 + (size_t)i * Dm, pTmp, MTOK, Dm, FFd);
        add_ln_k<<<MTOK, 256>>>(pH, pTmp, ln2g + (size_t)i * Dm, ln2b + (size_t)i * Dm);
    }

    final_head_k<<<Bsz, 256>>>(lnfg, lnfb, Wout, bout);
    vq_k<<<Bsz, 256>>>(cb);
    decoder_k<<<Bsz, 256>>>(cb, Wd1, bd1, lndg, lndb, Wd2, bd2, Wd3, bd3, outp);
    scalars_k<<<1, 1024>>>(outp);
}

// round 2
// speedup vs baseline: 2.9386x; 2.9386x over previous
#include <cuda_runtime.h>
#include <math.h>
#include <stdint.h>

// ---------------- problem constants ----------------
#define Bsz 2048
#define Ssz 64
#define Cin 142
#define Dm  256
#define NH  8
#define DHd 32
#define FFd 512
#define NL  3
#define Ed  128
#define Kcb 1024
#define Tt  65          // S+1
#define MTOK (Bsz*Tt)   // 133120
#define LN_EPS 1e-5f

// ---------------- scratch (device globals; no allocation allowed) ----------------
__device__ float g_h   [(size_t)Bsz*Tt*Dm];
__device__ float g_qkv [(size_t)Bsz*Tt*3*Dm];
__device__ float g_attn[(size_t)Bsz*Tt*Dm];
__device__ float g_tmp [(size_t)Bsz*Tt*Dm];
__device__ float g_ff  [(size_t)Bsz*Tt*FFd];
__device__ float g_ze  [(size_t)Bsz*Ed];
__device__ int   g_idx [Bsz];
__device__ float g_cnorm[Kcb];
__device__ int   g_hist[Kcb];
__device__ float g_losspart[Bsz];

// ---------------- helpers ----------------
__device__ __forceinline__ float gelu_exact(float x) {
    return 0.5f * x * (1.0f + erff(x * 0.7071067811865475f));
}

__device__ __forceinline__ float bred256(float v, float* sm) {
    int tid = threadIdx.x;
    #pragma unroll
    for (int o = 16; o > 0; o >>= 1) v += __shfl_down_sync(0xffffffffu, v, o);
    if ((tid & 31) == 0) sm[tid >> 5] = v;
    __syncthreads();
    if (tid == 0) {
        float t = 0.f;
        #pragma unroll
        for (int i = 0; i < 8; i++) t += sm[i];
        sm[0] = t;
    }
    __syncthreads();
    float r = sm[0];
    __syncthreads();
    return r;
}

__device__ __forceinline__ float pe_val(int s, int c) {
    int j = c >> 1;
    float freq = expf(-(float)(2 * j) * (9.210340371976184f / 256.0f));
    float ang = (float)s * freq;
    return (c & 1) ? cosf(ang) : sinf(ang);
}

// ---------------- GEMM: C[M,N] = A[M,K] @ W[N,K]^T + bias ----------------
// 128x128 block tile, BK=8, double-buffered smem, 256 threads, 8x8 microtile.
// Requires: M % 128 == 0, N % 128 == 0.
// VEC=1: K % 8 == 0 (vectorized loads, no bounds checks).
// VEC=0: arbitrary K (scalar predicated loads).
// EPI: 0 = bias, 1 = bias+gelu, 2 = bias+positional-encoding + row remap
//      (input rows m=b*64+s -> out rows b*65+1+s, N must be 256)
template <int EPI, int VEC>
__global__ __launch_bounds__(256) void gemm128_k(
    const float* __restrict__ A, const float* __restrict__ W,
    const float* __restrict__ bias, float* __restrict__ C,
    int M, int N, int K)
{
    __shared__ float As[2][8][128];
    __shared__ float Bs[2][8][128];

    const int tid  = threadIdx.x;
    const int row0 = blockIdx.y * 128;
    const int col0 = blockIdx.x * 128;

    // loader mapping: each thread loads one float4 (or 4 scalars) of A and of W
    const int lr  = tid >> 1;          // 0..127 : row within tile
    const int lk4 = (tid & 1) * 4;     // 0 or 4 : k offset within BK

    // compute mapping
    const int tx = tid & 15;           // column group
    const int ty = tid >> 4;           // row group

    float acc[8][8];
    #pragma unroll
    for (int i = 0; i < 8; i++)
        #pragma unroll
        for (int j = 0; j < 8; j++) acc[i][j] = 0.f;

    const float* Arow = A + (size_t)(row0 + lr) * K;
    const float* Wrow = W + (size_t)(col0 + lr) * K;

    const int nk = (K + 7) / 8;

    float ra[4], rb[4];

    // ---- load stage 0 ----
    {
        if (VEC) {
            float4 va = *reinterpret_cast<const float4*>(Arow + lk4);
            float4 vb = *reinterpret_cast<const float4*>(Wrow + lk4);
            ra[0]=va.x; ra[1]=va.y; ra[2]=va.z; ra[3]=va.w;
            rb[0]=vb.x; rb[1]=vb.y; rb[2]=vb.z; rb[3]=vb.w;
        } else {
            #pragma unroll
            for (int i = 0; i < 4; i++) {
                int kg = lk4 + i;
                ra[i] = (kg < K) ? Arow[kg] : 0.f;
                rb[i] = (kg < K) ? Wrow[kg] : 0.f;
            }
        }
        #pragma unroll
        for (int i = 0; i < 4; i++) {
            As[0][lk4 + i][lr] = ra[i];
            Bs[0][lk4 + i][lr] = rb[i];
        }
    }
    __syncthreads();

    int buf = 0;
    for (int s = 0; s < nk; s++) {
        // prefetch next stage into registers
        const bool more = (s + 1 < nk);
        if (more) {
            int k0 = (s + 1) * 8;
            if (VEC) {
                float4 va = *reinterpret_cast<const float4*>(Arow + k0 + lk4);
                float4 vb = *reinterpret_cast<const float4*>(Wrow + k0 + lk4);
                ra[0]=va.x; ra[1]=va.y; ra[2]=va.z; ra[3]=va.w;
                rb[0]=vb.x; rb[1]=vb.y; rb[2]=vb.z; rb[3]=vb.w;
            } else {
                #pragma unroll
                for (int i = 0; i < 4; i++) {
                    int kg = k0 + lk4 + i;
                    ra[i] = (kg < K) ? Arow[kg] : 0.f;
                    rb[i] = (kg < K) ? Wrow[kg] : 0.f;
                }
            }
        }

        // compute 8 k-steps
        #pragma unroll
        for (int k = 0; k < 8; k++) {
            float4 a0 = *reinterpret_cast<const float4*>(&As[buf][k][ty << 2]);
            float4 a1 = *reinterpret_cast<const float4*>(&As[buf][k][(ty << 2) + 64]);
            float4 b0 = *reinterpret_cast<const float4*>(&Bs[buf][k][tx << 2]);
            float4 b1 = *reinterpret_cast<const float4*>(&Bs[buf][k][(tx << 2) + 64]);
            float a[8] = {a0.x, a0.y, a0.z, a0.w, a1.x, a1.y, a1.z, a1.w};
            float b[8] = {b0.x, b0.y, b0.z, b0.w, b1.x, b1.y, b1.z, b1.w};
            #pragma unroll
            for (int i = 0; i < 8; i++)
                #pragma unroll
                for (int j = 0; j < 8; j++) acc[i][j] += a[i] * b[j];
        }

        if (more) {
            #pragma unroll
            for (int i = 0; i < 4; i++) {
                As[buf ^ 1][lk4 + i][lr] = ra[i];
                Bs[buf ^ 1][lk4 + i][lr] = rb[i];
            }
            __syncthreads();
            buf ^= 1;
        }
    }

    // ---- epilogue ----
    #pragma unroll
    for (int ih = 0; ih < 2; ih++) {
        #pragma unroll
        for (int i = 0; i < 4; i++) {
            int r = row0 + (ty << 2) + i + ih * 64;
            #pragma unroll
            for (int jh = 0; jh < 2; jh++) {
                int c = col0 + (tx << 2) + jh * 64;
                float4 bv = *reinterpret_cast<const float4*>(bias + c);
                float v0 = acc[ih * 4 + i][jh * 4 + 0] + bv.x;
                float v1 = acc[ih * 4 + i][jh * 4 + 1] + bv.y;
                float v2 = acc[ih * 4 + i][jh * 4 + 2] + bv.z;
                float v3 = acc[ih * 4 + i][jh * 4 + 3] + bv.w;
                if (EPI == 1) {
                    v0 = gelu_exact(v0); v1 = gelu_exact(v1);
                    v2 = gelu_exact(v2); v3 = gelu_exact(v3);
                }
                size_t out;
                if (EPI == 2) {
                    int ss = r & 63;
                    int bb = r >> 6;
                    v0 += pe_val(ss, c + 0);
                    v1 += pe_val(ss, c + 1);
                    v2 += pe_val(ss, c + 2);
                    v3 += pe_val(ss, c + 3);
                    out = ((size_t)bb * Tt + 1 + ss) * Dm + c;
                } else {
                    out = (size_t)r * N + c;
                }
                float4 o4 = make_float4(v0, v1, v2, v3);
                *reinterpret_cast<float4*>(C + out) = o4;
            }
        }
    }
}

// ---------------- cls token fill ----------------
__global__ __launch_bounds__(256) void cls_fill_k(const float* __restrict__ cls) {
    g_h[(size_t)blockIdx.x * Tt * Dm + threadIdx.x] = cls[threadIdx.x];
}

// ---------------- attention: one block per (batch, head) ----------------
__global__ __launch_bounds__(128) void attn_k(
    const float* __restrict__ qkv, float* __restrict__ outp)
{
    const int b  = blockIdx.x >> 3;
    const int hh = blockIdx.x & 7;
    const float* base = qkv + (size_t)b * Tt * (3 * Dm) + hh * DHd;

    __shared__ float q [Tt][33];
    __shared__ float kt[Tt][33];
    __shared__ float vt[Tt][33];
    __shared__ float sc[Tt * Tt];

    const int tid = threadIdx.x;

    for (int idx = tid; idx < Tt * DHd; idx += 128) {
        int t = idx >> 5, d = idx & 31;
        const float* r = base + (size_t)t * (3 * Dm);
        q [t][d] = r[d];
        kt[t][d] = r[Dm + d];
        vt[t][d] = r[2 * Dm + d];
    }
    __syncthreads();

    const float scale = 0.17677669529663689f; // 1/sqrt(32)
    for (int idx = tid; idx < Tt * Tt; idx += 128) {
        int i = idx / Tt, j = idx - i * Tt;
        float s = 0.f;
        #pragma unroll
        for (int d = 0; d < DHd; d++) s += q[i][d] * kt[j][d];
        sc[idx] = s * scale;
    }
    __syncthreads();

    if (tid < Tt) {
        float m = -3.4e38f;
        for (int j = 0; j < Tt; j++) m = fmaxf(m, sc[tid * Tt + j]);
        float ssum = 0.f;
        for (int j = 0; j < Tt; j++) {
            float e = expf(sc[tid * Tt + j] - m);
            sc[tid * Tt + j] = e;
            ssum += e;
        }
        float inv = 1.0f / ssum;
        for (int j = 0; j < Tt; j++) sc[tid * Tt + j] *= inv;
    }
    __syncthreads();

    for (int idx = tid; idx < Tt * DHd; idx += 128) {
        int i = idx >> 5, d = idx & 31;
        float o = 0.f;
        for (int j = 0; j < Tt; j++) o += sc[i * Tt + j] * vt[j][d];
        outp[((size_t)b * Tt + i) * Dm + hh * DHd + d] = o;
    }
}

// ---------------- residual add + LayerNorm (in place on g_h) ----------------
__global__ __launch_bounds__(256) void add_ln_k(
    float* __restrict__ h, const float* __restrict__ t,
    const float* __restrict__ g, const float* __restrict__ bb)
{
    __shared__ float sm[32];
    const int tid = threadIdx.x;
    const size_t base = (size_t)blockIdx.x * Dm;
    float v = h[base + tid] + t[base + tid];
    float mean = bred256(v, sm) * (1.0f / Dm);
    float d = v - mean;
    float var = bred256(d * d, sm) * (1.0f / Dm);
    h[base + tid] = d * rsqrtf(var + LN_EPS) * g[tid] + bb[tid];
}

// ---------------- final head: LN(cls) @ W_out^T + b_out -> g_ze ----------------
__global__ __launch_bounds__(256) void final_head_k(
    const float* __restrict__ lnfg, const float* __restrict__ lnfb,
    const float* __restrict__ Wout, const float* __restrict__ bout)
{
    __shared__ float xn[Dm];
    __shared__ float sm[32];
    const int tid = threadIdx.x;
    const int b = blockIdx.x;
    float v = g_h[(size_t)b * Tt * Dm + tid];
    float mean = bred256(v, sm) * (1.0f / Dm);
    float d = v - mean;
    float var = bred256(d * d, sm) * (1.0f / Dm);
    xn[tid] = d * rsqrtf(var + LN_EPS) * lnfg[tid] + lnfb[tid];
    __syncthreads();
    if (tid < Ed) {
        const float* w = Wout + (size_t)tid * Dm;
        float a = bout[tid];
        #pragma unroll 8
        for (int t = 0; t < Dm; t++) a += xn[t] * w[t];
        g_ze[(size_t)b * Ed + tid] = a;
    }
}

// ---------------- codebook squared norms ----------------
__global__ __launch_bounds__(128) void cnorm_k(const float* __restrict__ cb) {
    __shared__ float sm[4];
    const int tid = threadIdx.x;
    float v = cb[(size_t)blockIdx.x * Ed + tid];
    v *= v;
    #pragma unroll
    for (int o = 16; o > 0; o >>= 1) v += __shfl_down_sync(0xffffffffu, v, o);
    if ((tid & 31) == 0) sm[tid >> 5] = v;
    __syncthreads();
    if (tid == 0) g_cnorm[blockIdx.x] = sm[0] + sm[1] + sm[2] + sm[3];
}

// ---------------- VQ: argmin + histogram + per-row commitment partial ----------------
__global__ __launch_bounds__(256) void vq_k(const float* __restrict__ cb) {
    __shared__ float ze[Ed];
    __shared__ float bm[256];
    __shared__ int   bi[256];
    __shared__ int   chosen;
    __shared__ float sm[32];
    const int tid = threadIdx.x;
    const int b = blockIdx.x;
    if (tid < Ed) ze[tid] = g_ze[(size_t)b * Ed + tid];
    __syncthreads();

    float best = 3.4e38f;
    int besti = 0x7fffffff;
    for (int k = tid; k < Kcb; k += 256) {
        const float* c = cb + (size_t)k * Ed;
        float dot = 0.f;
        #pragma unroll 4
        for (int e = 0; e < Ed; e++) dot += ze[e] * c[e];
        float dd = g_cnorm[k] - 2.0f * dot;
        if (dd < best || (dd == best && k < besti)) { best = dd; besti = k; }
    }
    bm[tid] = best; bi[tid] = besti;
    __syncthreads();
    for (int off = 128; off > 0; off >>= 1) {
        if (tid < off) {
            float ob = bm[tid + off]; int oi = bi[tid + off];
            if (ob < bm[tid] || (ob == bm[tid] && oi < bi[tid])) { bm[tid] = ob; bi[tid] = oi; }
        }
        __syncthreads();
    }
    if (tid == 0) {
        chosen = bi[0];
        g_idx[b] = bi[0];
        atomicAdd(&g_hist[bi[0]], 1);
    }
    __syncthreads();

    const int kk = chosen;
    float part = 0.f;
    if (tid < Ed) {
        float diff = cb[(size_t)kk * Ed + tid] - ze[tid];
        part = diff * diff;
    }
    float tot = bred256(part, sm);
    if (tid == 0) g_losspart[b] = tot;
}

// ---------------- decoder MLP + output writes ----------------
__global__ __launch_bounds__(256) void decoder_k(
    const float* __restrict__ cb,
    const float* __restrict__ Wd1, const float* __restrict__ bd1,
    const float* __restrict__ lndg, const float* __restrict__ lndb,
    const float* __restrict__ Wd2, const float* __restrict__ bd2,
    const float* __restrict__ Wd3, const float* __restrict__ bd3,
    float* __restrict__ outp)
{
    __shared__ float zq[Ed];
    __shared__ float d1[Dm];
    __shared__ float d2s[Ed];
    __shared__ float sm[32];
    const int tid = threadIdx.x;
    const int b = blockIdx.x;
    const int ci = g_idx[b];
    if (tid < Ed) zq[tid] = cb[(size_t)ci * Ed + tid];
    __syncthreads();

    float t1 = bd1[tid];
    {
        const float* w = Wd1 + (size_t)tid * Ed;
        #pragma unroll 4
        for (int e = 0; e < Ed; e++) t1 += zq[e] * w[e];
    }
    float mean = bred256(t1, sm) * (1.0f / Dm);
    float dd = t1 - mean;
    float var = bred256(dd * dd, sm) * (1.0f / Dm);
    float xg = dd * rsqrtf(var + LN_EPS) * lndg[tid] + lndb[tid];
    d1[tid] = gelu_exact(xg);
    __syncthreads();

    if (tid < Ed) {
        const float* w2 = Wd2 + (size_t)tid * Dm;
        float t2 = bd2[tid];
        #pragma unroll 8
        for (int t = 0; t < Dm; t++) t2 += d1[t] * w2[t];
        d2s[tid] = gelu_exact(t2);
    }
    __syncthreads();

    if (tid < 2) {
        const float* w3 = Wd3 + (size_t)tid * Ed;
        float vv = bd3[tid];
        #pragma unroll 4
        for (int e = 0; e < Ed; e++) vv += d2s[e] * w3[e];
        outp[(size_t)b * 2 + tid] = vv;
    }
    if (tid == 2) outp[(size_t)Bsz * 2 + b] = (float)ci;
}

// ---------------- scalars: commitment loss + perplexity ----------------
__global__ __launch_bounds__(1024) void scalars_k(float* __restrict__ outp) {
    __shared__ float sm[32];
    const int tid = threadIdx.x;

    float p = (float)g_hist[tid] * (1.0f / (float)Bsz);
    float term = p * logf(p + 1e-10f);
    float v = term;
    #pragma unroll
    for (int o = 16; o > 0; o >>= 1) v += __shfl_down_sync(0xffffffffu, v, o);
    if ((tid & 31) == 0) sm[tid >> 5] = v;
    __syncthreads();
    float ent = 0.f;
    if (tid == 0) {
        for (int i = 0; i < 32; i++) ent += sm[i];
        sm[0] = ent;
    }
    __syncthreads();
    ent = sm[0];
    __syncthreads();

    float lp = g_losspart[tid] + g_losspart[tid + 1024];
    #pragma unroll
    for (int o = 16; o > 0; o >>= 1) lp += __shfl_down_sync(0xffffffffu, lp, o);
    if ((tid & 31) == 0) sm[tid >> 5] = lp;
    __syncthreads();
    if (tid == 0) {
        float tot = 0.f;
        for (int i = 0; i < 32; i++) tot += sm[i];
        outp[(size_t)Bsz * 2 + Bsz + 0] = 0.1f * tot / ((float)Bsz * (float)Ed);
        outp[(size_t)Bsz * 2 + Bsz + 1] = expf(-ent);
    }
}

// ---------------- zero histogram ----------------
__global__ __launch_bounds__(1024) void zero_k() {
    g_hist[threadIdx.x] = 0;
}

// ---------------- host ----------------
template <typename T>
static T* sym_addr(const void* sym) {
    void* p = nullptr;
    cudaGetSymbolAddress(&p, sym);
    return (T*)p;
}

extern "C" void kernel_launch(void* const* d_in, const int* in_sizes, int n_in,
                              void* d_out, int out_size)
{
    (void)in_sizes; (void)n_in; (void)out_size;
    const float* x     = (const float*)d_in[0];
    const float* W_in  = (const float*)d_in[1];
    const float* b_in  = (const float*)d_in[2];
    const float* cls   = (const float*)d_in[3];
    const float* Wqkv  = (const float*)d_in[4];
    const float* bqkv  = (const float*)d_in[5];
    const float* Wo    = (const float*)d_in[6];
    const float* bo    = (const float*)d_in[7];
    const float* W1    = (const float*)d_in[8];
    const float* b1    = (const float*)d_in[9];
    const float* W2    = (const float*)d_in[10];
    const float* b2    = (const float*)d_in[11];
    const float* ln1g  = (const float*)d_in[12];
    const float* ln1b  = (const float*)d_in[13];
    const float* ln2g  = (const float*)d_in[14];
    const float* ln2b  = (const float*)d_in[15];
    const float* lnfg  = (const float*)d_in[16];
    const float* lnfb  = (const float*)d_in[17];
    const float* Wout  = (const float*)d_in[18];
    const float* bout  = (const float*)d_in[19];
    const float* cb    = (const float*)d_in[20];
    const float* Wd1   = (const float*)d_in[21];
    const float* bd1   = (const float*)d_in[22];
    const float* lndg  = (const float*)d_in[23];
    const float* lndb  = (const float*)d_in[24];
    const float* Wd2   = (const float*)d_in[25];
    const float* bd2   = (const float*)d_in[26];
    const float* Wd3   = (const float*)d_in[27];
    const float* bd3   = (const float*)d_in[28];
    float* outp = (float*)d_out;

    float* pH    = sym_addr<float>(g_h);
    float* pQkv  = sym_addr<float>(g_qkv);
    float* pAttn = sym_addr<float>(g_attn);
    float* pTmp  = sym_addr<float>(g_tmp);
    float* pFF   = sym_addr<float>(g_ff);

    zero_k<<<1, 1024>>>();
    cnorm_k<<<Kcb, 128>>>(cb);
    cls_fill_k<<<Bsz, 256>>>(cls);

    // input projection + positional encoding (K=142: scalar path)
    gemm128_k<2, 0><<<dim3(Dm / 128, (Bsz * Ssz) / 128), 256>>>(
        x, W_in, b_in, pH, Bsz * Ssz, Dm, Cin);

    for (int i = 0; i < NL; i++) {
        gemm128_k<0, 1><<<dim3((3 * Dm) / 128, MTOK / 128), 256>>>(
            pH, Wqkv + (size_t)i * 3 * Dm * Dm, bqkv + (size_t)i * 3 * Dm, pQkv, MTOK, 3 * Dm, Dm);
        attn_k<<<Bsz * NH, 128>>>(pQkv, pAttn);
        gemm128_k<0, 1><<<dim3(Dm / 128, MTOK / 128), 256>>>(
            pAttn, Wo + (size_t)i * Dm * Dm, bo + (size_t)i * Dm, pTmp, MTOK, Dm, Dm);
        add_ln_k<<<MTOK, 256>>>(pH, pTmp, ln1g + (size_t)i * Dm, ln1b + (size_t)i * Dm);
        gemm128_k<1, 1><<<dim3(FFd / 128, MTOK / 128), 256>>>(
            pH, W1 + (size_t)i * FFd * Dm, b1 + (size_t)i * FFd, pFF, MTOK, FFd, Dm);
        gemm128_k<0, 1><<<dim3(Dm / 128, MTOK / 128), 256>>>(
            pFF, W2 + (size_t)i * Dm * FFd, b2 + (size_t)i * Dm, pTmp, MTOK, Dm, FFd);
        add_ln_k<<<MTOK, 256>>>(pH, pTmp, ln2g + (size_t)i * Dm, ln2b + (size_t)i * Dm);
    }

    final_head_k<<<Bsz, 256>>>(lnfg, lnfb, Wout, bout);
    vq_k<<<Bsz, 256>>>(cb);
    decoder_k<<<Bsz, 256>>>(cb, Wd1, bd1, lndg, lndb, Wd2, bd2, Wd3, bd3, outp);
    scalars_k<<<1, 1024>>>(outp);
}

// round 4
// speedup vs baseline: 3.3722x; 1.1476x over previous
#include <cuda_runtime.h>
#include <cuda_bf16.h>
#include <math.h>
#include <stdint.h>

// ---------------- problem constants ----------------
#define Bsz 2048
#define Ssz 64
#define Cin 142
#define Dm  256
#define NH  8
#define DHd 32
#define FFd 512
#define NL  3
#define Ed  128
#define Kcb 1024
#define Tt  65          // S+1
#define MTOK (Bsz*Tt)   // 133120
#define LN_EPS 1e-5f

#define PL0 ((size_t)MTOK*Dm)    // plane stride act0
#define PL1 ((size_t)MTOK*FFd)   // plane stride act1
#define WQKV_SZ (3*Dm*Dm)
#define WO_SZ   (Dm*Dm)
#define W1_SZ   (FFd*Dm)
#define W2_SZ   (Dm*FFd)

// ---------------- scratch (device globals; no allocation allowed) ----------------
__device__ float g_h   [(size_t)Bsz*Tt*Dm];
__device__ float g_qkv [(size_t)Bsz*Tt*3*Dm];
__device__ float g_tmp [(size_t)Bsz*Tt*Dm];
__device__ float g_ze  [(size_t)Bsz*Ed];
__device__ int   g_idx [Bsz];
__device__ float g_cnorm[Kcb];
__device__ int   g_hist[Kcb];
__device__ float g_losspart[Bsz];

// bf16 3-split activation planes
__device__ __nv_bfloat16 g_act0[3*PL0];
__device__ __nv_bfloat16 g_act1[3*PL1];
// bf16 3-split weights
__device__ __nv_bfloat16 g_wqkvb[(size_t)NL*3*WQKV_SZ];
__device__ __nv_bfloat16 g_wob  [(size_t)NL*3*WO_SZ];
__device__ __nv_bfloat16 g_w1b  [(size_t)NL*3*W1_SZ];
__device__ __nv_bfloat16 g_w2b  [(size_t)NL*3*W2_SZ];

// ---------------- helpers ----------------
__device__ __forceinline__ uint32_t smem_to_u32(const void* p) {
    uint32_t a;
    asm("{ .reg .u64 t; cvta.to.shared.u64 t, %1; cvt.u32.u64 %0, t; }" : "=r"(a) : "l"(p));
    return a;
}
__device__ __forceinline__ void cp_async16(uint32_t saddr, const void* gaddr) {
    asm volatile("cp.async.cg.shared.global [%0], [%1], 16;" :: "r"(saddr), "l"(gaddr));
}
__device__ __forceinline__ uint32_t lds32(uint32_t addr) {
    uint32_t v; asm volatile("ld.shared.b32 %0, [%1];" : "=r"(v) : "r"(addr)); return v;
}
__device__ __forceinline__ float gelu_exact(float x) {
    return 0.5f * x * (1.0f + erff(x * 0.7071067811865475f));
}
__device__ __forceinline__ void split3(float v, __nv_bfloat16& h, __nv_bfloat16& m, __nv_bfloat16& l) {
    h = __float2bfloat16(v);
    float r1 = v - __bfloat162float(h);
    m = __float2bfloat16(r1);
    float r2 = r1 - __bfloat162float(m);
    l = __float2bfloat16(r2);
}
__device__ __forceinline__ float bred256(float v, float* sm) {
    int tid = threadIdx.x;
    #pragma unroll
    for (int o = 16; o > 0; o >>= 1) v += __shfl_down_sync(0xffffffffu, v, o);
    if ((tid & 31) == 0) sm[tid >> 5] = v;
    __syncthreads();
    if (tid == 0) {
        float t = 0.f;
        #pragma unroll
        for (int i = 0; i < 8; i++) t += sm[i];
        sm[0] = t;
    }
    __syncthreads();
    float r = sm[0];
    __syncthreads();
    return r;
}
__device__ __forceinline__ float pe_val(int s, int c) {
    int j = c >> 1;
    float freq = expf(-(float)(2 * j) * (9.210340371976184f / 256.0f));
    float ang = (float)s * freq;
    return (c & 1) ? cosf(ang) : sinf(ang);
}

// ---------------- mma.sync bf16 6-term split GEMM ----------------
// C[M,N] = A[M,K] @ W[N,K]^T + bias   (A,W as 3 bf16 planes hi/mid/lo)
// tile 128x128, BK=32, cp.async double-buffer, 8 warps, warp tile 64x32.
// smem per plane per stage: 128 rows x 64B (32 bf16) with 16B-chunk XOR swizzle.
#define PLANE_B 8192
#define STAGE_B 49152          // 6 planes
#define SMEM_DYN (2*STAGE_B)   // 96 KB

__device__ __forceinline__ uint32_t sw_addr(uint32_t plane_base, int r, int colk) {
    int chunk = (colk >> 3) ^ ((r >> 1) & 3);
    return plane_base + r * 64 + (chunk << 4) + ((colk & 7) << 1);
}

__device__ __forceinline__ void issue_stage(
    uint32_t sbase, const __nv_bfloat16* __restrict__ A, size_t aps,
    const __nv_bfloat16* __restrict__ W, size_t wps,
    int row0, int col0, int K, int k0, int tid)
{
    #pragma unroll
    for (int i = 0; i < 12; i++) {
        const int plane = i >> 1;
        const int idx = ((i & 1) << 8) + tid;     // 0..511
        const int r = idx >> 2, c16 = idx & 3;
        const __nv_bfloat16* src = (plane < 3)
            ? A + (size_t)plane * aps + (size_t)(row0 + r) * K + (k0 + c16 * 8)
            : W + (size_t)(plane - 3) * wps + (size_t)(col0 + r) * K + (k0 + c16 * 8);
        uint32_t dst = sbase + plane * PLANE_B + r * 64 + ((c16 ^ ((r >> 1) & 3)) << 4);
        cp_async16(dst, src);
    }
}

__device__ __forceinline__ void mma16816(float* c, const uint32_t* a, const uint32_t* b) {
    asm volatile(
        "mma.sync.aligned.m16n8k16.row.col.f32.bf16.bf16.f32 "
        "{%0,%1,%2,%3}, {%4,%5,%6,%7}, {%8,%9}, {%0,%1,%2,%3};"
        : "+f"(c[0]), "+f"(c[1]), "+f"(c[2]), "+f"(c[3])
        : "r"(a[0]), "r"(a[1]), "r"(a[2]), "r"(a[3]), "r"(b[0]), "r"(b[1]));
}

// EPI 0: fp32 out. EPI 1: gelu -> 3-plane bf16 out to g_act1.
template <int EPI>
__global__ __launch_bounds__(256, 2)
void bfgemm_k(const __nv_bfloat16* __restrict__ A, size_t aps,
              const __nv_bfloat16* __restrict__ W, size_t wps,
              const float* __restrict__ bias, float* __restrict__ C,
              int M, int N, int K)
{
    extern __shared__ char smem[];
    const uint32_t sb = smem_to_u32(smem);
    const int tid = threadIdx.x;
    const int lane = tid & 31, wid = tid >> 5;
    const int row0 = blockIdx.y * 128;
    const int col0 = blockIdx.x * 128;
    const int wm0 = (wid & 1) * 64;
    const int wn0 = (wid >> 1) * 32;
    const int qr = lane >> 2, qc = lane & 3;

    float acc[4][4][4];
    #pragma unroll
    for (int a = 0; a < 4; a++)
        #pragma unroll
        for (int b = 0; b < 4; b++)
            #pragma unroll
            for (int c = 0; c < 4; c++) acc[a][b][c] = 0.f;

    const int nk = K >> 5;

    issue_stage(sb, A, aps, W, wps, row0, col0, K, 0, tid);
    asm volatile("cp.async.commit_group;" ::: "memory");

    static const int ta[6] = {0, 0, 1, 0, 1, 2};
    static const int tb[6] = {0, 1, 0, 2, 1, 0};

    for (int s = 0; s < nk; s++) {
        if (s + 1 < nk) {
            issue_stage(sb + ((s + 1) & 1) * STAGE_B, A, aps, W, wps, row0, col0, K, (s + 1) << 5, tid);
            asm volatile("cp.async.commit_group;" ::: "memory");
            asm volatile("cp.async.wait_group 1;" ::: "memory");
        } else {
            asm volatile("cp.async.wait_group 0;" ::: "memory");
        }
        __syncthreads();

        const uint32_t stg = sb + (s & 1) * STAGE_B;
        #pragma unroll
        for (int t = 0; t < 6; t++) {
            const uint32_t abase = stg + ta[t] * PLANE_B;
            const uint32_t bbase = stg + (3 + tb[t]) * PLANE_B;
            #pragma unroll
            for (int kk = 0; kk < 32; kk += 16) {
                uint32_t areg[4][4];
                #pragma unroll
                for (int mi = 0; mi < 4; mi++) {
                    int r0 = wm0 + mi * 16 + qr;
                    areg[mi][0] = lds32(sw_addr(abase, r0,     kk + qc * 2));
                    areg[mi][1] = lds32(sw_addr(abase, r0 + 8, kk + qc * 2));
                    areg[mi][2] = lds32(sw_addr(abase, r0,     kk + 8 + qc * 2));
                    areg[mi][3] = lds32(sw_addr(abase, r0 + 8, kk + 8 + qc * 2));
                }
                uint32_t breg[4][2];
                #pragma unroll
                for (int ni = 0; ni < 4; ni++) {
                    int rn = wn0 + ni * 8 + qr;
                    breg[ni][0] = lds32(sw_addr(bbase, rn, kk + qc * 2));
                    breg[ni][1] = lds32(sw_addr(bbase, rn, kk + 8 + qc * 2));
                }
                #pragma unroll
                for (int mi = 0; mi < 4; mi++)
                    #pragma unroll
                    for (int ni = 0; ni < 4; ni++)
                        mma16816(acc[mi][ni], areg[mi], breg[ni]);
            }
        }
        __syncthreads();
    }

    // ---- epilogue ----
    #pragma unroll
    for (int mi = 0; mi < 4; mi++) {
        #pragma unroll
        for (int ni = 0; ni < 4; ni++) {
            int col = col0 + wn0 + ni * 8 + qc * 2;
            float b0 = bias[col], b1 = bias[col + 1];
            #pragma unroll
            for (int half = 0; half < 2; half++) {
                int r = row0 + wm0 + mi * 16 + qr + half * 8;
                float v0 = acc[mi][ni][half * 2 + 0] + b0;
                float v1 = acc[mi][ni][half * 2 + 1] + b1;
                size_t o = (size_t)r * N + col;
                if (EPI == 0) {
                    *reinterpret_cast<float2*>(C + o) = make_float2(v0, v1);
                } else {
                    float g0 = gelu_exact(v0), g1 = gelu_exact(v1);
                    __nv_bfloat16 h0, m0, l0, h1, m1, l1;
                    split3(g0, h0, m0, l0);
                    split3(g1, h1, m1, l1);
                    *reinterpret_cast<__nv_bfloat162*>(&g_act1[o]) = __nv_bfloat162(h0, h1);
                    *reinterpret_cast<__nv_bfloat162*>(&g_act1[PL1 + o]) = __nv_bfloat162(m0, m1);
                    *reinterpret_cast<__nv_bfloat162*>(&g_act1[2 * PL1 + o]) = __nv_bfloat162(l0, l1);
                }
            }
        }
    }
}

// ---------------- weight split conversion ----------------
__global__ __launch_bounds__(256) void conv3_k(
    const float* __restrict__ s, __nv_bfloat16* __restrict__ ph,
    __nv_bfloat16* __restrict__ pm, __nv_bfloat16* __restrict__ pl, int n)
{
    int i = blockIdx.x * 256 + threadIdx.x;
    if (i < n) {
        __nv_bfloat16 a, b, c;
        split3(s[i], a, b, c);
        ph[i] = a; pm[i] = b; pl[i] = c;
    }
}

// ---------------- fp32 GEMM (input projection only, K=142) ----------------
template <int EPI, int VEC>
__global__ __launch_bounds__(256) void gemm128_k(
    const float* __restrict__ A, const float* __restrict__ W,
    const float* __restrict__ bias, float* __restrict__ C,
    int M, int N, int K)
{
    __shared__ float As[2][8][128];
    __shared__ float Bs[2][8][128];

    const int tid  = threadIdx.x;
    const int row0 = blockIdx.y * 128;
    const int col0 = blockIdx.x * 128;
    const int lr  = tid >> 1;
    const int lk4 = (tid & 1) * 4;
    const int tx = tid & 15;
    const int ty = tid >> 4;

    float acc[8][8];
    #pragma unroll
    for (int i = 0; i < 8; i++)
        #pragma unroll
        for (int j = 0; j < 8; j++) acc[i][j] = 0.f;

    const float* Arow = A + (size_t)(row0 + lr) * K;
    const float* Wrow = W + (size_t)(col0 + lr) * K;
    const int nk = (K + 7) / 8;
    float ra[4], rb[4];

    {
        if (VEC) {
            float4 va = *reinterpret_cast<const float4*>(Arow + lk4);
            float4 vb = *reinterpret_cast<const float4*>(Wrow + lk4);
            ra[0]=va.x; ra[1]=va.y; ra[2]=va.z; ra[3]=va.w;
            rb[0]=vb.x; rb[1]=vb.y; rb[2]=vb.z; rb[3]=vb.w;
        } else {
            #pragma unroll
            for (int i = 0; i < 4; i++) {
                int kg = lk4 + i;
                ra[i] = (kg < K) ? Arow[kg] : 0.f;
                rb[i] = (kg < K) ? Wrow[kg] : 0.f;
            }
        }
        #pragma unroll
        for (int i = 0; i < 4; i++) {
            As[0][lk4 + i][lr] = ra[i];
            Bs[0][lk4 + i][lr] = rb[i];
        }
    }
    __syncthreads();

    int buf = 0;
    for (int s = 0; s < nk; s++) {
        const bool more = (s + 1 < nk);
        if (more) {
            int k0 = (s + 1) * 8;
            if (VEC) {
                float4 va = *reinterpret_cast<const float4*>(Arow + k0 + lk4);
                float4 vb = *reinterpret_cast<const float4*>(Wrow + k0 + lk4);
                ra[0]=va.x; ra[1]=va.y; ra[2]=va.z; ra[3]=va.w;
                rb[0]=vb.x; rb[1]=vb.y; rb[2]=vb.z; rb[3]=vb.w;
            } else {
                #pragma unroll
                for (int i = 0; i < 4; i++) {
                    int kg = k0 + lk4 + i;
                    ra[i] = (kg < K) ? Arow[kg] : 0.f;
                    rb[i] = (kg < K) ? Wrow[kg] : 0.f;
                }
            }
        }
        #pragma unroll
        for (int k = 0; k < 8; k++) {
            float4 a0 = *reinterpret_cast<const float4*>(&As[buf][k][ty << 2]);
            float4 a1 = *reinterpret_cast<const float4*>(&As[buf][k][(ty << 2) + 64]);
            float4 b0 = *reinterpret_cast<const float4*>(&Bs[buf][k][tx << 2]);
            float4 b1 = *reinterpret_cast<const float4*>(&Bs[buf][k][(tx << 2) + 64]);
            float a[8] = {a0.x, a0.y, a0.z, a0.w, a1.x, a1.y, a1.z, a1.w};
            float b[8] = {b0.x, b0.y, b0.z, b0.w, b1.x, b1.y, b1.z, b1.w};
            #pragma unroll
            for (int i = 0; i < 8; i++)
                #pragma unroll
                for (int j = 0; j < 8; j++) acc[i][j] += a[i] * b[j];
        }
        if (more) {
            #pragma unroll
            for (int i = 0; i < 4; i++) {
                As[buf ^ 1][lk4 + i][lr] = ra[i];
                Bs[buf ^ 1][lk4 + i][lr] = rb[i];
            }
            __syncthreads();
            buf ^= 1;
        }
    }

    #pragma unroll
    for (int ih = 0; ih < 2; ih++) {
        #pragma unroll
        for (int i = 0; i < 4; i++) {
            int r = row0 + (ty << 2) + i + ih * 64;
            #pragma unroll
            for (int jh = 0; jh < 2; jh++) {
                int c = col0 + (tx << 2) + jh * 64;
                float4 bv = *reinterpret_cast<const float4*>(bias + c);
                float v0 = acc[ih * 4 + i][jh * 4 + 0] + bv.x;
                float v1 = acc[ih * 4 + i][jh * 4 + 1] + bv.y;
                float v2 = acc[ih * 4 + i][jh * 4 + 2] + bv.z;
                float v3 = acc[ih * 4 + i][jh * 4 + 3] + bv.w;
                size_t out;
                if (EPI == 2) {
                    int ss = r & 63;
                    int bb = r >> 6;
                    v0 += pe_val(ss, c + 0);
                    v1 += pe_val(ss, c + 1);
                    v2 += pe_val(ss, c + 2);
                    v3 += pe_val(ss, c + 3);
                    out = ((size_t)bb * Tt + 1 + ss) * Dm + c;
                    float vv[4] = {v0, v1, v2, v3};
                    #pragma unroll
                    for (int q = 0; q < 4; q++) {
                        __nv_bfloat16 hh, mm, ll;
                        split3(vv[q], hh, mm, ll);
                        g_act0[out + q] = hh;
                        g_act0[PL0 + out + q] = mm;
                        g_act0[2 * PL0 + out + q] = ll;
                    }
                } else {
                    out = (size_t)r * N + c;
                }
                float4 o4 = make_float4(v0, v1, v2, v3);
                *reinterpret_cast<float4*>(C + out) = o4;
            }
        }
    }
}

// ---------------- cls token fill ----------------
__global__ __launch_bounds__(256) void cls_fill_k(const float* __restrict__ cls) {
    float v = cls[threadIdx.x];
    size_t idx = (size_t)blockIdx.x * Tt * Dm + threadIdx.x;
    g_h[idx] = v;
    __nv_bfloat16 hh, mm, ll;
    split3(v, hh, mm, ll);
    g_act0[idx] = hh;
    g_act0[PL0 + idx] = mm;
    g_act0[2 * PL0 + idx] = ll;
}

// ---------------- attention (out -> bf16 planes) ----------------
__global__ __launch_bounds__(128) void attn_k(const float* __restrict__ qkv)
{
    const int b  = blockIdx.x >> 3;
    const int hh = blockIdx.x & 7;
    const float* base = qkv + (size_t)b * Tt * (3 * Dm) + hh * DHd;

    __shared__ float q [Tt][33];
    __shared__ float kt[Tt][33];
    __shared__ float vt[Tt][33];
    __shared__ float sc[Tt * Tt];

    const int tid = threadIdx.x;

    for (int idx = tid; idx < Tt * DHd; idx += 128) {
        int t = idx >> 5, d = idx & 31;
        const float* r = base + (size_t)t * (3 * Dm);
        q [t][d] = r[d];
        kt[t][d] = r[Dm + d];
        vt[t][d] = r[2 * Dm + d];
    }
    __syncthreads();

    const float scale = 0.17677669529663689f;
    for (int idx = tid; idx < Tt * Tt; idx += 128) {
        int i = idx / Tt, j = idx - i * Tt;
        float s = 0.f;
        #pragma unroll
        for (int d = 0; d < DHd; d++) s += q[i][d] * kt[j][d];
        sc[idx] = s * scale;
    }
    __syncthreads();

    if (tid < Tt) {
        float m = -3.4e38f;
        for (int j = 0; j < Tt; j++) m = fmaxf(m, sc[tid * Tt + j]);
        float ssum = 0.f;
        for (int j = 0; j < Tt; j++) {
            float e = expf(sc[tid * Tt + j] - m);
            sc[tid * Tt + j] = e;
            ssum += e;
        }
        float inv = 1.0f / ssum;
        for (int j = 0; j < Tt; j++) sc[tid * Tt + j] *= inv;
    }
    __syncthreads();

    for (int idx = tid; idx < Tt * DHd; idx += 128) {
        int i = idx >> 5, d = idx & 31;
        float o = 0.f;
        for (int j = 0; j < Tt; j++) o += sc[i * Tt + j] * vt[j][d];
        size_t oidx = ((size_t)b * Tt + i) * Dm + hh * DHd + d;
        __nv_bfloat16 h2, m2, l2;
        split3(o, h2, m2, l2);
        g_act0[oidx] = h2;
        g_act0[PL0 + oidx] = m2;
        g_act0[2 * PL0 + oidx] = l2;
    }
}

// ---------------- residual add + LayerNorm ----------------
__global__ __launch_bounds__(256) void add_ln_k(
    float* __restrict__ h, const float* __restrict__ t,
    const float* __restrict__ g, const float* __restrict__ bb)
{
    __shared__ float sm[32];
    const int tid = threadIdx.x;
    const size_t base = (size_t)blockIdx.x * Dm;
    float v = h[base + tid] + t[base + tid];
    float mean = bred256(v, sm) * (1.0f / Dm);
    float d = v - mean;
    float var = bred256(d * d, sm) * (1.0f / Dm);
    float o = d * rsqrtf(var + LN_EPS) * g[tid] + bb[tid];
    h[base + tid] = o;
    __nv_bfloat16 hh, mm, ll;
    split3(o, hh, mm, ll);
    g_act0[base + tid] = hh;
    g_act0[PL0 + base + tid] = mm;
    g_act0[2 * PL0 + base + tid] = ll;
}

// ---------------- final head ----------------
__global__ __launch_bounds__(256) void final_head_k(
    const float* __restrict__ lnfg, const float* __restrict__ lnfb,
    const float* __restrict__ Wout, const float* __restrict__ bout)
{
    __shared__ float xn[Dm];
    __shared__ float sm[32];
    const int tid = threadIdx.x;
    const int b = blockIdx.x;
    float v = g_h[(size_t)b * Tt * Dm + tid];
    float mean = bred256(v, sm) * (1.0f / Dm);
    float d = v - mean;
    float var = bred256(d * d, sm) * (1.0f / Dm);
    xn[tid] = d * rsqrtf(var + LN_EPS) * lnfg[tid] + lnfb[tid];
    __syncthreads();
    if (tid < Ed) {
        const float* w = Wout + (size_t)tid * Dm;
        float a = bout[tid];
        #pragma unroll 8
        for (int t = 0; t < Dm; t++) a += xn[t] * w[t];
        g_ze[(size_t)b * Ed + tid] = a;
    }
}

// ---------------- codebook norms ----------------
__global__ __launch_bounds__(128) void cnorm_k(const float* __restrict__ cb) {
    __shared__ float sm[4];
    const int tid = threadIdx.x;
    float v = cb[(size_t)blockIdx.x * Ed + tid];
    v *= v;
    #pragma unroll
    for (int o = 16; o > 0; o >>= 1) v += __shfl_down_sync(0xffffffffu, v, o);
    if ((tid & 31) == 0) sm[tid >> 5] = v;
    __syncthreads();
    if (tid == 0) g_cnorm[blockIdx.x] = sm[0] + sm[1] + sm[2] + sm[3];
}

// ---------------- VQ ----------------
__global__ __launch_bounds__(256) void vq_k(const float* __restrict__ cb) {
    __shared__ float ze[Ed];
    __shared__ float bm[256];
    __shared__ int   bi[256];
    __shared__ int   chosen;
    __shared__ float sm[32];
    const int tid = threadIdx.x;
    const int b = blockIdx.x;
    if (tid < Ed) ze[tid] = g_ze[(size_t)b * Ed + tid];
    __syncthreads();

    float best = 3.4e38f;
    int besti = 0x7fffffff;
    for (int k = tid; k < Kcb; k += 256) {
        const float* c = cb + (size_t)k * Ed;
        float dot = 0.f;
        #pragma unroll 4
        for (int e = 0; e < Ed; e++) dot += ze[e] * c[e];
        float dd = g_cnorm[k] - 2.0f * dot;
        if (dd < best || (dd == best && k < besti)) { best = dd; besti = k; }
    }
    bm[tid] = best; bi[tid] = besti;
    __syncthreads();
    for (int off = 128; off > 0; off >>= 1) {
        if (tid < off) {
            float ob = bm[tid + off]; int oi = bi[tid + off];
            if (ob < bm[tid] || (ob == bm[tid] && oi < bi[tid])) { bm[tid] = ob; bi[tid] = oi; }
        }
        __syncthreads();
    }
    if (tid == 0) {
        chosen = bi[0];
        g_idx[b] = bi[0];
        atomicAdd(&g_hist[bi[0]], 1);
    }
    __syncthreads();

    const int kk = chosen;
    float part = 0.f;
    if (tid < Ed) {
        float diff = cb[(size_t)kk * Ed + tid] - ze[tid];
        part = diff * diff;
    }
    float tot = bred256(part, sm);
    if (tid == 0) g_losspart[b] = tot;
}

// ---------------- decoder ----------------
__global__ __launch_bounds__(256) void decoder_k(
    const float* __restrict__ cb,
    const float* __restrict__ Wd1, const float* __restrict__ bd1,
    const float* __restrict__ lndg, const float* __restrict__ lndb,
    const float* __restrict__ Wd2, const float* __restrict__ bd2,
    const float* __restrict__ Wd3, const float* __restrict__ bd3,
    float* __restrict__ outp)
{
    __shared__ float zq[Ed];
    __shared__ float d1[Dm];
    __shared__ float d2s[Ed];
    __shared__ float sm[32];
    const int tid = threadIdx.x;
    const int b = blockIdx.x;
    const int ci = g_idx[b];
    if (tid < Ed) zq[tid] = cb[(size_t)ci * Ed + tid];
    __syncthreads();

    float t1 = bd1[tid];
    {
        const float* w = Wd1 + (size_t)tid * Ed;
        #pragma unroll 4
        for (int e = 0; e < Ed; e++) t1 += zq[e] * w[e];
    }
    float mean = bred256(t1, sm) * (1.0f / Dm);
    float dd = t1 - mean;
    float var = bred256(dd * dd, sm) * (1.0f / Dm);
    float xg = dd * rsqrtf(var + LN_EPS) * lndg[tid] + lndb[tid];
    d1[tid] = gelu_exact(xg);
    __syncthreads();

    if (tid < Ed) {
        const float* w2 = Wd2 + (size_t)tid * Dm;
        float t2 = bd2[tid];
        #pragma unroll 8
        for (int t = 0; t < Dm; t++) t2 += d1[t] * w2[t];
        d2s[tid] = gelu_exact(t2);
    }
    __syncthreads();

    if (tid < 2) {
        const float* w3 = Wd3 + (size_t)tid * Ed;
        float vv = bd3[tid];
        #pragma unroll 4
        for (int e = 0; e < Ed; e++) vv += d2s[e] * w3[e];
        outp[(size_t)b * 2 + tid] = vv;
    }
    if (tid == 2) outp[(size_t)Bsz * 2 + b] = (float)ci;
}

// ---------------- scalars ----------------
__global__ __launch_bounds__(1024) void scalars_k(float* __restrict__ outp) {
    __shared__ float sm[32];
    const int tid = threadIdx.x;

    float p = (float)g_hist[tid] * (1.0f / (float)Bsz);
    float term = p * logf(p + 1e-10f);
    float v = term;
    #pragma unroll
    for (int o = 16; o > 0; o >>= 1) v += __shfl_down_sync(0xffffffffu, v, o);
    if ((tid & 31) == 0) sm[tid >> 5] = v;
    __syncthreads();
    float ent = 0.f;
    if (tid == 0) {
        for (int i = 0; i < 32; i++) ent += sm[i];
        sm[0] = ent;
    }
    __syncthreads();
    ent = sm[0];
    __syncthreads();

    float lp = g_losspart[tid] + g_losspart[tid + 1024];
    #pragma unroll
    for (int o = 16; o > 0; o >>= 1) lp += __shfl_down_sync(0xffffffffu, lp, o);
    if ((tid & 31) == 0) sm[tid >> 5] = lp;
    __syncthreads();
    if (tid == 0) {
        float tot = 0.f;
        for (int i = 0; i < 32; i++) tot += sm[i];
        outp[(size_t)Bsz * 2 + Bsz + 0] = 0.1f * tot / ((float)Bsz * (float)Ed);
        outp[(size_t)Bsz * 2 + Bsz + 1] = expf(-ent);
    }
}

__global__ __launch_bounds__(1024) void zero_k() {
    g_hist[threadIdx.x] = 0;
}

// ---------------- host ----------------
template <typename T>
static T* sym_addr(const void* sym) {
    void* p = nullptr;
    cudaGetSymbolAddress(&p, sym);
    return (T*)p;
}

extern "C" void kernel_launch(void* const* d_in, const int* in_sizes, int n_in,
                              void* d_out, int out_size)
{
    (void)in_sizes; (void)n_in; (void)out_size;
    const float* x     = (const float*)d_in[0];
    const float* W_in  = (const float*)d_in[1];
    const float* b_in  = (const float*)d_in[2];
    const float* cls   = (const float*)d_in[3];
    const float* Wqkv  = (const float*)d_in[4];
    const float* bqkv  = (const float*)d_in[5];
    const float* Wo    = (const float*)d_in[6];
    const float* bo    = (const float*)d_in[7];
    const float* W1    = (const float*)d_in[8];
    const float* b1    = (const float*)d_in[9];
    const float* W2    = (const float*)d_in[10];
    const float* b2    = (const float*)d_in[11];
    const float* ln1g  = (const float*)d_in[12];
    const float* ln1b  = (const float*)d_in[13];
    const float* ln2g  = (const float*)d_in[14];
    const float* ln2b  = (const float*)d_in[15];
    const float* lnfg  = (const float*)d_in[16];
    const float* lnfb  = (const float*)d_in[17];
    const float* Wout  = (const float*)d_in[18];
    const float* bout  = (const float*)d_in[19];
    const float* cb    = (const float*)d_in[20];
    const float* Wd1   = (const float*)d_in[21];
    const float* bd1   = (const float*)d_in[22];
    const float* lndg  = (const float*)d_in[23];
    const float* lndb  = (const float*)d_in[24];
    const float* Wd2   = (const float*)d_in[25];
    const float* bd2   = (const float*)d_in[26];
    const float* Wd3   = (const float*)d_in[27];
    const float* bd3   = (const float*)d_in[28];
    float* outp = (float*)d_out;

    float* pH    = sym_addr<float>(g_h);
    float* pQkv  = sym_addr<float>(g_qkv);
    float* pTmp  = sym_addr<float>(g_tmp);
    __nv_bfloat16* pAct0 = sym_addr<__nv_bfloat16>(g_act0);
    __nv_bfloat16* pAct1 = sym_addr<__nv_bfloat16>(g_act1);
    __nv_bfloat16* pWq = sym_addr<__nv_bfloat16>(g_wqkvb);
    __nv_bfloat16* pWo = sym_addr<__nv_bfloat16>(g_wob);
    __nv_bfloat16* pW1 = sym_addr<__nv_bfloat16>(g_w1b);
    __nv_bfloat16* pW2 = sym_addr<__nv_bfloat16>(g_w2b);

    cudaFuncSetAttribute(bfgemm_k<0>, cudaFuncAttributeMaxDynamicSharedMemorySize, SMEM_DYN);
    cudaFuncSetAttribute(bfgemm_k<1>, cudaFuncAttributeMaxDynamicSharedMemorySize, SMEM_DYN);

    zero_k<<<1, 1024>>>();
    cnorm_k<<<Kcb, 128>>>(cb);
    cls_fill_k<<<Bsz, 256>>>(cls);

    // weight splits
    for (int i = 0; i < NL; i++) {
        conv3_k<<<(WQKV_SZ + 255) / 256, 256>>>(Wqkv + (size_t)i * WQKV_SZ,
            pWq + ((size_t)i * 3 + 0) * WQKV_SZ, pWq + ((size_t)i * 3 + 1) * WQKV_SZ,
            pWq + ((size_t)i * 3 + 2) * WQKV_SZ, WQKV_SZ);
        conv3_k<<<(WO_SZ + 255) / 256, 256>>>(Wo + (size_t)i * WO_SZ,
            pWo + ((size_t)i * 3 + 0) * WO_SZ, pWo + ((size_t)i * 3 + 1) * WO_SZ,
            pWo + ((size_t)i * 3 + 2) * WO_SZ, WO_SZ);
        conv3_k<<<(W1_SZ + 255) / 256, 256>>>(W1 + (size_t)i * W1_SZ,
            pW1 + ((size_t)i * 3 + 0) * W1_SZ, pW1 + ((size_t)i * 3 + 1) * W1_SZ,
            pW1 + ((size_t)i * 3 + 2) * W1_SZ, W1_SZ);
        conv3_k<<<(W2_SZ + 255) / 256, 256>>>(W2 + (size_t)i * W2_SZ,
            pW2 + ((size_t)i * 3 + 0) * W2_SZ, pW2 + ((size_t)i * 3 + 1) * W2_SZ,
            pW2 + ((size_t)i * 3 + 2) * W2_SZ, W2_SZ);
    }

    // input projection + PE (fp32, K=142) -> g_h + g_act0 planes
    gemm128_k<2, 0><<<dim3(Dm / 128, (Bsz * Ssz) / 128), 256>>>(
        x, W_in, b_in, pH, Bsz * Ssz, Dm, Cin);

    for (int i = 0; i < NL; i++) {
        bfgemm_k<0><<<dim3(768 / 128, MTOK / 128), 256, SMEM_DYN>>>(
            pAct0, PL0, pWq + (size_t)i * 3 * WQKV_SZ, (size_t)WQKV_SZ,
            bqkv + (size_t)i * 3 * Dm, pQkv, MTOK, 3 * Dm, Dm);
        attn_k<<<Bsz * NH, 128>>>(pQkv);
        bfgemm_k<0><<<dim3(Dm / 128, MTOK / 128), 256, SMEM_DYN>>>(
            pAct0, PL0, pWo + (size_t)i * 3 * WO_SZ, (size_t)WO_SZ,
            bo + (size_t)i * Dm, pTmp, MTOK, Dm, Dm);
        add_ln_k<<<MTOK, 256>>>(pH, pTmp, ln1g + (size_t)i * Dm, ln1b + (size_t)i * Dm);
        bfgemm_k<1><<<dim3(FFd / 128, MTOK / 128), 256, SMEM_DYN>>>(
            pAct0, PL0, pW1 + (size_t)i * 3 * W1_SZ, (size_t)W1_SZ,
            b1 + (size_t)i * FFd, pTmp /*unused*/, MTOK, FFd, Dm);
        bfgemm_k<0><<<dim3(Dm / 128, MTOK / 128), 256, SMEM_DYN>>>(
            pAct1, PL1, pW2 + (size_t)i * 3 * W2_SZ, (size_t)W2_SZ,
            b2 + (size_t)i * Dm, pTmp, MTOK, Dm, FFd);
        add_ln_k<<<MTOK, 256>>>(pH, pTmp, ln2g + (size_t)i * Dm, ln2b + (size_t)i * Dm);
    }

    final_head_k<<<Bsz, 256>>>(lnfg, lnfb, Wout, bout);
    vq_k<<<Bsz, 256>>>(cb);
    decoder_k<<<Bsz, 256>>>(cb, Wd1, bd1, lndg, lndb, Wd2, bd2, Wd3, bd3, outp);
    scalars_k<<<1, 1024>>>(outp);
}

// round 6
// speedup vs baseline: 4.5886x; 1.3607x over previous
#include <cuda_runtime.h>
#include <cuda_bf16.h>
#include <math.h>
#include <stdint.h>

// ---------------- problem constants ----------------
#define Bsz 2048
#define Ssz 64
#define Cin 142
#define Dm  256
#define NH  8
#define DHd 32
#define FFd 512
#define NL  3
#define Ed  128
#define Kcb 1024
#define Tt  65          // S+1
#define MTOK (Bsz*Tt)   // 133120
#define LN_EPS 1e-5f

#define PL0 ((size_t)MTOK*Dm)    // plane stride act0
#define PL1 ((size_t)MTOK*FFd)   // plane stride act1
#define WQKV_SZ (3*Dm*Dm)
#define WO_SZ   (Dm*Dm)
#define W1_SZ   (FFd*Dm)
#define W2_SZ   (Dm*FFd)
#define WLAYER  (WQKV_SZ+WO_SZ+W1_SZ+W2_SZ)   // 524288

// ---------------- scratch (device globals; no allocation allowed) ----------------
__device__ float g_h   [(size_t)Bsz*Tt*Dm];
__device__ float g_qkv [(size_t)Bsz*Tt*3*Dm];
__device__ float g_tmp [(size_t)Bsz*Tt*Dm];
__device__ float g_ze  [(size_t)Bsz*Ed];
__device__ int   g_idx [Bsz];
__device__ float g_cnorm[Kcb];
__device__ int   g_hist[Kcb];
__device__ float g_losspart[Bsz];

// bf16 2-split activation planes (hi, lo)
__device__ __nv_bfloat16 g_act0[2*PL0];
__device__ __nv_bfloat16 g_act1[2*PL1];
// bf16 2-split weights
__device__ __nv_bfloat16 g_wqkvb[(size_t)NL*2*WQKV_SZ];
__device__ __nv_bfloat16 g_wob  [(size_t)NL*2*WO_SZ];
__device__ __nv_bfloat16 g_w1b  [(size_t)NL*2*W1_SZ];
__device__ __nv_bfloat16 g_w2b  [(size_t)NL*2*W2_SZ];

// ---------------- low-level helpers ----------------
__device__ __forceinline__ uint32_t smem_to_u32(const void* p) {
    uint32_t a;
    asm("{ .reg .u64 t; cvta.to.shared.u64 t, %1; cvt.u32.u64 %0, t; }" : "=r"(a) : "l"(p));
    return a;
}
__device__ __forceinline__ void cp_async16(uint32_t saddr, const void* gaddr) {
    asm volatile("cp.async.cg.shared.global [%0], [%1], 16;" :: "r"(saddr), "l"(gaddr));
}
__device__ __forceinline__ void ldsm4(uint32_t* r, uint32_t addr) {
    asm volatile("ldmatrix.sync.aligned.m8n8.x4.shared.b16 {%0,%1,%2,%3}, [%4];"
        : "=r"(r[0]), "=r"(r[1]), "=r"(r[2]), "=r"(r[3]) : "r"(addr));
}
__device__ __forceinline__ void mma16816(float* c, const uint32_t* a, const uint32_t* b) {
    asm volatile(
        "mma.sync.aligned.m16n8k16.row.col.f32.bf16.bf16.f32 "
        "{%0,%1,%2,%3}, {%4,%5,%6,%7}, {%8,%9}, {%0,%1,%2,%3};"
        : "+f"(c[0]), "+f"(c[1]), "+f"(c[2]), "+f"(c[3])
        : "r"(a[0]), "r"(a[1]), "r"(a[2]), "r"(a[3]), "r"(b[0]), "r"(b[1]));
}
__device__ __forceinline__ float gelu_exact(float x) {
    return 0.5f * x * (1.0f + erff(x * 0.7071067811865475f));
}
__device__ __forceinline__ void split2(float v, __nv_bfloat16& h, __nv_bfloat16& l) {
    h = __float2bfloat16(v);
    l = __float2bfloat16(v - __bfloat162float(h));
}
__device__ __forceinline__ float bred256(float v, float* sm) {
    int tid = threadIdx.x;
    #pragma unroll
    for (int o = 16; o > 0; o >>= 1) v += __shfl_down_sync(0xffffffffu, v, o);
    if ((tid & 31) == 0) sm[tid >> 5] = v;
    __syncthreads();
    if (tid == 0) {
        float t = 0.f;
        #pragma unroll
        for (int i = 0; i < 8; i++) t += sm[i];
        sm[0] = t;
    }
    __syncthreads();
    float r = sm[0];
    __syncthreads();
    return r;
}
__device__ __forceinline__ float pe_val(int s, int c) {
    int j = c >> 1;
    float freq = expf(-(float)(2 * j) * (9.210340371976184f / 256.0f));
    float ang = (float)s * freq;
    return (c & 1) ? cosf(ang) : sinf(ang);
}

// ---------------- mma.sync bf16 2-split (3-term) GEMM ----------------
// C[M,N] = A[M,K] @ W[N,K]^T + bias   (A,W as hi/lo bf16 planes)
// tile 128x128, BK=32, 3-stage cp.async pipeline, 8 warps, warp tile 64x32.
// smem plane: 128 rows x 64B with 16B-chunk XOR swizzle.
#define PLANE_B 8192
#define STAGE_B 32768          // 4 planes (A-hi, A-lo, W-hi, W-lo)
#define SMEM_DYN (3*STAGE_B)   // 96 KB

__device__ __forceinline__ uint32_t sw_addr(uint32_t plane_base, int r, int colk) {
    int chunk = (colk >> 3) ^ ((r >> 1) & 3);
    return plane_base + r * 64 + (chunk << 4) + ((colk & 7) << 1);
}

__device__ __forceinline__ void issue_stage(
    uint32_t sbase, const __nv_bfloat16* __restrict__ A, size_t aps,
    const __nv_bfloat16* __restrict__ W, size_t wps,
    int row0, int col0, int K, int k0, int tid)
{
    #pragma unroll
    for (int i = 0; i < 8; i++) {
        const int plane = i >> 1;
        const int idx = ((i & 1) << 8) + tid;     // 0..511
        const int r = idx >> 2, c16 = idx & 3;
        const __nv_bfloat16* src = (plane < 2)
            ? A + (size_t)plane * aps + (size_t)(row0 + r) * K + (k0 + c16 * 8)
            : W + (size_t)(plane - 2) * wps + (size_t)(col0 + r) * K + (k0 + c16 * 8);
        uint32_t dst = sbase + plane * PLANE_B + r * 64 + ((c16 ^ ((r >> 1) & 3)) << 4);
        cp_async16(dst, src);
    }
}

// EPI 0: fp32 out. EPI 1: gelu -> 2-plane bf16 out to g_act1.
template <int EPI>
__global__ __launch_bounds__(256, 2)
void bfgemm_k(const __nv_bfloat16* __restrict__ A, size_t aps,
              const __nv_bfloat16* __restrict__ W, size_t wps,
              const float* __restrict__ bias, float* __restrict__ C,
              int M, int N, int K)
{
    extern __shared__ char smem[];
    const uint32_t sb = smem_to_u32(smem);
    const int tid = threadIdx.x;
    const int lane = tid & 31, wid = tid >> 5;
    const int row0 = blockIdx.y * 128;
    const int col0 = blockIdx.x * 128;
    const int wm0 = (wid & 1) * 64;
    const int wn0 = (wid >> 1) * 32;
    const int qr = lane >> 2, qc = lane & 3;

    // ldmatrix lane-address components
    const int lj = lane >> 3;            // matrix index 0..3
    const int lr8 = lane & 7;            // row within 8x8 matrix
    const int a_row_off = ((lj & 1) << 3) + lr8;   // A: +0/+8 rows
    const int a_k_off   = (lj >> 1) << 3;          // A: +0/+8 k
    const int b_row_off = ((lj >> 1) << 3) + lr8;  // B: +0/+8 n
    const int b_k_off   = (lj & 1) << 3;           // B: +0/+8 k

    float acc[4][4][4];
    #pragma unroll
    for (int a = 0; a < 4; a++)
        #pragma unroll
        for (int b = 0; b < 4; b++)
            #pragma unroll
            for (int c = 0; c < 4; c++) acc[a][b][c] = 0.f;

    const int nk = K >> 5;

    issue_stage(sb, A, aps, W, wps, row0, col0, K, 0, tid);
    asm volatile("cp.async.commit_group;" ::: "memory");
    issue_stage(sb + STAGE_B, A, aps, W, wps, row0, col0, K, 32, tid);
    asm volatile("cp.async.commit_group;" ::: "memory");

    for (int s = 0; s < nk; s++) {
        if (s + 2 < nk) {
            issue_stage(sb + ((s + 2) % 3) * STAGE_B, A, aps, W, wps, row0, col0, K, (s + 2) << 5, tid);
            asm volatile("cp.async.commit_group;" ::: "memory");
            asm volatile("cp.async.wait_group 2;" ::: "memory");
        } else if (s + 1 < nk) {
            asm volatile("cp.async.wait_group 1;" ::: "memory");
        } else {
            asm volatile("cp.async.wait_group 0;" ::: "memory");
        }
        __syncthreads();

        const uint32_t stg = sb + (s % 3) * STAGE_B;
        const uint32_t ah_b = stg;                 // A hi
        const uint32_t al_b = stg + PLANE_B;       // A lo
        const uint32_t wh_b = stg + 2 * PLANE_B;   // W hi
        const uint32_t wl_b = stg + 3 * PLANE_B;   // W lo

        #pragma unroll
        for (int kk = 0; kk < 32; kk += 16) {
            uint32_t areg[4][4];       // current A fragments (hi, then overwritten by lo)
            uint32_t bh[4][2], bl[4][2];

            // load B-hi
            #pragma unroll
            for (int np = 0; np < 2; np++) {
                uint32_t t4[4];
                ldsm4(t4, sw_addr(wh_b, wn0 + np * 16 + b_row_off, kk + b_k_off));
                bh[np * 2][0] = t4[0]; bh[np * 2][1] = t4[1];
                bh[np * 2 + 1][0] = t4[2]; bh[np * 2 + 1][1] = t4[3];
            }
            // load A-hi, mma hh
            #pragma unroll
            for (int mi = 0; mi < 4; mi++)
                ldsm4(areg[mi], sw_addr(ah_b, wm0 + mi * 16 + a_row_off, kk + a_k_off));
            #pragma unroll
            for (int mi = 0; mi < 4; mi++)
                #pragma unroll
                for (int ni = 0; ni < 4; ni++)
                    mma16816(acc[mi][ni], areg[mi], bh[ni]);
            // load B-lo, mma hl (A-hi x W-lo)
            #pragma unroll
            for (int np = 0; np < 2; np++) {
                uint32_t t4[4];
                ldsm4(t4, sw_addr(wl_b, wn0 + np * 16 + b_row_off, kk + b_k_off));
                bl[np * 2][0] = t4[0]; bl[np * 2][1] = t4[1];
                bl[np * 2 + 1][0] = t4[2]; bl[np * 2 + 1][1] = t4[3];
            }
            #pragma unroll
            for (int mi = 0; mi < 4; mi++)
                #pragma unroll
                for (int ni = 0; ni < 4; ni++)
                    mma16816(acc[mi][ni], areg[mi], bl[ni]);
            // load A-lo, mma lh (A-lo x W-hi)
            #pragma unroll
            for (int mi = 0; mi < 4; mi++)
                ldsm4(areg[mi], sw_addr(al_b, wm0 + mi * 16 + a_row_off, kk + a_k_off));
            #pragma unroll
            for (int mi = 0; mi < 4; mi++)
                #pragma unroll
                for (int ni = 0; ni < 4; ni++)
                    mma16816(acc[mi][ni], areg[mi], bh[ni]);
        }
        __syncthreads();
    }

    // ---- epilogue ----
    #pragma unroll
    for (int mi = 0; mi < 4; mi++) {
        #pragma unroll
        for (int ni = 0; ni < 4; ni++) {
            int col = col0 + wn0 + ni * 8 + qc * 2;
            float b0 = bias[col], b1 = bias[col + 1];
            #pragma unroll
            for (int half = 0; half < 2; half++) {
                int r = row0 + wm0 + mi * 16 + qr + half * 8;
                float v0 = acc[mi][ni][half * 2 + 0] + b0;
                float v1 = acc[mi][ni][half * 2 + 1] + b1;
                size_t o = (size_t)r * N + col;
                if (EPI == 0) {
                    *reinterpret_cast<float2*>(C + o) = make_float2(v0, v1);
                } else {
                    float g0 = gelu_exact(v0), g1 = gelu_exact(v1);
                    __nv_bfloat16 h0, l0, h1, l1;
                    split2(g0, h0, l0);
                    split2(g1, h1, l1);
                    *reinterpret_cast<__nv_bfloat162*>(&g_act1[o]) = __nv_bfloat162(h0, h1);
                    *reinterpret_cast<__nv_bfloat162*>(&g_act1[PL1 + o]) = __nv_bfloat162(l0, l1);
                }
            }
        }
    }
}

// ---------------- fused weight split conversion (single launch) ----------------
__global__ __launch_bounds__(256) void convw_k(
    const float* __restrict__ Wqkv, const float* __restrict__ Wo,
    const float* __restrict__ W1, const float* __restrict__ W2)
{
    const size_t total = (size_t)NL * WLAYER;
    for (size_t i = (size_t)blockIdx.x * blockDim.x + threadIdx.x; i < total;
         i += (size_t)gridDim.x * blockDim.x) {
        int layer = (int)(i / WLAYER);
        int off = (int)(i % WLAYER);
        float v; __nv_bfloat16 *dh, *dl;
        if (off < WQKV_SZ) {
            v = Wqkv[(size_t)layer * WQKV_SZ + off];
            dh = g_wqkvb + ((size_t)layer * 2 + 0) * WQKV_SZ + off;
            dl = g_wqkvb + ((size_t)layer * 2 + 1) * WQKV_SZ + off;
        } else if (off < WQKV_SZ + WO_SZ) {
            int o2 = off - WQKV_SZ;
            v = Wo[(size_t)layer * WO_SZ + o2];
            dh = g_wob + ((size_t)layer * 2 + 0) * WO_SZ + o2;
            dl = g_wob + ((size_t)layer * 2 + 1) * WO_SZ + o2;
        } else if (off < WQKV_SZ + WO_SZ + W1_SZ) {
            int o2 = off - WQKV_SZ - WO_SZ;
            v = W1[(size_t)layer * W1_SZ + o2];
            dh = g_w1b + ((size_t)layer * 2 + 0) * W1_SZ + o2;
            dl = g_w1b + ((size_t)layer * 2 + 1) * W1_SZ + o2;
        } else {
            int o2 = off - WQKV_SZ - WO_SZ - W1_SZ;
            v = W2[(size_t)layer * W2_SZ + o2];
            dh = g_w2b + ((size_t)layer * 2 + 0) * W2_SZ + o2;
            dl = g_w2b + ((size_t)layer * 2 + 1) * W2_SZ + o2;
        }
        __nv_bfloat16 a, b;
        split2(v, a, b);
        *dh = a; *dl = b;
    }
}

// ---------------- fp32 GEMM (input projection, K=142) ----------------
__global__ __launch_bounds__(256) void gemm128_k(
    const float* __restrict__ A, const float* __restrict__ W,
    const float* __restrict__ bias, float* __restrict__ C,
    int M, int N, int K)
{
    __shared__ float As[2][8][128];
    __shared__ float Bs[2][8][128];

    const int tid  = threadIdx.x;
    const int row0 = blockIdx.y * 128;
    const int col0 = blockIdx.x * 128;
    const int lr  = tid >> 1;
    const int lk4 = (tid & 1) * 4;
    const int tx = tid & 15;
    const int ty = tid >> 4;

    float acc[8][8];
    #pragma unroll
    for (int i = 0; i < 8; i++)
        #pragma unroll
        for (int j = 0; j < 8; j++) acc[i][j] = 0.f;

    const float* Arow = A + (size_t)(row0 + lr) * K;
    const float* Wrow = W + (size_t)(col0 + lr) * K;
    const int nk = (K + 7) / 8;
    float ra[4], rb[4];

    {
        #pragma unroll
        for (int i = 0; i < 4; i++) {
            int kg = lk4 + i;
            ra[i] = (kg < K) ? Arow[kg] : 0.f;
            rb[i] = (kg < K) ? Wrow[kg] : 0.f;
        }
        #pragma unroll
        for (int i = 0; i < 4; i++) {
            As[0][lk4 + i][lr] = ra[i];
            Bs[0][lk4 + i][lr] = rb[i];
        }
    }
    __syncthreads();

    int buf = 0;
    for (int s = 0; s < nk; s++) {
        const bool more = (s + 1 < nk);
        if (more) {
            int k0 = (s + 1) * 8;
            #pragma unroll
            for (int i = 0; i < 4; i++) {
                int kg = k0 + lk4 + i;
                ra[i] = (kg < K) ? Arow[kg] : 0.f;
                rb[i] = (kg < K) ? Wrow[kg] : 0.f;
            }
        }
        #pragma unroll
        for (int k = 0; k < 8; k++) {
            float4 a0 = *reinterpret_cast<const float4*>(&As[buf][k][ty << 2]);
            float4 a1 = *reinterpret_cast<const float4*>(&As[buf][k][(ty << 2) + 64]);
            float4 b0 = *reinterpret_cast<const float4*>(&Bs[buf][k][tx << 2]);
            float4 b1 = *reinterpret_cast<const float4*>(&Bs[buf][k][(tx << 2) + 64]);
            float a[8] = {a0.x, a0.y, a0.z, a0.w, a1.x, a1.y, a1.z, a1.w};
            float b[8] = {b0.x, b0.y, b0.z, b0.w, b1.x, b1.y, b1.z, b1.w};
            #pragma unroll
            for (int i = 0; i < 8; i++)
                #pragma unroll
                for (int j = 0; j < 8; j++) acc[i][j] += a[i] * b[j];
        }
        if (more) {
            #pragma unroll
            for (int i = 0; i < 4; i++) {
                As[buf ^ 1][lk4 + i][lr] = ra[i];
                Bs[buf ^ 1][lk4 + i][lr] = rb[i];
            }
            __syncthreads();
            buf ^= 1;
        }
    }

    #pragma unroll
    for (int ih = 0; ih < 2; ih++) {
        #pragma unroll
        for (int i = 0; i < 4; i++) {
            int r = row0 + (ty << 2) + i + ih * 64;
            #pragma unroll
            for (int jh = 0; jh < 2; jh++) {
                int c = col0 + (tx << 2) + jh * 64;
                float4 bv = *reinterpret_cast<const float4*>(bias + c);
                float vv[4];
                vv[0] = acc[ih * 4 + i][jh * 4 + 0] + bv.x;
                vv[1] = acc[ih * 4 + i][jh * 4 + 1] + bv.y;
                vv[2] = acc[ih * 4 + i][jh * 4 + 2] + bv.z;
                vv[3] = acc[ih * 4 + i][jh * 4 + 3] + bv.w;
                int ss = r & 63;
                int bb = r >> 6;
                #pragma unroll
                for (int q = 0; q < 4; q++) vv[q] += pe_val(ss, c + q);
                size_t out = ((size_t)bb * Tt + 1 + ss) * Dm + c;
                #pragma unroll
                for (int q = 0; q < 4; q++) {
                    __nv_bfloat16 hh, ll;
                    split2(vv[q], hh, ll);
                    g_act0[out + q] = hh;
                    g_act0[PL0 + out + q] = ll;
                }
                *reinterpret_cast<float4*>(C + out) = make_float4(vv[0], vv[1], vv[2], vv[3]);
            }
        }
    }
}

// ---------------- cls token fill ----------------
__global__ __launch_bounds__(256) void cls_fill_k(const float* __restrict__ cls) {
    float v = cls[threadIdx.x];
    size_t idx = (size_t)blockIdx.x * Tt * Dm + threadIdx.x;
    g_h[idx] = v;
    __nv_bfloat16 hh, ll;
    split2(v, hh, ll);
    g_act0[idx] = hh;
    g_act0[PL0 + idx] = ll;
}

// ---------------- attention (out -> bf16 planes) ----------------
__global__ __launch_bounds__(128) void attn_k(const float* __restrict__ qkv)
{
    const int b  = blockIdx.x >> 3;
    const int hh = blockIdx.x & 7;
    const float* base = qkv + (size_t)b * Tt * (3 * Dm) + hh * DHd;

    __shared__ float q [Tt][33];
    __shared__ float kt[Tt][33];
    __shared__ float vt[Tt][33];
    __shared__ float sc[Tt * Tt];

    const int tid = threadIdx.x;

    for (int idx = tid; idx < Tt * DHd; idx += 128) {
        int t = idx >> 5, d = idx & 31;
        const float* r = base + (size_t)t * (3 * Dm);
        q [t][d] = r[d];
        kt[t][d] = r[Dm + d];
        vt[t][d] = r[2 * Dm + d];
    }
    __syncthreads();

    const float scale = 0.17677669529663689f;
    for (int idx = tid; idx < Tt * Tt; idx += 128) {
        int i = idx / Tt, j = idx - i * Tt;
        float s = 0.f;
        #pragma unroll
        for (int d = 0; d < DHd; d++) s += q[i][d] * kt[j][d];
        sc[idx] = s * scale;
    }
    __syncthreads();

    if (tid < Tt) {
        float m = -3.4e38f;
        for (int j = 0; j < Tt; j++) m = fmaxf(m, sc[tid * Tt + j]);
        float ssum = 0.f;
        for (int j = 0; j < Tt; j++) {
            float e = expf(sc[tid * Tt + j] - m);
            sc[tid * Tt + j] = e;
            ssum += e;
        }
        float inv = 1.0f / ssum;
        for (int j = 0; j < Tt; j++) sc[tid * Tt + j] *= inv;
    }
    __syncthreads();

    for (int idx = tid; idx < Tt * DHd; idx += 128) {
        int i = idx >> 5, d = idx & 31;
        float o = 0.f;
        for (int j = 0; j < Tt; j++) o += sc[i * Tt + j] * vt[j][d];
        size_t oidx = ((size_t)b * Tt + i) * Dm + hh * DHd + d;
        __nv_bfloat16 h2, l2;
        split2(o, h2, l2);
        g_act0[oidx] = h2;
        g_act0[PL0 + oidx] = l2;
    }
}

// ---------------- residual add + LayerNorm ----------------
__global__ __launch_bounds__(256) void add_ln_k(
    float* __restrict__ h, const float* __restrict__ t,
    const float* __restrict__ g, const float* __restrict__ bb)
{
    __shared__ float sm[32];
    const int tid = threadIdx.x;
    const size_t base = (size_t)blockIdx.x * Dm;
    float v = h[base + tid] + t[base + tid];
    float mean = bred256(v, sm) * (1.0f / Dm);
    float d = v - mean;
    float var = bred256(d * d, sm) * (1.0f / Dm);
    float o = d * rsqrtf(var + LN_EPS) * g[tid] + bb[tid];
    h[base + tid] = o;
    __nv_bfloat16 hh, ll;
    split2(o, hh, ll);
    g_act0[base + tid] = hh;
    g_act0[PL0 + base + tid] = ll;
}

// ---------------- final head ----------------
__global__ __launch_bounds__(256) void final_head_k(
    const float* __restrict__ lnfg, const float* __restrict__ lnfb,
    const float* __restrict__ Wout, const float* __restrict__ bout)
{
    __shared__ float xn[Dm];
    __shared__ float sm[32];
    const int tid = threadIdx.x;
    const int b = blockIdx.x;
    float v = g_h[(size_t)b * Tt * Dm + tid];
    float mean = bred256(v, sm) * (1.0f / Dm);
    float d = v - mean;
    float var = bred256(d * d, sm) * (1.0f / Dm);
    xn[tid] = d * rsqrtf(var + LN_EPS) * lnfg[tid] + lnfb[tid];
    __syncthreads();
    if (tid < Ed) {
        const float* w = Wout + (size_t)tid * Dm;
        float a = bout[tid];
        #pragma unroll 8
        for (int t = 0; t < Dm; t++) a += xn[t] * w[t];
        g_ze[(size_t)b * Ed + tid] = a;
    }
}

// ---------------- codebook norms ----------------
__global__ __launch_bounds__(128) void cnorm_k(const float* __restrict__ cb) {
    __shared__ float sm[4];
    const int tid = threadIdx.x;
    float v = cb[(size_t)blockIdx.x * Ed + tid];
    v *= v;
    #pragma unroll
    for (int o = 16; o > 0; o >>= 1) v += __shfl_down_sync(0xffffffffu, v, o);
    if ((tid & 31) == 0) sm[tid >> 5] = v;
    __syncthreads();
    if (tid == 0) g_cnorm[blockIdx.x] = sm[0] + sm[1] + sm[2] + sm[3];
}

// ---------------- VQ ----------------
__global__ __launch_bounds__(256) void vq_k(const float* __restrict__ cb) {
    __shared__ float ze[Ed];
    __shared__ float bm[256];
    __shared__ int   bi[256];
    __shared__ int   chosen;
    __shared__ float sm[32];
    const int tid = threadIdx.x;
    const int b = blockIdx.x;
    if (tid < Ed) ze[tid] = g_ze[(size_t)b * Ed + tid];
    __syncthreads();

    float best = 3.4e38f;
    int besti = 0x7fffffff;
    for (int k = tid; k < Kcb; k += 256) {
        const float* c = cb + (size_t)k * Ed;
        float dot = 0.f;
        #pragma unroll 4
        for (int e = 0; e < Ed; e++) dot += ze[e] * c[e];
        float dd = g_cnorm[k] - 2.0f * dot;
        if (dd < best || (dd == best && k < besti)) { best = dd; besti = k; }
    }
    bm[tid] = best; bi[tid] = besti;
    __syncthreads();
    for (int off = 128; off > 0; off >>= 1) {
        if (tid < off) {
            float ob = bm[tid + off]; int oi = bi[tid + off];
            if (ob < bm[tid] || (ob == bm[tid] && oi < bi[tid])) { bm[tid] = ob; bi[tid] = oi; }
        }
        __syncthreads();
    }
    if (tid == 0) {
        chosen = bi[0];
        g_idx[b] = bi[0];
        atomicAdd(&g_hist[bi[0]], 1);
    }
    __syncthreads();

    const int kk = chosen;
    float part = 0.f;
    if (tid < Ed) {
        float diff = cb[(size_t)kk * Ed + tid] - ze[tid];
        part = diff * diff;
    }
    float tot = bred256(part, sm);
    if (tid == 0) g_losspart[b] = tot;
}

// ---------------- decoder ----------------
__global__ __launch_bounds__(256) void decoder_k(
    const float* __restrict__ cb,
    const float* __restrict__ Wd1, const float* __restrict__ bd1,
    const float* __restrict__ lndg, const float* __restrict__ lndb,
    const float* __restrict__ Wd2, const float* __restrict__ bd2,
    const float* __restrict__ Wd3, const float* __restrict__ bd3,
    float* __restrict__ outp)
{
    __shared__ float zq[Ed];
    __shared__ float d1[Dm];
    __shared__ float d2s[Ed];
    __shared__ float sm[32];
    const int tid = threadIdx.x;
    const int b = blockIdx.x;
    const int ci = g_idx[b];
    if (tid < Ed) zq[tid] = cb[(size_t)ci * Ed + tid];
    __syncthreads();

    float t1 = bd1[tid];
    {
        const float* w = Wd1 + (size_t)tid * Ed;
        #pragma unroll 4
        for (int e = 0; e < Ed; e++) t1 += zq[e] * w[e];
    }
    float mean = bred256(t1, sm) * (1.0f / Dm);
    float dd = t1 - mean;
    float var = bred256(dd * dd, sm) * (1.0f / Dm);
    float xg = dd * rsqrtf(var + LN_EPS) * lndg[tid] + lndb[tid];
    d1[tid] = gelu_exact(xg);
    __syncthreads();

    if (tid < Ed) {
        const float* w2 = Wd2 + (size_t)tid * Dm;
        float t2 = bd2[tid];
        #pragma unroll 8
        for (int t = 0; t < Dm; t++) t2 += d1[t] * w2[t];
        d2s[tid] = gelu_exact(t2);
    }
    __syncthreads();

    if (tid < 2) {
        const float* w3 = Wd3 + (size_t)tid * Ed;
        float vv = bd3[tid];
        #pragma unroll 4
        for (int e = 0; e < Ed; e++) vv += d2s[e] * w3[e];
        outp[(size_t)b * 2 + tid] = vv;
    }
    if (tid == 2) outp[(size_t)Bsz * 2 + b] = (float)ci;
}

// ---------------- scalars ----------------
__global__ __launch_bounds__(1024) void scalars_k(float* __restrict__ outp) {
    __shared__ float sm[32];
    const int tid = threadIdx.x;

    float p = (float)g_hist[tid] * (1.0f / (float)Bsz);
    float term = p * logf(p + 1e-10f);
    float v = term;
    #pragma unroll
    for (int o = 16; o > 0; o >>= 1) v += __shfl_down_sync(0xffffffffu, v, o);
    if ((tid & 31) == 0) sm[tid >> 5] = v;
    __syncthreads();
    float ent = 0.f;
    if (tid == 0) {
        for (int i = 0; i < 32; i++) ent += sm[i];
        sm[0] = ent;
    }
    __syncthreads();
    ent = sm[0];
    __syncthreads();

    float lp = g_losspart[tid] + g_losspart[tid + 1024];
    #pragma unroll
    for (int o = 16; o > 0; o >>= 1) lp += __shfl_down_sync(0xffffffffu, lp, o);
    if ((tid & 31) == 0) sm[tid >> 5] = lp;
    __syncthreads();
    if (tid == 0) {
        float tot = 0.f;
        for (int i = 0; i < 32; i++) tot += sm[i];
        outp[(size_t)Bsz * 2 + Bsz + 0] = 0.1f * tot / ((float)Bsz * (float)Ed);
        outp[(size_t)Bsz * 2 + Bsz + 1] = expf(-ent);
    }
}

__global__ __launch_bounds__(1024) void zero_k() {
    g_hist[threadIdx.x] = 0;
}

// ---------------- host ----------------
template <typename T>
static T* sym_addr(const void* sym) {
    void* p = nullptr;
    cudaGetSymbolAddress(&p, sym);
    return (T*)p;
}

extern "C" void kernel_launch(void* const* d_in, const int* in_sizes, int n_in,
                              void* d_out, int out_size)
{
    (void)in_sizes; (void)n_in; (void)out_size;
    const float* x     = (const float*)d_in[0];
    const float* W_in  = (const float*)d_in[1];
    const float* b_in  = (const float*)d_in[2];
    const float* cls   = (const float*)d_in[3];
    const float* Wqkv  = (const float*)d_in[4];
    const float* bqkv  = (const float*)d_in[5];
    const float* Wo    = (const float*)d_in[6];
    const float* bo    = (const float*)d_in[7];
    const float* W1    = (const float*)d_in[8];
    const float* b1    = (const float*)d_in[9];
    const float* W2    = (const float*)d_in[10];
    const float* b2    = (const float*)d_in[11];
    const float* ln1g  = (const float*)d_in[12];
    const float* ln1b  = (const float*)d_in[13];
    const float* ln2g  = (const float*)d_in[14];
    const float* ln2b  = (const float*)d_in[15];
    const float* lnfg  = (const float*)d_in[16];
    const float* lnfb  = (const float*)d_in[17];
    const float* Wout  = (const float*)d_in[18];
    const float* bout  = (const float*)d_in[19];
    const float* cb    = (const float*)d_in[20];
    const float* Wd1   = (const float*)d_in[21];
    const float* bd1   = (const float*)d_in[22];
    const float* lndg  = (const float*)d_in[23];
    const float* lndb  = (const float*)d_in[24];
    const float* Wd2   = (const float*)d_in[25];
    const float* bd2   = (const float*)d_in[26];
    const float* Wd3   = (const float*)d_in[27];
    const float* bd3   = (const float*)d_in[28];
    float* outp = (float*)d_out;

    float* pH    = sym_addr<float>(g_h);
    float* pQkv  = sym_addr<float>(g_qkv);
    float* pTmp  = sym_addr<float>(g_tmp);
    __nv_bfloat16* pAct0 = sym_addr<__nv_bfloat16>(g_act0);
    __nv_bfloat16* pAct1 = sym_addr<__nv_bfloat16>(g_act1);
    __nv_bfloat16* pWq = sym_addr<__nv_bfloat16>(g_wqkvb);
    __nv_bfloat16* pWo = sym_addr<__nv_bfloat16>(g_wob);
    __nv_bfloat16* pW1 = sym_addr<__nv_bfloat16>(g_w1b);
    __nv_bfloat16* pW2 = sym_addr<__nv_bfloat16>(g_w2b);

    cudaFuncSetAttribute(bfgemm_k<0>, cudaFuncAttributeMaxDynamicSharedMemorySize, SMEM_DYN);
    cudaFuncSetAttribute(bfgemm_k<1>, cudaFuncAttributeMaxDynamicSharedMemorySize, SMEM_DYN);

    // launch order chosen so launch #6 is the first (hot) QKV bfgemm for ncu -s 5
    zero_k<<<1, 1024>>>();                               // 1
    cnorm_k<<<Kcb, 128>>>(cb);                           // 2
    cls_fill_k<<<Bsz, 256>>>(cls);                       // 3
    convw_k<<<1024, 256>>>(Wqkv, Wo, W1, W2);            // 4
    gemm128_k<<<dim3(Dm / 128, (Bsz * Ssz) / 128), 256>>>(
        x, W_in, b_in, pH, Bsz * Ssz, Dm, Cin);          // 5

    for (int i = 0; i < NL; i++) {
        bfgemm_k<0><<<dim3(768 / 128, MTOK / 128), 256, SMEM_DYN>>>(
            pAct0, PL0, pWq + (size_t)i * 2 * WQKV_SZ, (size_t)WQKV_SZ,
            bqkv + (size_t)i * 3 * Dm, pQkv, MTOK, 3 * Dm, Dm);      // 6 on i=0
        attn_k<<<Bsz * NH, 128>>>(pQkv);
        bfgemm_k<0><<<dim3(Dm / 128, MTOK / 128), 256, SMEM_DYN>>>(
            pAct0, PL0, pWo + (size_t)i * 2 * WO_SZ, (size_t)WO_SZ,
            bo + (size_t)i * Dm, pTmp, MTOK, Dm, Dm);
        add_ln_k<<<MTOK, 256>>>(pH, pTmp, ln1g + (size_t)i * Dm, ln1b + (size_t)i * Dm);
        bfgemm_k<1><<<dim3(FFd / 128, MTOK / 128), 256, SMEM_DYN>>>(
            pAct0, PL0, pW1 + (size_t)i * 2 * W1_SZ, (size_t)W1_SZ,
            b1 + (size_t)i * FFd, pTmp /*unused*/, MTOK, FFd, Dm);
        bfgemm_k<0><<<dim3(Dm / 128, MTOK / 128), 256, SMEM_DYN>>>(
            pAct1, PL1, pW2 + (size_t)i * 2 * W2_SZ, (size_t)W2_SZ,
            b2 + (size_t)i * Dm, pTmp, MTOK, Dm, FFd);
        add_ln_k<<<MTOK, 256>>>(pH, pTmp, ln2g + (size_t)i * Dm, ln2b + (size_t)i * Dm);
    }

    final_head_k<<<Bsz, 256>>>(lnfg, lnfb, Wout, bout);
    vq_k<<<Bsz, 256>>>(cb);
    decoder_k<<<Bsz, 256>>>(cb, Wd1, bd1, lndg, lndb, Wd2, bd2, Wd3, bd3, outp);
    scalars_k<<<1, 1024>>>(outp);
}

// round 7
// speedup vs baseline: 4.7045x; 1.0253x over previous
#include <cuda_runtime.h>
#include <cuda_bf16.h>
#include <math.h>
#include <stdint.h>

// ---------------- problem constants ----------------
#define Bsz 2048
#define Ssz 64
#define Cin 142
#define Dm  256
#define NH  8
#define DHd 32
#define FFd 512
#define NL  3
#define Ed  128
#define Kcb 1024
#define Tt  65          // S+1
#define MTOK (Bsz*Tt)   // 133120
#define LN_EPS 1e-5f

#define PL0 ((size_t)MTOK*Dm)    // plane stride act0
#define PL1 ((size_t)MTOK*FFd)   // plane stride act1
#define PLQ ((size_t)MTOK*3*Dm)  // plane stride qkv
#define WQKV_SZ (3*Dm*Dm)
#define WO_SZ   (Dm*Dm)
#define W1_SZ   (FFd*Dm)
#define W2_SZ   (Dm*FFd)
#define WLAYER  (WQKV_SZ+WO_SZ+W1_SZ+W2_SZ)

// ---------------- scratch (device globals; no allocation allowed) ----------------
__device__ float g_h   [(size_t)Bsz*Tt*Dm];
__device__ float g_tmp [(size_t)Bsz*Tt*Dm];
__device__ float g_ze  [(size_t)Bsz*Ed];
__device__ int   g_idx [Bsz];
__device__ float g_cnorm[Kcb];
__device__ int   g_hist[Kcb];
__device__ float g_losspart[Bsz];

// bf16 2-split planes (hi, lo)
__device__ __nv_bfloat16 g_act0[2*PL0];
__device__ __nv_bfloat16 g_act1[2*PL1];
__device__ __nv_bfloat16 g_qkvb[2*PLQ];
__device__ __nv_bfloat16 g_wqkvb[(size_t)NL*2*WQKV_SZ];
__device__ __nv_bfloat16 g_wob  [(size_t)NL*2*WO_SZ];
__device__ __nv_bfloat16 g_w1b  [(size_t)NL*2*W1_SZ];
__device__ __nv_bfloat16 g_w2b  [(size_t)NL*2*W2_SZ];

// ---------------- low-level helpers ----------------
__device__ __forceinline__ uint32_t smem_to_u32(const void* p) {
    uint32_t a;
    asm("{ .reg .u64 t; cvta.to.shared.u64 t, %1; cvt.u32.u64 %0, t; }" : "=r"(a) : "l"(p));
    return a;
}
__device__ __forceinline__ void cp_async16(uint32_t saddr, const void* gaddr) {
    asm volatile("cp.async.cg.shared.global [%0], [%1], 16;" :: "r"(saddr), "l"(gaddr));
}
__device__ __forceinline__ void ldsm4(uint32_t* r, uint32_t addr) {
    asm volatile("ldmatrix.sync.aligned.m8n8.x4.shared.b16 {%0,%1,%2,%3}, [%4];"
        : "=r"(r[0]), "=r"(r[1]), "=r"(r[2]), "=r"(r[3]) : "r"(addr));
}
__device__ __forceinline__ void mma16816(float* c, const uint32_t* a, const uint32_t* b) {
    asm volatile(
        "mma.sync.aligned.m16n8k16.row.col.f32.bf16.bf16.f32 "
        "{%0,%1,%2,%3}, {%4,%5,%6,%7}, {%8,%9}, {%0,%1,%2,%3};"
        : "+f"(c[0]), "+f"(c[1]), "+f"(c[2]), "+f"(c[3])
        : "r"(a[0]), "r"(a[1]), "r"(a[2]), "r"(a[3]), "r"(b[0]), "r"(b[1]));
}
__device__ __forceinline__ float gelu_exact(float x) {
    return 0.5f * x * (1.0f + erff(x * 0.7071067811865475f));
}
__device__ __forceinline__ void split2(float v, __nv_bfloat16& h, __nv_bfloat16& l) {
    h = __float2bfloat16(v);
    l = __float2bfloat16(v - __bfloat162float(h));
}
__device__ __forceinline__ float bred256(float v, float* sm) {
    int tid = threadIdx.x;
    #pragma unroll
    for (int o = 16; o > 0; o >>= 1) v += __shfl_down_sync(0xffffffffu, v, o);
    if ((tid & 31) == 0) sm[tid >> 5] = v;
    __syncthreads();
    if (tid == 0) {
        float t = 0.f;
        #pragma unroll
        for (int i = 0; i < 8; i++) t += sm[i];
        sm[0] = t;
    }
    __syncthreads();
    float r = sm[0];
    __syncthreads();
    return r;
}
__device__ __forceinline__ float pe_val(int s, int c) {
    int j = c >> 1;
    float freq = expf(-(float)(2 * j) * (9.210340371976184f / 256.0f));
    float ang = (float)s * freq;
    return (c & 1) ? cosf(ang) : sinf(ang);
}

// ---------------- mma.sync bf16 2-split (3-term) GEMM ----------------
#define PLANE_B 8192
#define STAGE_B 32768
#define SMEM_DYN (3*STAGE_B)   // 96 KB

__device__ __forceinline__ uint32_t sw_addr(uint32_t plane_base, int r, int colk) {
    int chunk = (colk >> 3) ^ ((r >> 1) & 3);
    return plane_base + r * 64 + (chunk << 4) + ((colk & 7) << 1);
}

__device__ __forceinline__ void issue_stage(
    uint32_t sbase, const __nv_bfloat16* __restrict__ A, size_t aps,
    const __nv_bfloat16* __restrict__ W, size_t wps,
    int row0, int col0, int K, int k0, int tid)
{
    #pragma unroll
    for (int i = 0; i < 8; i++) {
        const int plane = i >> 1;
        const int idx = ((i & 1) << 8) + tid;
        const int r = idx >> 2, c16 = idx & 3;
        const __nv_bfloat16* src = (plane < 2)
            ? A + (size_t)plane * aps + (size_t)(row0 + r) * K + (k0 + c16 * 8)
            : W + (size_t)(plane - 2) * wps + (size_t)(col0 + r) * K + (k0 + c16 * 8);
        uint32_t dst = sbase + plane * PLANE_B + r * 64 + ((c16 ^ ((r >> 1) & 3)) << 4);
        cp_async16(dst, src);
    }
}

// EPI 0: fp32 out to C. EPI 1: gelu -> 2-plane bf16 to g_act1. EPI 2: 2-plane bf16 to g_qkvb.
template <int EPI>
__global__ __launch_bounds__(256, 2)
void bfgemm_k(const __nv_bfloat16* __restrict__ A, size_t aps,
              const __nv_bfloat16* __restrict__ W, size_t wps,
              const float* __restrict__ bias, float* __restrict__ C,
              int M, int N, int K)
{
    extern __shared__ char smem[];
    const uint32_t sb = smem_to_u32(smem);
    const int tid = threadIdx.x;
    const int lane = tid & 31, wid = tid >> 5;
    const int row0 = blockIdx.y * 128;
    const int col0 = blockIdx.x * 128;
    const int wm0 = (wid & 1) * 64;
    const int wn0 = (wid >> 1) * 32;
    const int qr = lane >> 2, qc = lane & 3;

    const int lj = lane >> 3;
    const int lr8 = lane & 7;
    const int a_row_off = ((lj & 1) << 3) + lr8;
    const int a_k_off   = (lj >> 1) << 3;
    const int b_row_off = ((lj >> 1) << 3) + lr8;
    const int b_k_off   = (lj & 1) << 3;

    float acc[4][4][4];
    #pragma unroll
    for (int a = 0; a < 4; a++)
        #pragma unroll
        for (int b = 0; b < 4; b++)
            #pragma unroll
            for (int c = 0; c < 4; c++) acc[a][b][c] = 0.f;

    const int nk = K >> 5;

    issue_stage(sb, A, aps, W, wps, row0, col0, K, 0, tid);
    asm volatile("cp.async.commit_group;" ::: "memory");
    issue_stage(sb + STAGE_B, A, aps, W, wps, row0, col0, K, 32, tid);
    asm volatile("cp.async.commit_group;" ::: "memory");

    for (int s = 0; s < nk; s++) {
        if (s + 2 < nk) {
            issue_stage(sb + ((s + 2) % 3) * STAGE_B, A, aps, W, wps, row0, col0, K, (s + 2) << 5, tid);
            asm volatile("cp.async.commit_group;" ::: "memory");
            asm volatile("cp.async.wait_group 2;" ::: "memory");
        } else if (s + 1 < nk) {
            asm volatile("cp.async.wait_group 1;" ::: "memory");
        } else {
            asm volatile("cp.async.wait_group 0;" ::: "memory");
        }
        __syncthreads();

        const uint32_t stg = sb + (s % 3) * STAGE_B;
        const uint32_t ah_b = stg;
        const uint32_t al_b = stg + PLANE_B;
        const uint32_t wh_b = stg + 2 * PLANE_B;
        const uint32_t wl_b = stg + 3 * PLANE_B;

        #pragma unroll
        for (int kk = 0; kk < 32; kk += 16) {
            uint32_t areg[4][4];
            uint32_t bh[4][2], bl[4][2];

            #pragma unroll
            for (int np = 0; np < 2; np++) {
                uint32_t t4[4];
                ldsm4(t4, sw_addr(wh_b, wn0 + np * 16 + b_row_off, kk + b_k_off));
                bh[np * 2][0] = t4[0]; bh[np * 2][1] = t4[1];
                bh[np * 2 + 1][0] = t4[2]; bh[np * 2 + 1][1] = t4[3];
            }
            #pragma unroll
            for (int mi = 0; mi < 4; mi++)
                ldsm4(areg[mi], sw_addr(ah_b, wm0 + mi * 16 + a_row_off, kk + a_k_off));
            #pragma unroll
            for (int mi = 0; mi < 4; mi++)
                #pragma unroll
                for (int ni = 0; ni < 4; ni++)
                    mma16816(acc[mi][ni], areg[mi], bh[ni]);
            #pragma unroll
            for (int np = 0; np < 2; np++) {
                uint32_t t4[4];
                ldsm4(t4, sw_addr(wl_b, wn0 + np * 16 + b_row_off, kk + b_k_off));
                bl[np * 2][0] = t4[0]; bl[np * 2][1] = t4[1];
                bl[np * 2 + 1][0] = t4[2]; bl[np * 2 + 1][1] = t4[3];
            }
            #pragma unroll
            for (int mi = 0; mi < 4; mi++)
                #pragma unroll
                for (int ni = 0; ni < 4; ni++)
                    mma16816(acc[mi][ni], areg[mi], bl[ni]);
            #pragma unroll
            for (int mi = 0; mi < 4; mi++)
                ldsm4(areg[mi], sw_addr(al_b, wm0 + mi * 16 + a_row_off, kk + a_k_off));
            #pragma unroll
            for (int mi = 0; mi < 4; mi++)
                #pragma unroll
                for (int ni = 0; ni < 4; ni++)
                    mma16816(acc[mi][ni], areg[mi], bh[ni]);
        }
        __syncthreads();
    }

    // ---- epilogue ----
    #pragma unroll
    for (int mi = 0; mi < 4; mi++) {
        #pragma unroll
        for (int ni = 0; ni < 4; ni++) {
            int col = col0 + wn0 + ni * 8 + qc * 2;
            float b0 = bias[col], b1 = bias[col + 1];
            #pragma unroll
            for (int half = 0; half < 2; half++) {
                int r = row0 + wm0 + mi * 16 + qr + half * 8;
                float v0 = acc[mi][ni][half * 2 + 0] + b0;
                float v1 = acc[mi][ni][half * 2 + 1] + b1;
                size_t o = (size_t)r * N + col;
                if (EPI == 0) {
                    *reinterpret_cast<float2*>(C + o) = make_float2(v0, v1);
                } else if (EPI == 1) {
                    float g0 = gelu_exact(v0), g1 = gelu_exact(v1);
                    __nv_bfloat16 h0, l0, h1, l1;
                    split2(g0, h0, l0);
                    split2(g1, h1, l1);
                    *reinterpret_cast<__nv_bfloat162*>(&g_act1[o]) = __nv_bfloat162(h0, h1);
                    *reinterpret_cast<__nv_bfloat162*>(&g_act1[PL1 + o]) = __nv_bfloat162(l0, l1);
                } else {
                    __nv_bfloat16 h0, l0, h1, l1;
                    split2(v0, h0, l0);
                    split2(v1, h1, l1);
                    *reinterpret_cast<__nv_bfloat162*>(&g_qkvb[o]) = __nv_bfloat162(h0, h1);
                    *reinterpret_cast<__nv_bfloat162*>(&g_qkvb[PLQ + o]) = __nv_bfloat162(l0, l1);
                }
            }
        }
    }
}

// ---------------- fused weight split conversion ----------------
__global__ __launch_bounds__(256) void convw_k(
    const float* __restrict__ Wqkv, const float* __restrict__ Wo,
    const float* __restrict__ W1, const float* __restrict__ W2)
{
    const size_t total = (size_t)NL * WLAYER;
    for (size_t i = (size_t)blockIdx.x * blockDim.x + threadIdx.x; i < total;
         i += (size_t)gridDim.x * blockDim.x) {
        int layer = (int)(i / WLAYER);
        int off = (int)(i % WLAYER);
        float v; __nv_bfloat16 *dh, *dl;
        if (off < WQKV_SZ) {
            v = Wqkv[(size_t)layer * WQKV_SZ + off];
            dh = g_wqkvb + ((size_t)layer * 2 + 0) * WQKV_SZ + off;
            dl = g_wqkvb + ((size_t)layer * 2 + 1) * WQKV_SZ + off;
        } else if (off < WQKV_SZ + WO_SZ) {
            int o2 = off - WQKV_SZ;
            v = Wo[(size_t)layer * WO_SZ + o2];
            dh = g_wob + ((size_t)layer * 2 + 0) * WO_SZ + o2;
            dl = g_wob + ((size_t)layer * 2 + 1) * WO_SZ + o2;
        } else if (off < WQKV_SZ + WO_SZ + W1_SZ) {
            int o2 = off - WQKV_SZ - WO_SZ;
            v = W1[(size_t)layer * W1_SZ + o2];
            dh = g_w1b + ((size_t)layer * 2 + 0) * W1_SZ + o2;
            dl = g_w1b + ((size_t)layer * 2 + 1) * W1_SZ + o2;
        } else {
            int o2 = off - WQKV_SZ - WO_SZ - W1_SZ;
            v = W2[(size_t)layer * W2_SZ + o2];
            dh = g_w2b + ((size_t)layer * 2 + 0) * W2_SZ + o2;
            dl = g_w2b + ((size_t)layer * 2 + 1) * W2_SZ + o2;
        }
        __nv_bfloat16 a, b;
        split2(v, a, b);
        *dh = a; *dl = b;
    }
}

// ---------------- fp32 GEMM (input projection, K=142) ----------------
__global__ __launch_bounds__(256) void gemm128_k(
    const float* __restrict__ A, const float* __restrict__ W,
    const float* __restrict__ bias, float* __restrict__ C,
    int M, int N, int K)
{
    __shared__ float As[2][8][128];
    __shared__ float Bs[2][8][128];

    const int tid  = threadIdx.x;
    const int row0 = blockIdx.y * 128;
    const int col0 = blockIdx.x * 128;
    const int lr  = tid >> 1;
    const int lk4 = (tid & 1) * 4;
    const int tx = tid & 15;
    const int ty = tid >> 4;

    float acc[8][8];
    #pragma unroll
    for (int i = 0; i < 8; i++)
        #pragma unroll
        for (int j = 0; j < 8; j++) acc[i][j] = 0.f;

    const float* Arow = A + (size_t)(row0 + lr) * K;
    const float* Wrow = W + (size_t)(col0 + lr) * K;
    const int nk = (K + 7) / 8;
    float ra[4], rb[4];

    {
        #pragma unroll
        for (int i = 0; i < 4; i++) {
            int kg = lk4 + i;
            ra[i] = (kg < K) ? Arow[kg] : 0.f;
            rb[i] = (kg < K) ? Wrow[kg] : 0.f;
        }
        #pragma unroll
        for (int i = 0; i < 4; i++) {
            As[0][lk4 + i][lr] = ra[i];
            Bs[0][lk4 + i][lr] = rb[i];
        }
    }
    __syncthreads();

    int buf = 0;
    for (int s = 0; s < nk; s++) {
        const bool more = (s + 1 < nk);
        if (more) {
            int k0 = (s + 1) * 8;
            #pragma unroll
            for (int i = 0; i < 4; i++) {
                int kg = k0 + lk4 + i;
                ra[i] = (kg < K) ? Arow[kg] : 0.f;
                rb[i] = (kg < K) ? Wrow[kg] : 0.f;
            }
        }
        #pragma unroll
        for (int k = 0; k < 8; k++) {
            float4 a0 = *reinterpret_cast<const float4*>(&As[buf][k][ty << 2]);
            float4 a1 = *reinterpret_cast<const float4*>(&As[buf][k][(ty << 2) + 64]);
            float4 b0 = *reinterpret_cast<const float4*>(&Bs[buf][k][tx << 2]);
            float4 b1 = *reinterpret_cast<const float4*>(&Bs[buf][k][(tx << 2) + 64]);
            float a[8] = {a0.x, a0.y, a0.z, a0.w, a1.x, a1.y, a1.z, a1.w};
            float b[8] = {b0.x, b0.y, b0.z, b0.w, b1.x, b1.y, b1.z, b1.w};
            #pragma unroll
            for (int i = 0; i < 8; i++)
                #pragma unroll
                for (int j = 0; j < 8; j++) acc[i][j] += a[i] * b[j];
        }
        if (more) {
            #pragma unroll
            for (int i = 0; i < 4; i++) {
                As[buf ^ 1][lk4 + i][lr] = ra[i];
                Bs[buf ^ 1][lk4 + i][lr] = rb[i];
            }
            __syncthreads();
            buf ^= 1;
        }
    }

    #pragma unroll
    for (int ih = 0; ih < 2; ih++) {
        #pragma unroll
        for (int i = 0; i < 4; i++) {
            int r = row0 + (ty << 2) + i + ih * 64;
            #pragma unroll
            for (int jh = 0; jh < 2; jh++) {
                int c = col0 + (tx << 2) + jh * 64;
                float4 bv = *reinterpret_cast<const float4*>(bias + c);
                float vv[4];
                vv[0] = acc[ih * 4 + i][jh * 4 + 0] + bv.x;
                vv[1] = acc[ih * 4 + i][jh * 4 + 1] + bv.y;
                vv[2] = acc[ih * 4 + i][jh * 4 + 2] + bv.z;
                vv[3] = acc[ih * 4 + i][jh * 4 + 3] + bv.w;
                int ss = r & 63;
                int bb = r >> 6;
                #pragma unroll
                for (int q = 0; q < 4; q++) vv[q] += pe_val(ss, c + q);
                size_t out = ((size_t)bb * Tt + 1 + ss) * Dm + c;
                #pragma unroll
                for (int q = 0; q < 4; q++) {
                    __nv_bfloat16 hh, ll;
                    split2(vv[q], hh, ll);
                    g_act0[out + q] = hh;
                    g_act0[PL0 + out + q] = ll;
                }
                *reinterpret_cast<float4*>(C + out) = make_float4(vv[0], vv[1], vv[2], vv[3]);
            }
        }
    }
}

// ---------------- cls token fill ----------------
__global__ __launch_bounds__(256) void cls_fill_k(const float* __restrict__ cls) {
    float v = cls[threadIdx.x];
    size_t idx = (size_t)blockIdx.x * Tt * Dm + threadIdx.x;
    g_h[idx] = v;
    __nv_bfloat16 hh, ll;
    split2(v, hh, ll);
    g_act0[idx] = hh;
    g_act0[PL0 + idx] = ll;
}

// ---------------- attention (reads qkv planes, writes act0 planes) ----------------
__global__ __launch_bounds__(128) void attn_k()
{
    const int b  = blockIdx.x >> 3;
    const int hh = blockIdx.x & 7;
    const size_t base = (size_t)b * Tt * (3 * Dm) + hh * DHd;

    __shared__ float q [Tt][33];
    __shared__ float kt[Tt][33];
    __shared__ float vt[Tt][33];
    __shared__ float sc[Tt * Tt];

    const int tid = threadIdx.x;

    for (int idx = tid; idx < Tt * DHd; idx += 128) {
        int t = idx >> 5, d = idx & 31;
        size_t o = base + (size_t)t * (3 * Dm) + d;
        q [t][d] = __bfloat162float(g_qkvb[o])            + __bfloat162float(g_qkvb[PLQ + o]);
        kt[t][d] = __bfloat162float(g_qkvb[o + Dm])       + __bfloat162float(g_qkvb[PLQ + o + Dm]);
        vt[t][d] = __bfloat162float(g_qkvb[o + 2 * Dm])   + __bfloat162float(g_qkvb[PLQ + o + 2 * Dm]);
    }
    __syncthreads();

    const float scale = 0.17677669529663689f;
    for (int idx = tid; idx < Tt * Tt; idx += 128) {
        int i = idx / Tt, j = idx - i * Tt;
        float s = 0.f;
        #pragma unroll
        for (int d = 0; d < DHd; d++) s += q[i][d] * kt[j][d];
        sc[idx] = s * scale;
    }
    __syncthreads();

    if (tid < Tt) {
        float m = -3.4e38f;
        for (int j = 0; j < Tt; j++) m = fmaxf(m, sc[tid * Tt + j]);
        float ssum = 0.f;
        for (int j = 0; j < Tt; j++) {
            float e = expf(sc[tid * Tt + j] - m);
            sc[tid * Tt + j] = e;
            ssum += e;
        }
        float inv = 1.0f / ssum;
        for (int j = 0; j < Tt; j++) sc[tid * Tt + j] *= inv;
    }
    __syncthreads();

    for (int idx = tid; idx < Tt * DHd; idx += 128) {
        int i = idx >> 5, d = idx & 31;
        float o = 0.f;
        for (int j = 0; j < Tt; j++) o += sc[i * Tt + j] * vt[j][d];
        size_t oidx = ((size_t)b * Tt + i) * Dm + hh * DHd + d;
        __nv_bfloat16 h2, l2;
        split2(o, h2, l2);
        g_act0[oidx] = h2;
        g_act0[PL0 + oidx] = l2;
    }
}

// ---------------- residual add + LayerNorm (4 tokens/block, float4) ----------------
__global__ __launch_bounds__(256) void add_ln_k(
    float* __restrict__ h, const float* __restrict__ t,
    const float* __restrict__ g, const float* __restrict__ bb)
{
    __shared__ float sms[8];
    const int tid = threadIdx.x;
    const int grp = tid >> 6;          // 0..3 (token within block)
    const int lt  = tid & 63;          // 0..63
    const int wid = tid >> 5;          // 0..7
    const size_t row = (size_t)blockIdx.x * 4 + grp;
    const size_t base = row * Dm + lt * 4;

    float4 hv = *reinterpret_cast<const float4*>(h + base);
    float4 tv = *reinterpret_cast<const float4*>(t + base);
    float v0 = hv.x + tv.x, v1 = hv.y + tv.y, v2 = hv.z + tv.z, v3 = hv.w + tv.w;

    float s = v0 + v1 + v2 + v3;
    #pragma unroll
    for (int o = 16; o > 0; o >>= 1) s += __shfl_down_sync(0xffffffffu, s, o);
    if ((tid & 31) == 0) sms[wid] = s;
    __syncthreads();
    float mean = (sms[grp * 2] + sms[grp * 2 + 1]) * (1.0f / Dm);
    __syncthreads();

    float d0 = v0 - mean, d1 = v1 - mean, d2 = v2 - mean, d3 = v3 - mean;
    float s2 = d0 * d0 + d1 * d1 + d2 * d2 + d3 * d3;
    #pragma unroll
    for (int o = 16; o > 0; o >>= 1) s2 += __shfl_down_sync(0xffffffffu, s2, o);
    if ((tid & 31) == 0) sms[wid] = s2;
    __syncthreads();
    float var = (sms[grp * 2] + sms[grp * 2 + 1]) * (1.0f / Dm);
    float rs = rsqrtf(var + LN_EPS);

    float4 gv = *reinterpret_cast<const float4*>(g + lt * 4);
    float4 bv = *reinterpret_cast<const float4*>(bb + lt * 4);
    float o0 = d0 * rs * gv.x + bv.x;
    float o1 = d1 * rs * gv.y + bv.y;
    float o2 = d2 * rs * gv.z + bv.z;
    float o3 = d3 * rs * gv.w + bv.w;

    *reinterpret_cast<float4*>(h + base) = make_float4(o0, o1, o2, o3);

    __nv_bfloat16 h0, l0, h1, l1, h2, l2, h3, l3;
    split2(o0, h0, l0); split2(o1, h1, l1); split2(o2, h2, l2); split2(o3, h3, l3);
    __nv_bfloat162 hp0(h0, h1), hp1(h2, h3), lp0(l0, l1), lp1(l2, l3);
    uint2 hw, lw;
    hw.x = *reinterpret_cast<uint32_t*>(&hp0); hw.y = *reinterpret_cast<uint32_t*>(&hp1);
    lw.x = *reinterpret_cast<uint32_t*>(&lp0); lw.y = *reinterpret_cast<uint32_t*>(&lp1);
    *reinterpret_cast<uint2*>(&g_act0[base]) = hw;
    *reinterpret_cast<uint2*>(&g_act0[PL0 + base]) = lw;
}

// ---------------- final head ----------------
__global__ __launch_bounds__(256) void final_head_k(
    const float* __restrict__ lnfg, const float* __restrict__ lnfb,
    const float* __restrict__ Wout, const float* __restrict__ bout)
{
    __shared__ float xn[Dm];
    __shared__ float sm[32];
    const int tid = threadIdx.x;
    const int b = blockIdx.x;
    float v = g_h[(size_t)b * Tt * Dm + tid];
    float mean = bred256(v, sm) * (1.0f / Dm);
    float d = v - mean;
    float var = bred256(d * d, sm) * (1.0f / Dm);
    xn[tid] = d * rsqrtf(var + LN_EPS) * lnfg[tid] + lnfb[tid];
    __syncthreads();
    if (tid < Ed) {
        const float* w = Wout + (size_t)tid * Dm;
        float a = bout[tid];
        #pragma unroll 8
        for (int t = 0; t < Dm; t++) a += xn[t] * w[t];
        g_ze[(size_t)b * Ed + tid] = a;
    }
}

// ---------------- codebook norms ----------------
__global__ __launch_bounds__(128) void cnorm_k(const float* __restrict__ cb) {
    __shared__ float sm[4];
    const int tid = threadIdx.x;
    float v = cb[(size_t)blockIdx.x * Ed + tid];
    v *= v;
    #pragma unroll
    for (int o = 16; o > 0; o >>= 1) v += __shfl_down_sync(0xffffffffu, v, o);
    if ((tid & 31) == 0) sm[tid >> 5] = v;
    __syncthreads();
    if (tid == 0) g_cnorm[blockIdx.x] = sm[0] + sm[1] + sm[2] + sm[3];
}

// ---------------- VQ ----------------
__global__ __launch_bounds__(256) void vq_k(const float* __restrict__ cb) {
    __shared__ float ze[Ed];
    __shared__ float bm[256];
    __shared__ int   bi[256];
    __shared__ int   chosen;
    __shared__ float sm[32];
    const int tid = threadIdx.x;
    const int b = blockIdx.x;
    if (tid < Ed) ze[tid] = g_ze[(size_t)b * Ed + tid];
    __syncthreads();

    float best = 3.4e38f;
    int besti = 0x7fffffff;
    for (int k = tid; k < Kcb; k += 256) {
        const float* c = cb + (size_t)k * Ed;
        float dot = 0.f;
        #pragma unroll 4
        for (int e = 0; e < Ed; e++) dot += ze[e] * c[e];
        float dd = g_cnorm[k] - 2.0f * dot;
        if (dd < best || (dd == best && k < besti)) { best = dd; besti = k; }
    }
    bm[tid] = best; bi[tid] = besti;
    __syncthreads();
    for (int off = 128; off > 0; off >>= 1) {
        if (tid < off) {
            float ob = bm[tid + off]; int oi = bi[tid + off];
            if (ob < bm[tid] || (ob == bm[tid] && oi < bi[tid])) { bm[tid] = ob; bi[tid] = oi; }
        }
        __syncthreads();
    }
    if (tid == 0) {
        chosen = bi[0];
        g_idx[b] = bi[0];
        atomicAdd(&g_hist[bi[0]], 1);
    }
    __syncthreads();

    const int kk = chosen;
    float part = 0.f;
    if (tid < Ed) {
        float diff = cb[(size_t)kk * Ed + tid] - ze[tid];
        part = diff * diff;
    }
    float tot = bred256(part, sm);
    if (tid == 0) g_losspart[b] = tot;
}

// ---------------- decoder ----------------
__global__ __launch_bounds__(256) void decoder_k(
    const float* __restrict__ cb,
    const float* __restrict__ Wd1, const float* __restrict__ bd1,
    const float* __restrict__ lndg, const float* __restrict__ lndb,
    const float* __restrict__ Wd2, const float* __restrict__ bd2,
    const float* __restrict__ Wd3, const float* __restrict__ bd3,
    float* __restrict__ outp)
{
    __shared__ float zq[Ed];
    __shared__ float d1[Dm];
    __shared__ float d2s[Ed];
    __shared__ float sm[32];
    const int tid = threadIdx.x;
    const int b = blockIdx.x;
    const int ci = g_idx[b];
    if (tid < Ed) zq[tid] = cb[(size_t)ci * Ed + tid];
    __syncthreads();

    float t1 = bd1[tid];
    {
        const float* w = Wd1 + (size_t)tid * Ed;
        #pragma unroll 4
        for (int e = 0; e < Ed; e++) t1 += zq[e] * w[e];
    }
    float mean = bred256(t1, sm) * (1.0f / Dm);
    float dd = t1 - mean;
    float var = bred256(dd * dd, sm) * (1.0f / Dm);
    float xg = dd * rsqrtf(var + LN_EPS) * lndg[tid] + lndb[tid];
    d1[tid] = gelu_exact(xg);
    __syncthreads();

    if (tid < Ed) {
        const float* w2 = Wd2 + (size_t)tid * Dm;
        float t2 = bd2[tid];
        #pragma unroll 8
        for (int t = 0; t < Dm; t++) t2 += d1[t] * w2[t];
        d2s[tid] = gelu_exact(t2);
    }
    __syncthreads();

    if (tid < 2) {
        const float* w3 = Wd3 + (size_t)tid * Ed;
        float vv = bd3[tid];
        #pragma unroll 4
        for (int e = 0; e < Ed; e++) vv += d2s[e] * w3[e];
        outp[(size_t)b * 2 + tid] = vv;
    }
    if (tid == 2) outp[(size_t)Bsz * 2 + b] = (float)ci;
}

// ---------------- scalars ----------------
__global__ __launch_bounds__(1024) void scalars_k(float* __restrict__ outp) {
    __shared__ float sm[32];
    const int tid = threadIdx.x;

    float p = (float)g_hist[tid] * (1.0f / (float)Bsz);
    float term = p * logf(p + 1e-10f);
    float v = term;
    #pragma unroll
    for (int o = 16; o > 0; o >>= 1) v += __shfl_down_sync(0xffffffffu, v, o);
    if ((tid & 31) == 0) sm[tid >> 5] = v;
    __syncthreads();
    float ent = 0.f;
    if (tid == 0) {
        for (int i = 0; i < 32; i++) ent += sm[i];
        sm[0] = ent;
    }
    __syncthreads();
    ent = sm[0];
    __syncthreads();

    float lp = g_losspart[tid] + g_losspart[tid + 1024];
    #pragma unroll
    for (int o = 16; o > 0; o >>= 1) lp += __shfl_down_sync(0xffffffffu, lp, o);
    if ((tid & 31) == 0) sm[tid >> 5] = lp;
    __syncthreads();
    if (tid == 0) {
        float tot = 0.f;
        for (int i = 0; i < 32; i++) tot += sm[i];
        outp[(size_t)Bsz * 2 + Bsz + 0] = 0.1f * tot / ((float)Bsz * (float)Ed);
        outp[(size_t)Bsz * 2 + Bsz + 1] = expf(-ent);
    }
}

__global__ __launch_bounds__(1024) void zero_k() {
    g_hist[threadIdx.x] = 0;
}

// ---------------- host ----------------
template <typename T>
static T* sym_addr(const void* sym) {
    void* p = nullptr;
    cudaGetSymbolAddress(&p, sym);
    return (T*)p;
}

extern "C" void kernel_launch(void* const* d_in, const int* in_sizes, int n_in,
                              void* d_out, int out_size)
{
    (void)in_sizes; (void)n_in; (void)out_size;
    const float* x     = (const float*)d_in[0];
    const float* W_in  = (const float*)d_in[1];
    const float* b_in  = (const float*)d_in[2];
    const float* cls   = (const float*)d_in[3];
    const float* Wqkv  = (const float*)d_in[4];
    const float* bqkv  = (const float*)d_in[5];
    const float* Wo    = (const float*)d_in[6];
    const float* bo    = (const float*)d_in[7];
    const float* W1    = (const float*)d_in[8];
    const float* b1    = (const float*)d_in[9];
    const float* W2    = (const float*)d_in[10];
    const float* b2    = (const float*)d_in[11];
    const float* ln1g  = (const float*)d_in[12];
    const float* ln1b  = (const float*)d_in[13];
    const float* ln2g  = (const float*)d_in[14];
    const float* ln2b  = (const float*)d_in[15];
    const float* lnfg  = (const float*)d_in[16];
    const float* lnfb  = (const float*)d_in[17];
    const float* Wout  = (const float*)d_in[18];
    const float* bout  = (const float*)d_in[19];
    const float* cb    = (const float*)d_in[20];
    const float* Wd1   = (const float*)d_in[21];
    const float* bd1   = (const float*)d_in[22];
    const float* lndg  = (const float*)d_in[23];
    const float* lndb  = (const float*)d_in[24];
    const float* Wd2   = (const float*)d_in[25];
    const float* bd2   = (const float*)d_in[26];
    const float* Wd3   = (const float*)d_in[27];
    const float* bd3   = (const float*)d_in[28];
    float* outp = (float*)d_out;

    float* pH    = sym_addr<float>(g_h);
    float* pTmp  = sym_addr<float>(g_tmp);
    __nv_bfloat16* pAct0 = sym_addr<__nv_bfloat16>(g_act0);
    __nv_bfloat16* pAct1 = sym_addr<__nv_bfloat16>(g_act1);
    __nv_bfloat16* pWq = sym_addr<__nv_bfloat16>(g_wqkvb);
    __nv_bfloat16* pWo = sym_addr<__nv_bfloat16>(g_wob);
    __nv_bfloat16* pW1 = sym_addr<__nv_bfloat16>(g_w1b);
    __nv_bfloat16* pW2 = sym_addr<__nv_bfloat16>(g_w2b);

    cudaFuncSetAttribute(bfgemm_k<0>, cudaFuncAttributeMaxDynamicSharedMemorySize, SMEM_DYN);
    cudaFuncSetAttribute(bfgemm_k<1>, cudaFuncAttributeMaxDynamicSharedMemorySize, SMEM_DYN);
    cudaFuncSetAttribute(bfgemm_k<2>, cudaFuncAttributeMaxDynamicSharedMemorySize, SMEM_DYN);

    // ordered so my launch #4 (ncu capture slot) is the first QKV bfgemm
    convw_k<<<1024, 256>>>(Wqkv, Wo, W1, W2);                       // 1
    gemm128_k<<<dim3(Dm / 128, (Bsz * Ssz) / 128), 256>>>(
        x, W_in, b_in, pH, Bsz * Ssz, Dm, Cin);                     // 2
    cls_fill_k<<<Bsz, 256>>>(cls);                                  // 3

    for (int i = 0; i < NL; i++) {
        bfgemm_k<2><<<dim3(768 / 128, MTOK / 128), 256, SMEM_DYN>>>(
            pAct0, PL0, pWq + (size_t)i * 2 * WQKV_SZ, (size_t)WQKV_SZ,
            bqkv + (size_t)i * 3 * Dm, nullptr, MTOK, 3 * Dm, Dm);  // 4 on i=0
        attn_k<<<Bsz * NH, 128>>>();
        bfgemm_k<0><<<dim3(Dm / 128, MTOK / 128), 256, SMEM_DYN>>>(
            pAct0, PL0, pWo + (size_t)i * 2 * WO_SZ, (size_t)WO_SZ,
            bo + (size_t)i * Dm, pTmp, MTOK, Dm, Dm);
        add_ln_k<<<MTOK / 4, 256>>>(pH, pTmp, ln1g + (size_t)i * Dm, ln1b + (size_t)i * Dm);
        bfgemm_k<1><<<dim3(FFd / 128, MTOK / 128), 256, SMEM_DYN>>>(
            pAct0, PL0, pW1 + (size_t)i * 2 * W1_SZ, (size_t)W1_SZ,
            b1 + (size_t)i * FFd, nullptr, MTOK, FFd, Dm);
        bfgemm_k<0><<<dim3(Dm / 128, MTOK / 128), 256, SMEM_DYN>>>(
            pAct1, PL1, pW2 + (size_t)i * 2 * W2_SZ, (size_t)W2_SZ,
            b2 + (size_t)i * Dm, pTmp, MTOK, Dm, FFd);
        add_ln_k<<<MTOK / 4, 256>>>(pH, pTmp, ln2g + (size_t)i * Dm, ln2b + (size_t)i * Dm);
    }

    zero_k<<<1, 1024>>>();
    cnorm_k<<<Kcb, 128>>>(cb);
    final_head_k<<<Bsz, 256>>>(lnfg, lnfb, Wout, bout);
    vq_k<<<Bsz, 256>>>(cb);
    decoder_k<<<Bsz, 256>>>(cb, Wd1, bd1, lndg, lndb, Wd2, bd2, Wd3, bd3, outp);
    scalars_k<<<1, 1024>>>(outp);
}

// round 8
// speedup vs baseline: 4.8941x; 1.0403x over previous
#include <cuda_runtime.h>
#include <cuda_bf16.h>
#include <math.h>
#include <stdint.h>

// ---------------- problem constants ----------------
#define Bsz 2048
#define Ssz 64
#define Cin 142
#define KIN 160                  // Cin padded to mult of 32
#define Dm  256
#define NH  8
#define DHd 32
#define FFd 512
#define NL  3
#define Ed  128
#define Kcb 1024
#define Tt  65
#define MTOK (Bsz*Tt)            // 133120
#define MIN0 (Bsz*Ssz)           // 131072 input-proj rows
#define LN_EPS 1e-5f

#define PL0 ((size_t)MTOK*Dm)
#define PL1 ((size_t)MTOK*FFd)
#define PLQ ((size_t)MTOK*3*Dm)
#define PLX ((size_t)MIN0*KIN)
#define WQKV_SZ (3*Dm*Dm)
#define WO_SZ   (Dm*Dm)
#define W1_SZ   (FFd*Dm)
#define W2_SZ   (Dm*FFd)
#define WLAYER  (WQKV_SZ+WO_SZ+W1_SZ+W2_SZ)

// ---------------- scratch ----------------
__device__ float g_h   [(size_t)Bsz*Tt*Dm];
__device__ float g_tmp [(size_t)Bsz*Tt*Dm];
__device__ float g_ze  [(size_t)Bsz*Ed];
__device__ int   g_idx [Bsz];
__device__ float g_cnorm[Kcb];
__device__ int   g_hist[Kcb];
__device__ float g_losspart[Bsz];

__device__ __nv_bfloat16 g_act0[2*PL0];
__device__ __nv_bfloat16 g_act1[2*PL1];
__device__ __nv_bfloat16 g_qkvb[2*PLQ];
__device__ __nv_bfloat16 g_xb  [2*PLX];
__device__ __nv_bfloat16 g_winb[2*Dm*KIN];
__device__ __nv_bfloat16 g_wqkvb[(size_t)NL*2*WQKV_SZ];
__device__ __nv_bfloat16 g_wob  [(size_t)NL*2*WO_SZ];
__device__ __nv_bfloat16 g_w1b  [(size_t)NL*2*W1_SZ];
__device__ __nv_bfloat16 g_w2b  [(size_t)NL*2*W2_SZ];

// ---------------- low-level helpers ----------------
__device__ __forceinline__ uint32_t smem_to_u32(const void* p) {
    uint32_t a;
    asm("{ .reg .u64 t; cvta.to.shared.u64 t, %1; cvt.u32.u64 %0, t; }" : "=r"(a) : "l"(p));
    return a;
}
__device__ __forceinline__ void cp_async16(uint32_t saddr, const void* gaddr) {
    asm volatile("cp.async.cg.shared.global [%0], [%1], 16;" :: "r"(saddr), "l"(gaddr));
}
__device__ __forceinline__ void ldsm4(uint32_t* r, uint32_t addr) {
    asm volatile("ldmatrix.sync.aligned.m8n8.x4.shared.b16 {%0,%1,%2,%3}, [%4];"
        : "=r"(r[0]), "=r"(r[1]), "=r"(r[2]), "=r"(r[3]) : "r"(addr));
}
__device__ __forceinline__ void mma16816(float* c, const uint32_t* a, const uint32_t* b) {
    asm volatile(
        "mma.sync.aligned.m16n8k16.row.col.f32.bf16.bf16.f32 "
        "{%0,%1,%2,%3}, {%4,%5,%6,%7}, {%8,%9}, {%0,%1,%2,%3};"
        : "+f"(c[0]), "+f"(c[1]), "+f"(c[2]), "+f"(c[3])
        : "r"(a[0]), "r"(a[1]), "r"(a[2]), "r"(a[3]), "r"(b[0]), "r"(b[1]));
}
__device__ __forceinline__ float gelu_exact(float x) {
    return 0.5f * x * (1.0f + erff(x * 0.7071067811865475f));
}
__device__ __forceinline__ void split2(float v, __nv_bfloat16& h, __nv_bfloat16& l) {
    h = __float2bfloat16(v);
    l = __float2bfloat16(v - __bfloat162float(h));
}
__device__ __forceinline__ float bred256(float v, float* sm) {
    int tid = threadIdx.x;
    #pragma unroll
    for (int o = 16; o > 0; o >>= 1) v += __shfl_down_sync(0xffffffffu, v, o);
    if ((tid & 31) == 0) sm[tid >> 5] = v;
    __syncthreads();
    if (tid == 0) {
        float t = 0.f;
        #pragma unroll
        for (int i = 0; i < 8; i++) t += sm[i];
        sm[0] = t;
    }
    __syncthreads();
    float r = sm[0];
    __syncthreads();
    return r;
}
__device__ __forceinline__ float pe_val(int s, int c) {
    int j = c >> 1;
    float freq = expf(-(float)(2 * j) * (9.210340371976184f / 256.0f));
    float ang = (float)s * freq;
    return (c & 1) ? cosf(ang) : sinf(ang);
}

// ---------------- mma.sync bf16 2-split (3-term) GEMM ----------------
#define PLANE_B 8192
#define STAGE_B 32768
#define SMEM_DYN (3*STAGE_B)   // 96 KB

__device__ __forceinline__ uint32_t sw_addr(uint32_t plane_base, int r, int colk) {
    int chunk = (colk >> 3) ^ ((r >> 1) & 3);
    return plane_base + r * 64 + (chunk << 4) + ((colk & 7) << 1);
}

__device__ __forceinline__ void issue_stage(
    uint32_t sbase, const __nv_bfloat16* __restrict__ A, size_t aps,
    const __nv_bfloat16* __restrict__ W, size_t wps,
    int row0, int col0, int K, int k0, int tid)
{
    #pragma unroll
    for (int i = 0; i < 8; i++) {
        const int plane = i >> 1;
        const int idx = ((i & 1) << 8) + tid;
        const int r = idx >> 2, c16 = idx & 3;
        const __nv_bfloat16* src = (plane < 2)
            ? A + (size_t)plane * aps + (size_t)(row0 + r) * K + (k0 + c16 * 8)
            : W + (size_t)(plane - 2) * wps + (size_t)(col0 + r) * K + (k0 + c16 * 8);
        uint32_t dst = sbase + plane * PLANE_B + r * 64 + ((c16 ^ ((r >> 1) & 3)) << 4);
        cp_async16(dst, src);
    }
}

// EPI 0: fp32 to C. EPI 1: gelu -> act1 planes. EPI 2: qkvb planes. EPI 3: input-proj (PE+remap -> g_h + act0 planes)
template <int EPI>
__global__ __launch_bounds__(256, 2)
void bfgemm_k(const __nv_bfloat16* __restrict__ A, size_t aps,
              const __nv_bfloat16* __restrict__ W, size_t wps,
              const float* __restrict__ bias, float* __restrict__ C,
              int M, int N, int K)
{
    extern __shared__ char smem[];
    const uint32_t sb = smem_to_u32(smem);
    const int tid = threadIdx.x;
    const int lane = tid & 31, wid = tid >> 5;
    const int row0 = blockIdx.y * 128;
    const int col0 = blockIdx.x * 128;
    const int wm0 = (wid & 1) * 64;
    const int wn0 = (wid >> 1) * 32;
    const int qr = lane >> 2, qc = lane & 3;

    const int lj = lane >> 3;
    const int lr8 = lane & 7;
    const int a_row_off = ((lj & 1) << 3) + lr8;
    const int a_k_off   = (lj >> 1) << 3;
    const int b_row_off = ((lj >> 1) << 3) + lr8;
    const int b_k_off   = (lj & 1) << 3;

    float acc[4][4][4];
    #pragma unroll
    for (int a = 0; a < 4; a++)
        #pragma unroll
        for (int b = 0; b < 4; b++)
            #pragma unroll
            for (int c = 0; c < 4; c++) acc[a][b][c] = 0.f;

    const int nk = K >> 5;

    issue_stage(sb, A, aps, W, wps, row0, col0, K, 0, tid);
    asm volatile("cp.async.commit_group;" ::: "memory");
    issue_stage(sb + STAGE_B, A, aps, W, wps, row0, col0, K, 32, tid);
    asm volatile("cp.async.commit_group;" ::: "memory");

    for (int s = 0; s < nk; s++) {
        if (s + 1 < nk) {
            asm volatile("cp.async.wait_group 1;" ::: "memory");
        } else {
            asm volatile("cp.async.wait_group 0;" ::: "memory");
        }
        __syncthreads();
        if (s + 2 < nk) {
            issue_stage(sb + ((s + 2) % 3) * STAGE_B, A, aps, W, wps, row0, col0, K, (s + 2) << 5, tid);
            asm volatile("cp.async.commit_group;" ::: "memory");
        }

        const uint32_t stg = sb + (s % 3) * STAGE_B;
        const uint32_t ah_b = stg;
        const uint32_t al_b = stg + PLANE_B;
        const uint32_t wh_b = stg + 2 * PLANE_B;
        const uint32_t wl_b = stg + 3 * PLANE_B;

        #pragma unroll
        for (int kk = 0; kk < 32; kk += 16) {
            uint32_t areg[4][4];
            uint32_t bh[4][2], bl[4][2];

            #pragma unroll
            for (int np = 0; np < 2; np++) {
                uint32_t t4[4];
                ldsm4(t4, sw_addr(wh_b, wn0 + np * 16 + b_row_off, kk + b_k_off));
                bh[np * 2][0] = t4[0]; bh[np * 2][1] = t4[1];
                bh[np * 2 + 1][0] = t4[2]; bh[np * 2 + 1][1] = t4[3];
            }
            #pragma unroll
            for (int mi = 0; mi < 4; mi++)
                ldsm4(areg[mi], sw_addr(ah_b, wm0 + mi * 16 + a_row_off, kk + a_k_off));
            #pragma unroll
            for (int mi = 0; mi < 4; mi++)
                #pragma unroll
                for (int ni = 0; ni < 4; ni++)
                    mma16816(acc[mi][ni], areg[mi], bh[ni]);
            #pragma unroll
            for (int np = 0; np < 2; np++) {
                uint32_t t4[4];
                ldsm4(t4, sw_addr(wl_b, wn0 + np * 16 + b_row_off, kk + b_k_off));
                bl[np * 2][0] = t4[0]; bl[np * 2][1] = t4[1];
                bl[np * 2 + 1][0] = t4[2]; bl[np * 2 + 1][1] = t4[3];
            }
            #pragma unroll
            for (int mi = 0; mi < 4; mi++)
                #pragma unroll
                for (int ni = 0; ni < 4; ni++)
                    mma16816(acc[mi][ni], areg[mi], bl[ni]);
            #pragma unroll
            for (int mi = 0; mi < 4; mi++)
                ldsm4(areg[mi], sw_addr(al_b, wm0 + mi * 16 + a_row_off, kk + a_k_off));
            #pragma unroll
            for (int mi = 0; mi < 4; mi++)
                #pragma unroll
                for (int ni = 0; ni < 4; ni++)
                    mma16816(acc[mi][ni], areg[mi], bh[ni]);
        }
        __syncthreads();
    }

    // ---- epilogue ----
    #pragma unroll
    for (int mi = 0; mi < 4; mi++) {
        #pragma unroll
        for (int ni = 0; ni < 4; ni++) {
            int col = col0 + wn0 + ni * 8 + qc * 2;
            float b0 = bias[col], b1 = bias[col + 1];
            #pragma unroll
            for (int half = 0; half < 2; half++) {
                int r = row0 + wm0 + mi * 16 + qr + half * 8;
                float v0 = acc[mi][ni][half * 2 + 0] + b0;
                float v1 = acc[mi][ni][half * 2 + 1] + b1;
                if (EPI == 3) {
                    int ss = r & 63, bb = r >> 6;
                    v0 += pe_val(ss, col);
                    v1 += pe_val(ss, col + 1);
                    size_t o = ((size_t)bb * Tt + 1 + ss) * Dm + col;
                    *reinterpret_cast<float2*>(&g_h[o]) = make_float2(v0, v1);
                    __nv_bfloat16 h0, l0, h1, l1;
                    split2(v0, h0, l0);
                    split2(v1, h1, l1);
                    *reinterpret_cast<__nv_bfloat162*>(&g_act0[o]) = __nv_bfloat162(h0, h1);
                    *reinterpret_cast<__nv_bfloat162*>(&g_act0[PL0 + o]) = __nv_bfloat162(l0, l1);
                } else {
                    size_t o = (size_t)r * N + col;
                    if (EPI == 0) {
                        *reinterpret_cast<float2*>(C + o) = make_float2(v0, v1);
                    } else if (EPI == 1) {
                        float g0 = gelu_exact(v0), g1 = gelu_exact(v1);
                        __nv_bfloat16 h0, l0, h1, l1;
                        split2(g0, h0, l0);
                        split2(g1, h1, l1);
                        *reinterpret_cast<__nv_bfloat162*>(&g_act1[o]) = __nv_bfloat162(h0, h1);
                        *reinterpret_cast<__nv_bfloat162*>(&g_act1[PL1 + o]) = __nv_bfloat162(l0, l1);
                    } else {
                        __nv_bfloat16 h0, l0, h1, l1;
                        split2(v0, h0, l0);
                        split2(v1, h1, l1);
                        *reinterpret_cast<__nv_bfloat162*>(&g_qkvb[o]) = __nv_bfloat162(h0, h1);
                        *reinterpret_cast<__nv_bfloat162*>(&g_qkvb[PLQ + o]) = __nv_bfloat162(l0, l1);
                    }
                }
            }
        }
    }
}

// ---------------- weight split (transformer weights) ----------------
__global__ __launch_bounds__(256) void convw_k(
    const float* __restrict__ Wqkv, const float* __restrict__ Wo,
    const float* __restrict__ W1, const float* __restrict__ W2)
{
    const size_t total = (size_t)NL * WLAYER;
    for (size_t i = (size_t)blockIdx.x * blockDim.x + threadIdx.x; i < total;
         i += (size_t)gridDim.x * blockDim.x) {
        int layer = (int)(i / WLAYER);
        int off = (int)(i % WLAYER);
        float v; __nv_bfloat16 *dh, *dl;
        if (off < WQKV_SZ) {
            v = Wqkv[(size_t)layer * WQKV_SZ + off];
            dh = g_wqkvb + ((size_t)layer * 2 + 0) * WQKV_SZ + off;
            dl = g_wqkvb + ((size_t)layer * 2 + 1) * WQKV_SZ + off;
        } else if (off < WQKV_SZ + WO_SZ) {
            int o2 = off - WQKV_SZ;
            v = Wo[(size_t)layer * WO_SZ + o2];
            dh = g_wob + ((size_t)layer * 2 + 0) * WO_SZ + o2;
            dl = g_wob + ((size_t)layer * 2 + 1) * WO_SZ + o2;
        } else if (off < WQKV_SZ + WO_SZ + W1_SZ) {
            int o2 = off - WQKV_SZ - WO_SZ;
            v = W1[(size_t)layer * W1_SZ + o2];
            dh = g_w1b + ((size_t)layer * 2 + 0) * W1_SZ + o2;
            dl = g_w1b + ((size_t)layer * 2 + 1) * W1_SZ + o2;
        } else {
            int o2 = off - WQKV_SZ - WO_SZ - W1_SZ;
            v = W2[(size_t)layer * W2_SZ + o2];
            dh = g_w2b + ((size_t)layer * 2 + 0) * W2_SZ + o2;
            dl = g_w2b + ((size_t)layer * 2 + 1) * W2_SZ + o2;
        }
        __nv_bfloat16 a, b;
        split2(v, a, b);
        *dh = a; *dl = b;
    }
}

// ---------------- x -> padded bf16 planes ----------------
__global__ __launch_bounds__(256) void convx_k(const float* __restrict__ x) {
    const size_t total = (size_t)MIN0 * KIN;
    for (size_t i = (size_t)blockIdx.x * blockDim.x + threadIdx.x; i < total;
         i += (size_t)gridDim.x * blockDim.x) {
        size_t row = i / KIN;
        int k = (int)(i % KIN);
        float v = (k < Cin) ? x[row * Cin + k] : 0.f;
        __nv_bfloat16 a, b;
        split2(v, a, b);
        g_xb[i] = a;
        g_xb[PLX + i] = b;
    }
}

// ---------------- W_in -> padded bf16 planes ----------------
__global__ __launch_bounds__(256) void convin_k(const float* __restrict__ W_in) {
    int i = blockIdx.x * 256 + threadIdx.x;
    if (i < Dm * KIN) {
        int row = i / KIN, k = i % KIN;
        float v = (k < Cin) ? W_in[row * Cin + k] : 0.f;
        __nv_bfloat16 a, b;
        split2(v, a, b);
        g_winb[i] = a;
        g_winb[Dm * KIN + i] = b;
    }
}

// ---------------- cls token fill ----------------
__global__ __launch_bounds__(256) void cls_fill_k(const float* __restrict__ cls) {
    float v = cls[threadIdx.x];
    size_t idx = (size_t)blockIdx.x * Tt * Dm + threadIdx.x;
    g_h[idx] = v;
    __nv_bfloat16 hh, ll;
    split2(v, hh, ll);
    g_act0[idx] = hh;
    g_act0[PL0 + idx] = ll;
}

// ---------------- attention (256 threads, warp softmax) ----------------
__global__ __launch_bounds__(256) void attn_k()
{
    const int b  = blockIdx.x >> 3;
    const int hh = blockIdx.x & 7;
    const size_t base = (size_t)b * Tt * (3 * Dm) + hh * DHd;

    __shared__ float q [Tt][33];
    __shared__ float kt[Tt][33];
    __shared__ float vt[Tt][33];
    __shared__ float sc[Tt * Tt];

    const int tid = threadIdx.x;
    const int lane = tid & 31, wid = tid >> 5;

    for (int idx = tid; idx < Tt * DHd; idx += 256) {
        int t = idx >> 5, d = idx & 31;
        size_t o = base + (size_t)t * (3 * Dm) + d;
        q [t][d] = __bfloat162float(g_qkvb[o])          + __bfloat162float(g_qkvb[PLQ + o]);
        kt[t][d] = __bfloat162float(g_qkvb[o + Dm])     + __bfloat162float(g_qkvb[PLQ + o + Dm]);
        vt[t][d] = __bfloat162float(g_qkvb[o + 2 * Dm]) + __bfloat162float(g_qkvb[PLQ + o + 2 * Dm]);
    }
    __syncthreads();

    const float scale = 0.17677669529663689f;
    for (int idx = tid; idx < Tt * Tt; idx += 256) {
        int i = idx / Tt, j = idx - i * Tt;
        float s = 0.f;
        #pragma unroll
        for (int d = 0; d < DHd; d++) s += q[i][d] * kt[j][d];
        sc[idx] = s * scale;
    }
    __syncthreads();

    // warp-parallel softmax: warp w handles rows w, w+8, ...
    for (int r = wid; r < Tt; r += 8) {
        float* row = sc + r * Tt;
        float e0 = row[lane];
        float e1 = row[32 + lane];           // covers 32..63
        float e2 = (lane == 0) ? row[64] : -3.4e38f;
        float m = fmaxf(fmaxf(e0, e1), e2);
        #pragma unroll
        for (int o = 16; o > 0; o >>= 1) m = fmaxf(m, __shfl_xor_sync(0xffffffffu, m, o));
        e0 = expf(e0 - m);
        e1 = expf(e1 - m);
        e2 = (lane == 0) ? expf(e2 - m) : 0.f;
        float s = e0 + e1 + e2;
        #pragma unroll
        for (int o = 16; o > 0; o >>= 1) s += __shfl_xor_sync(0xffffffffu, s, o);
        float inv = 1.0f / s;
        row[lane] = e0 * inv;
        row[32 + lane] = e1 * inv;
        if (lane == 0) row[64] = e2 * inv;
    }
    __syncthreads();

    for (int idx = tid; idx < Tt * DHd; idx += 256) {
        int i = idx >> 5, d = idx & 31;
        const float* row = sc + i * Tt;
        float o = 0.f;
        #pragma unroll 5
        for (int j = 0; j < Tt; j++) o += row[j] * vt[j][d];
        size_t oidx = ((size_t)b * Tt + i) * Dm + hh * DHd + d;
        __nv_bfloat16 h2, l2;
        split2(o, h2, l2);
        g_act0[oidx] = h2;
        g_act0[PL0 + oidx] = l2;
    }
}

// ---------------- residual add + LayerNorm (4 tokens/block, float4) ----------------
__global__ __launch_bounds__(256) void add_ln_k(
    float* __restrict__ h, const float* __restrict__ t,
    const float* __restrict__ g, const float* __restrict__ bb)
{
    __shared__ float sms[8];
    const int tid = threadIdx.x;
    const int grp = tid >> 6;
    const int lt  = tid & 63;
    const int wid = tid >> 5;
    const size_t row = (size_t)blockIdx.x * 4 + grp;
    const size_t base = row * Dm + lt * 4;

    float4 hv = *reinterpret_cast<const float4*>(h + base);
    float4 tv = *reinterpret_cast<const float4*>(t + base);
    float v0 = hv.x + tv.x, v1 = hv.y + tv.y, v2 = hv.z + tv.z, v3 = hv.w + tv.w;

    float s = v0 + v1 + v2 + v3;
    #pragma unroll
    for (int o = 16; o > 0; o >>= 1) s += __shfl_down_sync(0xffffffffu, s, o);
    if ((tid & 31) == 0) sms[wid] = s;
    __syncthreads();
    float mean = (sms[grp * 2] + sms[grp * 2 + 1]) * (1.0f / Dm);
    __syncthreads();

    float d0 = v0 - mean, d1 = v1 - mean, d2 = v2 - mean, d3 = v3 - mean;
    float s2 = d0 * d0 + d1 * d1 + d2 * d2 + d3 * d3;
    #pragma unroll
    for (int o = 16; o > 0; o >>= 1) s2 += __shfl_down_sync(0xffffffffu, s2, o);
    if ((tid & 31) == 0) sms[wid] = s2;
    __syncthreads();
    float var = (sms[grp * 2] + sms[grp * 2 + 1]) * (1.0f / Dm);
    float rs = rsqrtf(var + LN_EPS);

    float4 gv = *reinterpret_cast<const float4*>(g + lt * 4);
    float4 bv = *reinterpret_cast<const float4*>(bb + lt * 4);
    float o0 = d0 * rs * gv.x + bv.x;
    float o1 = d1 * rs * gv.y + bv.y;
    float o2 = d2 * rs * gv.z + bv.z;
    float o3 = d3 * rs * gv.w + bv.w;

    *reinterpret_cast<float4*>(h + base) = make_float4(o0, o1, o2, o3);

    __nv_bfloat16 h0, l0, h1, l1, h2, l2, h3, l3;
    split2(o0, h0, l0); split2(o1, h1, l1); split2(o2, h2, l2); split2(o3, h3, l3);
    __nv_bfloat162 hp0(h0, h1), hp1(h2, h3), lp0(l0, l1), lp1(l2, l3);
    uint2 hw, lw;
    hw.x = *reinterpret_cast<uint32_t*>(&hp0); hw.y = *reinterpret_cast<uint32_t*>(&hp1);
    lw.x = *reinterpret_cast<uint32_t*>(&lp0); lw.y = *reinterpret_cast<uint32_t*>(&lp1);
    *reinterpret_cast<uint2*>(&g_act0[base]) = hw;
    *reinterpret_cast<uint2*>(&g_act0[PL0 + base]) = lw;
}

// ---------------- final head ----------------
__global__ __launch_bounds__(256) void final_head_k(
    const float* __restrict__ lnfg, const float* __restrict__ lnfb,
    const float* __restrict__ Wout, const float* __restrict__ bout)
{
    __shared__ float xn[Dm];
    __shared__ float sm[32];
    const int tid = threadIdx.x;
    const int b = blockIdx.x;
    float v = g_h[(size_t)b * Tt * Dm + tid];
    float mean = bred256(v, sm) * (1.0f / Dm);
    float d = v - mean;
    float var = bred256(d * d, sm) * (1.0f / Dm);
    xn[tid] = d * rsqrtf(var + LN_EPS) * lnfg[tid] + lnfb[tid];
    __syncthreads();
    if (tid < Ed) {
        const float* w = Wout + (size_t)tid * Dm;
        float a = bout[tid];
        #pragma unroll 8
        for (int t = 0; t < Dm; t++) a += xn[t] * w[t];
        g_ze[(size_t)b * Ed + tid] = a;
    }
}

// ---------------- codebook norms ----------------
__global__ __launch_bounds__(128) void cnorm_k(const float* __restrict__ cb) {
    __shared__ float sm[4];
    const int tid = threadIdx.x;
    float v = cb[(size_t)blockIdx.x * Ed + tid];
    v *= v;
    #pragma unroll
    for (int o = 16; o > 0; o >>= 1) v += __shfl_down_sync(0xffffffffu, v, o);
    if ((tid & 31) == 0) sm[tid >> 5] = v;
    __syncthreads();
    if (tid == 0) g_cnorm[blockIdx.x] = sm[0] + sm[1] + sm[2] + sm[3];
}

// ---------------- VQ ----------------
__global__ __launch_bounds__(256) void vq_k(const float* __restrict__ cb) {
    __shared__ float ze[Ed];
    __shared__ float bm[256];
    __shared__ int   bi[256];
    __shared__ int   chosen;
    __shared__ float sm[32];
    const int tid = threadIdx.x;
    const int b = blockIdx.x;
    if (tid < Ed) ze[tid] = g_ze[(size_t)b * Ed + tid];
    __syncthreads();

    float best = 3.4e38f;
    int besti = 0x7fffffff;
    for (int k = tid; k < Kcb; k += 256) {
        const float* c = cb + (size_t)k * Ed;
        float dot = 0.f;
        #pragma unroll 4
        for (int e = 0; e < Ed; e++) dot += ze[e] * c[e];
        float dd = g_cnorm[k] - 2.0f * dot;
        if (dd < best || (dd == best && k < besti)) { best = dd; besti = k; }
    }
    bm[tid] = best; bi[tid] = besti;
    __syncthreads();
    for (int off = 128; off > 0; off >>= 1) {
        if (tid < off) {
            float ob = bm[tid + off]; int oi = bi[tid + off];
            if (ob < bm[tid] || (ob == bm[tid] && oi < bi[tid])) { bm[tid] = ob; bi[tid] = oi; }
        }
        __syncthreads();
    }
    if (tid == 0) {
        chosen = bi[0];
        g_idx[b] = bi[0];
        atomicAdd(&g_hist[bi[0]], 1);
    }
    __syncthreads();

    const int kk = chosen;
    float part = 0.f;
    if (tid < Ed) {
        float diff = cb[(size_t)kk * Ed + tid] - ze[tid];
        part = diff * diff;
    }
    float tot = bred256(part, sm);
    if (tid == 0) g_losspart[b] = tot;
}

// ---------------- decoder ----------------
__global__ __launch_bounds__(256) void decoder_k(
    const float* __restrict__ cb,
    const float* __restrict__ Wd1, const float* __restrict__ bd1,
    const float* __restrict__ lndg, const float* __restrict__ lndb,
    const float* __restrict__ Wd2, const float* __restrict__ bd2,
    const float* __restrict__ Wd3, const float* __restrict__ bd3,
    float* __restrict__ outp)
{
    __shared__ float zq[Ed];
    __shared__ float d1[Dm];
    __shared__ float d2s[Ed];
    __shared__ float sm[32];
    const int tid = threadIdx.x;
    const int b = blockIdx.x;
    const int ci = g_idx[b];
    if (tid < Ed) zq[tid] = cb[(size_t)ci * Ed + tid];
    __syncthreads();

    float t1 = bd1[tid];
    {
        const float* w = Wd1 + (size_t)tid * Ed;
        #pragma unroll 4
        for (int e = 0; e < Ed; e++) t1 += zq[e] * w[e];
    }
    float mean = bred256(t1, sm) * (1.0f / Dm);
    float dd = t1 - mean;
    float var = bred256(dd * dd, sm) * (1.0f / Dm);
    float xg = dd * rsqrtf(var + LN_EPS) * lndg[tid] + lndb[tid];
    d1[tid] = gelu_exact(xg);
    __syncthreads();

    if (tid < Ed) {
        const float* w2 = Wd2 + (size_t)tid * Dm;
        float t2 = bd2[tid];
        #pragma unroll 8
        for (int t = 0; t < Dm; t++) t2 += d1[t] * w2[t];
        d2s[tid] = gelu_exact(t2);
    }
    __syncthreads();

    if (tid < 2) {
        const float* w3 = Wd3 + (size_t)tid * Ed;
        float vv = bd3[tid];
        #pragma unroll 4
        for (int e = 0; e < Ed; e++) vv += d2s[e] * w3[e];
        outp[(size_t)b * 2 + tid] = vv;
    }
    if (tid == 2) outp[(size_t)Bsz * 2 + b] = (float)ci;
}

// ---------------- scalars ----------------
__global__ __launch_bounds__(1024) void scalars_k(float* __restrict__ outp) {
    __shared__ float sm[32];
    const int tid = threadIdx.x;

    float p = (float)g_hist[tid] * (1.0f / (float)Bsz);
    float term = p * logf(p + 1e-10f);
    float v = term;
    #pragma unroll
    for (int o = 16; o > 0; o >>= 1) v += __shfl_down_sync(0xffffffffu, v, o);
    if ((tid & 31) == 0) sm[tid >> 5] = v;
    __syncthreads();
    float ent = 0.f;
    if (tid == 0) {
        for (int i = 0; i < 32; i++) ent += sm[i];
        sm[0] = ent;
    }
    __syncthreads();
    ent = sm[0];
    __syncthreads();

    float lp = g_losspart[tid] + g_losspart[tid + 1024];
    #pragma unroll
    for (int o = 16; o > 0; o >>= 1) lp += __shfl_down_sync(0xffffffffu, lp, o);
    if ((tid & 31) == 0) sm[tid >> 5] = lp;
    __syncthreads();
    if (tid == 0) {
        float tot = 0.f;
        for (int i = 0; i < 32; i++) tot += sm[i];
        outp[(size_t)Bsz * 2 + Bsz + 0] = 0.1f * tot / ((float)Bsz * (float)Ed);
        outp[(size_t)Bsz * 2 + Bsz + 1] = expf(-ent);
    }
}

__global__ __launch_bounds__(1024) void zero_k() {
    g_hist[threadIdx.x] = 0;
}

// ---------------- host ----------------
template <typename T>
static T* sym_addr(const void* sym) {
    void* p = nullptr;
    cudaGetSymbolAddress(&p, sym);
    return (T*)p;
}

extern "C" void kernel_launch(void* const* d_in, const int* in_sizes, int n_in,
                              void* d_out, int out_size)
{
    (void)in_sizes; (void)n_in; (void)out_size;
    const float* x     = (const float*)d_in[0];
    const float* W_in  = (const float*)d_in[1];
    const float* b_in  = (const float*)d_in[2];
    const float* cls   = (const float*)d_in[3];
    const float* Wqkv  = (const float*)d_in[4];
    const float* bqkv  = (const float*)d_in[5];
    const float* Wo    = (const float*)d_in[6];
    const float* bo    = (const float*)d_in[7];
    const float* W1    = (const float*)d_in[8];
    const float* b1    = (const float*)d_in[9];
    const float* W2    = (const float*)d_in[10];
    const float* b2    = (const float*)d_in[11];
    const float* ln1g  = (const float*)d_in[12];
    const float* ln1b  = (const float*)d_in[13];
    const float* ln2g  = (const float*)d_in[14];
    const float* ln2b  = (const float*)d_in[15];
    const float* lnfg  = (const float*)d_in[16];
    const float* lnfb  = (const float*)d_in[17];
    const float* Wout  = (const float*)d_in[18];
    const float* bout  = (const float*)d_in[19];
    const float* cb    = (const float*)d_in[20];
    const float* Wd1   = (const float*)d_in[21];
    const float* bd1   = (const float*)d_in[22];
    const float* lndg  = (const float*)d_in[23];
    const float* lndb  = (const float*)d_in[24];
    const float* Wd2   = (const float*)d_in[25];
    const float* bd2   = (const float*)d_in[26];
    const float* Wd3   = (const float*)d_in[27];
    const float* bd3   = (const float*)d_in[28];
    float* outp = (float*)d_out;

    float* pH    = sym_addr<float>(g_h);
    float* pTmp  = sym_addr<float>(g_tmp);
    __nv_bfloat16* pAct0 = sym_addr<__nv_bfloat16>(g_act0);
    __nv_bfloat16* pAct1 = sym_addr<__nv_bfloat16>(g_act1);
    __nv_bfloat16* pXb   = sym_addr<__nv_bfloat16>(g_xb);
    __nv_bfloat16* pWin  = sym_addr<__nv_bfloat16>(g_winb);
    __nv_bfloat16* pWq = sym_addr<__nv_bfloat16>(g_wqkvb);
    __nv_bfloat16* pWo = sym_addr<__nv_bfloat16>(g_wob);
    __nv_bfloat16* pW1 = sym_addr<__nv_bfloat16>(g_w1b);
    __nv_bfloat16* pW2 = sym_addr<__nv_bfloat16>(g_w2b);

    cudaFuncSetAttribute(bfgemm_k<0>, cudaFuncAttributeMaxDynamicSharedMemorySize, SMEM_DYN);
    cudaFuncSetAttribute(bfgemm_k<1>, cudaFuncAttributeMaxDynamicSharedMemorySize, SMEM_DYN);
    cudaFuncSetAttribute(bfgemm_k<2>, cudaFuncAttributeMaxDynamicSharedMemorySize, SMEM_DYN);
    cudaFuncSetAttribute(bfgemm_k<3>, cudaFuncAttributeMaxDynamicSharedMemorySize, SMEM_DYN);

    convw_k<<<1024, 256>>>(Wqkv, Wo, W1, W2);                       // 1
    convx_k<<<2048, 256>>>(x);                                      // 2
    convin_k<<<(Dm * KIN + 255) / 256, 256>>>(W_in);                // 3
    // input projection + PE via mma path (launch #4 = ncu capture slot)
    bfgemm_k<3><<<dim3(Dm / 128, MIN0 / 128), 256, SMEM_DYN>>>(
        pXb, PLX, pWin, (size_t)Dm * KIN, b_in, nullptr, MIN0, Dm, KIN);
    cls_fill_k<<<Bsz, 256>>>(cls);

    for (int i = 0; i < NL; i++) {
        bfgemm_k<2><<<dim3(768 / 128, MTOK / 128), 256, SMEM_DYN>>>(
            pAct0, PL0, pWq + (size_t)i * 2 * WQKV_SZ, (size_t)WQKV_SZ,
            bqkv + (size_t)i * 3 * Dm, nullptr, MTOK, 3 * Dm, Dm);
        attn_k<<<Bsz * NH, 256>>>();
        bfgemm_k<0><<<dim3(Dm / 128, MTOK / 128), 256, SMEM_DYN>>>(
            pAct0, PL0, pWo + (size_t)i * 2 * WO_SZ, (size_t)WO_SZ,
            bo + (size_t)i * Dm, pTmp, MTOK, Dm, Dm);
        add_ln_k<<<MTOK / 4, 256>>>(pH, pTmp, ln1g + (size_t)i * Dm, ln1b + (size_t)i * Dm);
        bfgemm_k<1><<<dim3(FFd / 128, MTOK / 128), 256, SMEM_DYN>>>(
            pAct0, PL0, pW1 + (size_t)i * 2 * W1_SZ, (size_t)W1_SZ,
            b1 + (size_t)i * FFd, nullptr, MTOK, FFd, Dm);
        bfgemm_k<0><<<dim3(Dm / 128, MTOK / 128), 256, SMEM_DYN>>>(
            pAct1, PL1, pW2 + (size_t)i * 2 * W2_SZ, (size_t)W2_SZ,
            b2 + (size_t)i * Dm, pTmp, MTOK, Dm, FFd);
        add_ln_k<<<MTOK / 4, 256>>>(pH, pTmp, ln2g + (size_t)i * Dm, ln2b + (size_t)i * Dm);
    }

    zero_k<<<1, 1024>>>();
    cnorm_k<<<Kcb, 128>>>(cb);
    final_head_k<<<Bsz, 256>>>(lnfg, lnfb, Wout, bout);
    vq_k<<<Bsz, 256>>>(cb);
    decoder_k<<<Bsz, 256>>>(cb, Wd1, bd1, lndg, lndb, Wd2, bd2, Wd3, bd3, outp);
    scalars_k<<<1, 1024>>>(outp);
}

// round 10
// speedup vs baseline: 5.5485x; 1.1337x over previous
#include <cuda_runtime.h>
#include <cuda_bf16.h>
#include <math.h>
#include <stdint.h>

// ---------------- problem constants ----------------
#define Bsz 2048
#define Ssz 64
#define Cin 142
#define KIN 160
#define Dm  256
#define NH  8
#define DHd 32
#define FFd 512
#define NL  3
#define Ed  128
#define Kcb 1024
#define Tt  65
#define MTOK (Bsz*Tt)
#define MIN0 (Bsz*Ssz)
#define LN_EPS 1e-5f

#define PL0 ((size_t)MTOK*Dm)
#define PL1 ((size_t)MTOK*FFd)
#define PLQ ((size_t)MTOK*3*Dm)
#define PLX ((size_t)MIN0*KIN)
#define WQKV_SZ (3*Dm*Dm)
#define WO_SZ   (Dm*Dm)
#define W1_SZ   (FFd*Dm)
#define W2_SZ   (Dm*FFd)
#define WLAYER  (WQKV_SZ+WO_SZ+W1_SZ+W2_SZ)

// ---------------- scratch ----------------
__device__ float g_h   [(size_t)Bsz*Tt*Dm];
__device__ float g_tmp [(size_t)Bsz*Tt*Dm];
__device__ float g_ze  [(size_t)Bsz*Ed];
__device__ int   g_idx [Bsz];
__device__ float g_cnorm[Kcb];
__device__ int   g_hist[Kcb];
__device__ float g_losspart[Bsz];

__device__ __nv_bfloat16 g_act0[2*PL0];
__device__ __nv_bfloat16 g_act1[2*PL1];
__device__ __nv_bfloat16 g_qkvb[2*PLQ];
__device__ __nv_bfloat16 g_xb  [2*PLX];
__device__ __nv_bfloat16 g_winb[2*Dm*KIN];
__device__ __nv_bfloat16 g_wqkvb[(size_t)NL*2*WQKV_SZ];
__device__ __nv_bfloat16 g_wob  [(size_t)NL*2*WO_SZ];
__device__ __nv_bfloat16 g_w1b  [(size_t)NL*2*W1_SZ];
__device__ __nv_bfloat16 g_w2b  [(size_t)NL*2*W2_SZ];

// ---------------- low-level helpers ----------------
__device__ __forceinline__ uint32_t smem_to_u32(const void* p) {
    uint32_t a;
    asm("{ .reg .u64 t; cvta.to.shared.u64 t, %1; cvt.u32.u64 %0, t; }" : "=r"(a) : "l"(p));
    return a;
}
__device__ __forceinline__ void cp_async16(uint32_t saddr, const void* gaddr) {
    asm volatile("cp.async.cg.shared.global [%0], [%1], 16;" :: "r"(saddr), "l"(gaddr));
}
__device__ __forceinline__ void ldsm4(uint32_t* r, uint32_t addr) {
    asm volatile("ldmatrix.sync.aligned.m8n8.x4.shared.b16 {%0,%1,%2,%3}, [%4];"
        : "=r"(r[0]), "=r"(r[1]), "=r"(r[2]), "=r"(r[3]) : "r"(addr));
}
__device__ __forceinline__ void mma16816(float* c, const uint32_t* a, const uint32_t* b) {
    asm volatile(
        "mma.sync.aligned.m16n8k16.row.col.f32.bf16.bf16.f32 "
        "{%0,%1,%2,%3}, {%4,%5,%6,%7}, {%8,%9}, {%0,%1,%2,%3};"
        : "+f"(c[0]), "+f"(c[1]), "+f"(c[2]), "+f"(c[3])
        : "r"(a[0]), "r"(a[1]), "r"(a[2]), "r"(a[3]), "r"(b[0]), "r"(b[1]));
}
__device__ __forceinline__ float gelu_exact(float x) {
    return 0.5f * x * (1.0f + erff(x * 0.7071067811865475f));
}
__device__ __forceinline__ void split2(float v, __nv_bfloat16& h, __nv_bfloat16& l) {
    h = __float2bfloat16(v);
    l = __float2bfloat16(v - __bfloat162float(h));
}
__device__ __forceinline__ float bred256(float v, float* sm) {
    int tid = threadIdx.x;
    #pragma unroll
    for (int o = 16; o > 0; o >>= 1) v += __shfl_down_sync(0xffffffffu, v, o);
    if ((tid & 31) == 0) sm[tid >> 5] = v;
    __syncthreads();
    if (tid == 0) {
        float t = 0.f;
        #pragma unroll
        for (int i = 0; i < 8; i++) t += sm[i];
        sm[0] = t;
    }
    __syncthreads();
    float r = sm[0];
    __syncthreads();
    return r;
}
__device__ __forceinline__ float pe_val(int s, int c) {
    int j = c >> 1;
    float freq = expf(-(float)(2 * j) * (9.210340371976184f / 256.0f));
    float ang = (float)s * freq;
    return (c & 1) ? cosf(ang) : sinf(ang);
}

// ---------------- mma.sync bf16 2-split (3-term) GEMM ----------------
#define PLANE_B 8192
#define STAGE_B 32768
#define SMEM_DYN (3*STAGE_B)   // 96 KB

__device__ __forceinline__ uint32_t sw_addr(uint32_t plane_base, int r, int colk) {
    int chunk = (colk >> 3) ^ ((r >> 1) & 3);
    return plane_base + r * 64 + (chunk << 4) + ((colk & 7) << 1);
}

__device__ __forceinline__ void issue_stage(
    uint32_t sbase, const __nv_bfloat16* __restrict__ A, size_t aps,
    const __nv_bfloat16* __restrict__ W, size_t wps,
    int row0, int col0, int K, int k0, int tid)
{
    #pragma unroll
    for (int i = 0; i < 8; i++) {
        const int plane = i >> 1;
        const int idx = ((i & 1) << 8) + tid;
        const int r = idx >> 2, c16 = idx & 3;
        const __nv_bfloat16* src = (plane < 2)
            ? A + (size_t)plane * aps + (size_t)(row0 + r) * K + (k0 + c16 * 8)
            : W + (size_t)(plane - 2) * wps + (size_t)(col0 + r) * K + (k0 + c16 * 8);
        uint32_t dst = sbase + plane * PLANE_B + r * 64 + ((c16 ^ ((r >> 1) & 3)) << 4);
        cp_async16(dst, src);
    }
}

// EPI 0: residual (reads g_h) + fp32 to C. EPI 1: gelu -> act1 planes.
// EPI 2: qkvb planes. EPI 3: input-proj (PE + remap -> g_h + act0 planes)
template <int EPI>
__global__ __launch_bounds__(256, 2)
void bfgemm_k(const __nv_bfloat16* __restrict__ A, size_t aps,
              const __nv_bfloat16* __restrict__ W, size_t wps,
              const float* __restrict__ bias, float* __restrict__ C,
              int M, int N, int K)
{
    extern __shared__ char smem[];
    const uint32_t sb = smem_to_u32(smem);
    const int tid = threadIdx.x;
    const int lane = tid & 31, wid = tid >> 5;
    const int row0 = blockIdx.y * 128;
    const int col0 = blockIdx.x * 128;
    const int wm0 = (wid & 1) * 64;
    const int wn0 = (wid >> 1) * 32;
    const int qr = lane >> 2, qc = lane & 3;

    const int lj = lane >> 3;
    const int lr8 = lane & 7;
    const int a_row_off = ((lj & 1) << 3) + lr8;
    const int a_k_off   = (lj >> 1) << 3;
    const int b_row_off = ((lj >> 1) << 3) + lr8;
    const int b_k_off   = (lj & 1) << 3;

    float acc[4][4][4];
    #pragma unroll
    for (int a = 0; a < 4; a++)
        #pragma unroll
        for (int b = 0; b < 4; b++)
            #pragma unroll
            for (int c = 0; c < 4; c++) acc[a][b][c] = 0.f;

    const int nk = K >> 5;

    issue_stage(sb, A, aps, W, wps, row0, col0, K, 0, tid);
    asm volatile("cp.async.commit_group;" ::: "memory");
    issue_stage(sb + STAGE_B, A, aps, W, wps, row0, col0, K, 32, tid);
    asm volatile("cp.async.commit_group;" ::: "memory");

    for (int s = 0; s < nk; s++) {
        if (s + 1 < nk) {
            asm volatile("cp.async.wait_group 1;" ::: "memory");
        } else {
            asm volatile("cp.async.wait_group 0;" ::: "memory");
        }
        __syncthreads();
        if (s + 2 < nk) {
            issue_stage(sb + ((s + 2) % 3) * STAGE_B, A, aps, W, wps, row0, col0, K, (s + 2) << 5, tid);
            asm volatile("cp.async.commit_group;" ::: "memory");
        }

        const uint32_t stg = sb + (s % 3) * STAGE_B;
        const uint32_t ah_b = stg;
        const uint32_t al_b = stg + PLANE_B;
        const uint32_t wh_b = stg + 2 * PLANE_B;
        const uint32_t wl_b = stg + 3 * PLANE_B;

        #pragma unroll
        for (int kk = 0; kk < 32; kk += 16) {
            uint32_t areg[4][4];
            uint32_t bh[4][2], bl[4][2];

            #pragma unroll
            for (int np = 0; np < 2; np++) {
                uint32_t t4[4];
                ldsm4(t4, sw_addr(wh_b, wn0 + np * 16 + b_row_off, kk + b_k_off));
                bh[np * 2][0] = t4[0]; bh[np * 2][1] = t4[1];
                bh[np * 2 + 1][0] = t4[2]; bh[np * 2 + 1][1] = t4[3];
            }
            #pragma unroll
            for (int mi = 0; mi < 4; mi++)
                ldsm4(areg[mi], sw_addr(ah_b, wm0 + mi * 16 + a_row_off, kk + a_k_off));
            #pragma unroll
            for (int mi = 0; mi < 4; mi++)
                #pragma unroll
                for (int ni = 0; ni < 4; ni++)
                    mma16816(acc[mi][ni], areg[mi], bh[ni]);
            #pragma unroll
            for (int np = 0; np < 2; np++) {
                uint32_t t4[4];
                ldsm4(t4, sw_addr(wl_b, wn0 + np * 16 + b_row_off, kk + b_k_off));
                bl[np * 2][0] = t4[0]; bl[np * 2][1] = t4[1];
                bl[np * 2 + 1][0] = t4[2]; bl[np * 2 + 1][1] = t4[3];
            }
            #pragma unroll
            for (int mi = 0; mi < 4; mi++)
                #pragma unroll
                for (int ni = 0; ni < 4; ni++)
                    mma16816(acc[mi][ni], areg[mi], bl[ni]);
            #pragma unroll
            for (int mi = 0; mi < 4; mi++)
                ldsm4(areg[mi], sw_addr(al_b, wm0 + mi * 16 + a_row_off, kk + a_k_off));
            #pragma unroll
            for (int mi = 0; mi < 4; mi++)
                #pragma unroll
                for (int ni = 0; ni < 4; ni++)
                    mma16816(acc[mi][ni], areg[mi], bh[ni]);
        }
        __syncthreads();
    }

    // ---- epilogue ----
    #pragma unroll
    for (int mi = 0; mi < 4; mi++) {
        #pragma unroll
        for (int ni = 0; ni < 4; ni++) {
            int col = col0 + wn0 + ni * 8 + qc * 2;
            float b0 = bias[col], b1 = bias[col + 1];
            #pragma unroll
            for (int half = 0; half < 2; half++) {
                int r = row0 + wm0 + mi * 16 + qr + half * 8;
                float v0 = acc[mi][ni][half * 2 + 0] + b0;
                float v1 = acc[mi][ni][half * 2 + 1] + b1;
                if (EPI == 3) {
                    int ss = r & 63, bb = r >> 6;
                    v0 += pe_val(ss, col);
                    v1 += pe_val(ss, col + 1);
                    size_t o = ((size_t)bb * Tt + 1 + ss) * Dm + col;
                    *reinterpret_cast<float2*>(&g_h[o]) = make_float2(v0, v1);
                    __nv_bfloat16 h0, l0, h1, l1;
                    split2(v0, h0, l0);
                    split2(v1, h1, l1);
                    *reinterpret_cast<__nv_bfloat162*>(&g_act0[o]) = __nv_bfloat162(h0, h1);
                    *reinterpret_cast<__nv_bfloat162*>(&g_act0[PL0 + o]) = __nv_bfloat162(l0, l1);
                } else {
                    size_t o = (size_t)r * N + col;
                    if (EPI == 0) {
                        float2 hv = *reinterpret_cast<const float2*>(&g_h[o]);
                        *reinterpret_cast<float2*>(C + o) = make_float2(v0 + hv.x, v1 + hv.y);
                    } else if (EPI == 1) {
                        float g0 = gelu_exact(v0), g1 = gelu_exact(v1);
                        __nv_bfloat16 h0, l0, h1, l1;
                        split2(g0, h0, l0);
                        split2(g1, h1, l1);
                        *reinterpret_cast<__nv_bfloat162*>(&g_act1[o]) = __nv_bfloat162(h0, h1);
                        *reinterpret_cast<__nv_bfloat162*>(&g_act1[PL1 + o]) = __nv_bfloat162(l0, l1);
                    } else {
                        __nv_bfloat16 h0, l0, h1, l1;
                        split2(v0, h0, l0);
                        split2(v1, h1, l1);
                        *reinterpret_cast<__nv_bfloat162*>(&g_qkvb[o]) = __nv_bfloat162(h0, h1);
                        *reinterpret_cast<__nv_bfloat162*>(&g_qkvb[PLQ + o]) = __nv_bfloat162(l0, l1);
                    }
                }
            }
        }
    }
}

// ---------------- weight split ----------------
__global__ __launch_bounds__(256) void convw_k(
    const float* __restrict__ Wqkv, const float* __restrict__ Wo,
    const float* __restrict__ W1, const float* __restrict__ W2)
{
    const size_t total = (size_t)NL * WLAYER;
    for (size_t i = (size_t)blockIdx.x * blockDim.x + threadIdx.x; i < total;
         i += (size_t)gridDim.x * blockDim.x) {
        int layer = (int)(i / WLAYER);
        int off = (int)(i % WLAYER);
        float v; __nv_bfloat16 *dh, *dl;
        if (off < WQKV_SZ) {
            v = Wqkv[(size_t)layer * WQKV_SZ + off];
            dh = g_wqkvb + ((size_t)layer * 2 + 0) * WQKV_SZ + off;
            dl = g_wqkvb + ((size_t)layer * 2 + 1) * WQKV_SZ + off;
        } else if (off < WQKV_SZ + WO_SZ) {
            int o2 = off - WQKV_SZ;
            v = Wo[(size_t)layer * WO_SZ + o2];
            dh = g_wob + ((size_t)layer * 2 + 0) * WO_SZ + o2;
            dl = g_wob + ((size_t)layer * 2 + 1) * WO_SZ + o2;
        } else if (off < WQKV_SZ + WO_SZ + W1_SZ) {
            int o2 = off - WQKV_SZ - WO_SZ;
            v = W1[(size_t)layer * W1_SZ + o2];
            dh = g_w1b + ((size_t)layer * 2 + 0) * W1_SZ + o2;
            dl = g_w1b + ((size_t)layer * 2 + 1) * W1_SZ + o2;
        } else {
            int o2 = off - WQKV_SZ - WO_SZ - W1_SZ;
            v = W2[(size_t)layer * W2_SZ + o2];
            dh = g_w2b + ((size_t)layer * 2 + 0) * W2_SZ + o2;
            dl = g_w2b + ((size_t)layer * 2 + 1) * W2_SZ + o2;
        }
        __nv_bfloat16 a, b;
        split2(v, a, b);
        *dh = a; *dl = b;
    }
}

// ---------------- prep: x planes + W_in planes + cls fill ----------------
__global__ __launch_bounds__(256) void prep_k(
    const float* __restrict__ x, const float* __restrict__ W_in,
    const float* __restrict__ cls)
{
    const size_t totX = (size_t)MIN0 * KIN;
    const size_t totW = (size_t)Dm * KIN;
    const size_t totC = (size_t)Bsz * Dm;
    const size_t total = totX + totW + totC;
    for (size_t i = (size_t)blockIdx.x * blockDim.x + threadIdx.x; i < total;
         i += (size_t)gridDim.x * blockDim.x) {
        if (i < totX) {
            size_t row = i / KIN;
            int k = (int)(i % KIN);
            float v = (k < Cin) ? x[row * Cin + k] : 0.f;
            __nv_bfloat16 a, b;
            split2(v, a, b);
            g_xb[i] = a;
            g_xb[PLX + i] = b;
        } else if (i < totX + totW) {
            size_t j = i - totX;
            int row = (int)(j / KIN), k = (int)(j % KIN);
            float v = (k < Cin) ? W_in[row * Cin + k] : 0.f;
            __nv_bfloat16 a, b;
            split2(v, a, b);
            g_winb[j] = a;
            g_winb[(size_t)Dm * KIN + j] = b;
        } else {
            size_t j = i - totX - totW;
            size_t bb = j / Dm;
            int d = (int)(j % Dm);
            float v = cls[d];
            size_t idx = bb * Tt * Dm + d;
            g_h[idx] = v;
            __nv_bfloat16 hh, ll;
            split2(v, hh, ll);
            g_act0[idx] = hh;
            g_act0[PL0 + idx] = ll;
        }
    }
}

// ---------------- attention: register-blocked ----------------
#define TP 68   // padded T
__global__ __launch_bounds__(256) void attn_k()
{
    const int b  = blockIdx.x >> 3;
    const int hh = blockIdx.x & 7;
    const size_t base = (size_t)b * Tt * (3 * Dm) + hh * DHd;

    __shared__ float q [TP][33];
    __shared__ float kt[TP][33];
    __shared__ float vt[TP][33];
    __shared__ float sc[TP * TP];

    const int tid = threadIdx.x;
    const int lane = tid & 31, wid = tid >> 5;

    // load + zero-pad rows 65..67
    for (int idx = tid; idx < TP * DHd; idx += 256) {
        int t = idx >> 5, d = idx & 31;
        if (t < Tt) {
            size_t o = base + (size_t)t * (3 * Dm) + d;
            q [t][d] = __bfloat162float(g_qkvb[o])          + __bfloat162float(g_qkvb[PLQ + o]);
            kt[t][d] = __bfloat162float(g_qkvb[o + Dm])     + __bfloat162float(g_qkvb[PLQ + o + Dm]);
            vt[t][d] = __bfloat162float(g_qkvb[o + 2 * Dm]) + __bfloat162float(g_qkvb[PLQ + o + 2 * Dm]);
        } else {
            q[t][d] = 0.f; kt[t][d] = 0.f; vt[t][d] = 0.f;
        }
    }
    __syncthreads();

    // scores: 4x4 register tiles, 17x17 = 289 tiles
    const float scale = 0.17677669529663689f;
    for (int tile = tid; tile < 289; tile += 256) {
        int ti = tile / 17, tj = tile - ti * 17;
        int i0 = ti << 2, j0 = tj << 2;
        float a2[4][4];
        #pragma unroll
        for (int a = 0; a < 4; a++)
            #pragma unroll
            for (int bq = 0; bq < 4; bq++) a2[a][bq] = 0.f;
        #pragma unroll 8
        for (int d = 0; d < DHd; d++) {
            float qv[4], kv[4];
            #pragma unroll
            for (int a = 0; a < 4; a++) qv[a] = q[i0 + a][d];
            #pragma unroll
            for (int bq = 0; bq < 4; bq++) kv[bq] = kt[j0 + bq][d];
            #pragma unroll
            for (int a = 0; a < 4; a++)
                #pragma unroll
                for (int bq = 0; bq < 4; bq++) a2[a][bq] += qv[a] * kv[bq];
        }
        #pragma unroll
        for (int a = 0; a < 4; a++)
            #pragma unroll
            for (int bq = 0; bq < 4; bq++)
                sc[(i0 + a) * TP + j0 + bq] = a2[a][bq] * scale;
    }
    __syncthreads();

    // warp-parallel softmax over rows (ignores padded cols >= 65)
    for (int r = wid; r < Tt; r += 8) {
        float* row = sc + r * TP;
        float e0 = row[lane];
        float e1 = row[32 + lane];
        float e2 = (lane == 0) ? row[64] : -3.4e38f;
        float m = fmaxf(fmaxf(e0, e1), e2);
        #pragma unroll
        for (int o = 16; o > 0; o >>= 1) m = fmaxf(m, __shfl_xor_sync(0xffffffffu, m, o));
        e0 = expf(e0 - m);
        e1 = expf(e1 - m);
        e2 = (lane == 0) ? expf(e2 - m) : 0.f;
        float s = e0 + e1 + e2;
        #pragma unroll
        for (int o = 16; o > 0; o >>= 1) s += __shfl_xor_sync(0xffffffffu, s, o);
        float inv = 1.0f / s;
        row[lane] = e0 * inv;
        row[32 + lane] = e1 * inv;
        if (lane == 0) row[64] = e2 * inv;
    }
    __syncthreads();

    // AV: 4-row blocking; item = (i-group 0..16) x (d 0..31)
    for (int item = tid; item < 17 * 32; item += 256) {
        int ig = item >> 5, d = item & 31;
        int i0 = ig << 2;
        float o0 = 0.f, o1 = 0.f, o2 = 0.f, o3 = 0.f;
        #pragma unroll 5
        for (int j = 0; j < Tt; j++) {
            float vv = vt[j][d];
            o0 += sc[(i0 + 0) * TP + j] * vv;
            o1 += sc[(i0 + 1) * TP + j] * vv;
            o2 += sc[(i0 + 2) * TP + j] * vv;
            o3 += sc[(i0 + 3) * TP + j] * vv;
        }
        float ov[4] = {o0, o1, o2, o3};
        #pragma unroll
        for (int a = 0; a < 4; a++) {
            int i = i0 + a;
            if (i < Tt) {
                size_t oidx = ((size_t)b * Tt + i) * Dm + hh * DHd + d;
                __nv_bfloat16 h2, l2;
                split2(ov[a], h2, l2);
                g_act0[oidx] = h2;
                g_act0[PL0 + oidx] = l2;
            }
        }
    }
}

// ---------------- LayerNorm (input presummed in t), writes h + planes ----------------
__global__ __launch_bounds__(256) void add_ln_k(
    float* __restrict__ h, const float* __restrict__ t,
    const float* __restrict__ g, const float* __restrict__ bb)
{
    __shared__ float sms[8];
    const int tid = threadIdx.x;
    const int grp = tid >> 6;
    const int lt  = tid & 63;
    const int wid = tid >> 5;
    const size_t row = (size_t)blockIdx.x * 4 + grp;
    const size_t base = row * Dm + lt * 4;

    float4 tv = *reinterpret_cast<const float4*>(t + base);
    float v0 = tv.x, v1 = tv.y, v2 = tv.z, v3 = tv.w;

    float s = v0 + v1 + v2 + v3;
    #pragma unroll
    for (int o = 16; o > 0; o >>= 1) s += __shfl_down_sync(0xffffffffu, s, o);
    if ((tid & 31) == 0) sms[wid] = s;
    __syncthreads();
    float mean = (sms[grp * 2] + sms[grp * 2 + 1]) * (1.0f / Dm);
    __syncthreads();

    float d0 = v0 - mean, d1 = v1 - mean, d2 = v2 - mean, d3 = v3 - mean;
    float s2 = d0 * d0 + d1 * d1 + d2 * d2 + d3 * d3;
    #pragma unroll
    for (int o = 16; o > 0; o >>= 1) s2 += __shfl_down_sync(0xffffffffu, s2, o);
    if ((tid & 31) == 0) sms[wid] = s2;
    __syncthreads();
    float var = (sms[grp * 2] + sms[grp * 2 + 1]) * (1.0f / Dm);
    float rs = rsqrtf(var + LN_EPS);

    float4 gv = *reinterpret_cast<const float4*>(g + lt * 4);
    float4 bv = *reinterpret_cast<const float4*>(bb + lt * 4);
    float o0 = d0 * rs * gv.x + bv.x;
    float o1 = d1 * rs * gv.y + bv.y;
    float o2 = d2 * rs * gv.z + bv.z;
    float o3 = d3 * rs * gv.w + bv.w;

    *reinterpret_cast<float4*>(h + base) = make_float4(o0, o1, o2, o3);

    __nv_bfloat16 h0, l0, h1, l1, h2, l2, h3, l3;
    split2(o0, h0, l0); split2(o1, h1, l1); split2(o2, h2, l2); split2(o3, h3, l3);
    __nv_bfloat162 hp0(h0, h1), hp1(h2, h3), lp0(l0, l1), lp1(l2, l3);
    uint2 hw, lw;
    hw.x = *reinterpret_cast<uint32_t*>(&hp0); hw.y = *reinterpret_cast<uint32_t*>(&hp1);
    lw.x = *reinterpret_cast<uint32_t*>(&lp0); lw.y = *reinterpret_cast<uint32_t*>(&lp1);
    *reinterpret_cast<uint2*>(&g_act0[base]) = hw;
    *reinterpret_cast<uint2*>(&g_act0[PL0 + base]) = lw;
}

// ---------------- final head ----------------
__global__ __launch_bounds__(256) void final_head_k(
    const float* __restrict__ lnfg, const float* __restrict__ lnfb,
    const float* __restrict__ Wout, const float* __restrict__ bout)
{
    __shared__ float xn[Dm];
    __shared__ float sm[32];
    const int tid = threadIdx.x;
    const int b = blockIdx.x;
    float v = g_h[(size_t)b * Tt * Dm + tid];
    float mean = bred256(v, sm) * (1.0f / Dm);
    float d = v - mean;
    float var = bred256(d * d, sm) * (1.0f / Dm);
    xn[tid] = d * rsqrtf(var + LN_EPS) * lnfg[tid] + lnfb[tid];
    __syncthreads();
    if (tid < Ed) {
        const float* w = Wout + (size_t)tid * Dm;
        float a = bout[tid];
        #pragma unroll 8
        for (int t = 0; t < Dm; t++) a += xn[t] * w[t];
        g_ze[(size_t)b * Ed + tid] = a;
    }
}

// ---------------- codebook norms + hist zero ----------------
__global__ __launch_bounds__(128) void cnorm_k(const float* __restrict__ cb) {
    __shared__ float sm[4];
    const int tid = threadIdx.x;
    float v = cb[(size_t)blockIdx.x * Ed + tid];
    v *= v;
    #pragma unroll
    for (int o = 16; o > 0; o >>= 1) v += __shfl_down_sync(0xffffffffu, v, o);
    if ((tid & 31) == 0) sm[tid >> 5] = v;
    __syncthreads();
    if (tid == 0) {
        g_cnorm[blockIdx.x] = sm[0] + sm[1] + sm[2] + sm[3];
        g_hist[blockIdx.x] = 0;
    }
}

// ---------------- VQ ----------------
__global__ __launch_bounds__(256) void vq_k(const float* __restrict__ cb) {
    __shared__ float ze[Ed];
    __shared__ float bm[256];
    __shared__ int   bi[256];
    __shared__ int   chosen;
    __shared__ float sm[32];
    const int tid = threadIdx.x;
    const int b = blockIdx.x;
    if (tid < Ed) ze[tid] = g_ze[(size_t)b * Ed + tid];
    __syncthreads();

    float best = 3.4e38f;
    int besti = 0x7fffffff;
    for (int k = tid; k < Kcb; k += 256) {
        const float* c = cb + (size_t)k * Ed;
        float dot = 0.f;
        #pragma unroll 4
        for (int e = 0; e < Ed; e++) dot += ze[e] * c[e];
        float dd = g_cnorm[k] - 2.0f * dot;
        if (dd < best || (dd == best && k < besti)) { best = dd; besti = k; }
    }
    bm[tid] = best; bi[tid] = besti;
    __syncthreads();
    for (int off = 128; off > 0; off >>= 1) {
        if (tid < off) {
            float ob = bm[tid + off]; int oi = bi[tid + off];
            if (ob < bm[tid] || (ob == bm[tid] && oi < bi[tid])) { bm[tid] = ob; bi[tid] = oi; }
        }
        __syncthreads();
    }
    if (tid == 0) {
        chosen = bi[0];
        g_idx[b] = bi[0];
        atomicAdd(&g_hist[bi[0]], 1);
    }
    __syncthreads();

    const int kk = chosen;
    float part = 0.f;
    if (tid < Ed) {
        float diff = cb[(size_t)kk * Ed + tid] - ze[tid];
        part = diff * diff;
    }
    float tot = bred256(part, sm);
    if (tid == 0) g_losspart[b] = tot;
}

// ---------------- decoder ----------------
__global__ __launch_bounds__(256) void decoder_k(
    const float* __restrict__ cb,
    const float* __restrict__ Wd1, const float* __restrict__ bd1,
    const float* __restrict__ lndg, const float* __restrict__ lndb,
    const float* __restrict__ Wd2, const float* __restrict__ bd2,
    const float* __restrict__ Wd3, const float* __restrict__ bd3,
    float* __restrict__ outp)
{
    __shared__ float zq[Ed];
    __shared__ float d1[Dm];
    __shared__ float d2s[Ed];
    __shared__ float sm[32];
    const int tid = threadIdx.x;
    const int b = blockIdx.x;
    const int ci = g_idx[b];
    if (tid < Ed) zq[tid] = cb[(size_t)ci * Ed + tid];
    __syncthreads();

    float t1 = bd1[tid];
    {
        const float* w = Wd1 + (size_t)tid * Ed;
        #pragma unroll 4
        for (int e = 0; e < Ed; e++) t1 += zq[e] * w[e];
    }
    float mean = bred256(t1, sm) * (1.0f / Dm);
    float dd = t1 - mean;
    float var = bred256(dd * dd, sm) * (1.0f / Dm);
    float xg = dd * rsqrtf(var + LN_EPS) * lndg[tid] + lndb[tid];
    d1[tid] = gelu_exact(xg);
    __syncthreads();

    if (tid < Ed) {
        const float* w2 = Wd2 + (size_t)tid * Dm;
        float t2 = bd2[tid];
        #pragma unroll 8
        for (int t = 0; t < Dm; t++) t2 += d1[t] * w2[t];
        d2s[tid] = gelu_exact(t2);
    }
    __syncthreads();

    if (tid < 2) {
        const float* w3 = Wd3 + (size_t)tid * Ed;
        float vv = bd3[tid];
        #pragma unroll 4
        for (int e = 0; e < Ed; e++) vv += d2s[e] * w3[e];
        outp[(size_t)b * 2 + tid] = vv;
    }
    if (tid == 2) outp[(size_t)Bsz * 2 + b] = (float)ci;
}

// ---------------- scalars ----------------
__global__ __launch_bounds__(1024) void scalars_k(float* __restrict__ outp) {
    __shared__ float sm[32];
    const int tid = threadIdx.x;

    float p = (float)g_hist[tid] * (1.0f / (float)Bsz);
    float term = p * logf(p + 1e-10f);
    float v = term;
    #pragma unroll
    for (int o = 16; o > 0; o >>= 1) v += __shfl_down_sync(0xffffffffu, v, o);
    if ((tid & 31) == 0) sm[tid >> 5] = v;
    __syncthreads();
    float ent = 0.f;
    if (tid == 0) {
        for (int i = 0; i < 32; i++) ent += sm[i];
        sm[0] = ent;
    }
    __syncthreads();
    ent = sm[0];
    __syncthreads();

    float lp = g_losspart[tid] + g_losspart[tid + 1024];
    #pragma unroll
    for (int o = 16; o > 0; o >>= 1) lp += __shfl_down_sync(0xffffffffu, lp, o);
    if ((tid & 31) == 0) sm[tid >> 5] = lp;
    __syncthreads();
    if (tid == 0) {
        float tot = 0.f;
        for (int i = 0; i < 32; i++) tot += sm[i];
        outp[(size_t)Bsz * 2 + Bsz + 0] = 0.1f * tot / ((float)Bsz * (float)Ed);
        outp[(size_t)Bsz * 2 + Bsz + 1] = expf(-ent);
    }
}

// ---------------- host ----------------
template <typename T>
static T* sym_addr(const void* sym) {
    void* p = nullptr;
    cudaGetSymbolAddress(&p, sym);
    return (T*)p;
}

extern "C" void kernel_launch(void* const* d_in, const int* in_sizes, int n_in,
                              void* d_out, int out_size)
{
    (void)in_sizes; (void)n_in; (void)out_size;
    const float* x     = (const float*)d_in[0];
    const float* W_in  = (const float*)d_in[1];
    const float* b_in  = (const float*)d_in[2];
    const float* cls   = (const float*)d_in[3];
    const float* Wqkv  = (const float*)d_in[4];
    const float* bqkv  = (const float*)d_in[5];
    const float* Wo    = (const float*)d_in[6];
    const float* bo    = (const float*)d_in[7];
    const float* W1    = (const float*)d_in[8];
    const float* b1    = (const float*)d_in[9];
    const float* W2    = (const float*)d_in[10];
    const float* b2    = (const float*)d_in[11];
    const float* ln1g  = (const float*)d_in[12];
    const float* ln1b  = (const float*)d_in[13];
    const float* ln2g  = (const float*)d_in[14];
    const float* ln2b  = (const float*)d_in[15];
    const float* lnfg  = (const float*)d_in[16];
    const float* lnfb  = (const float*)d_in[17];
    const float* Wout  = (const float*)d_in[18];
    const float* bout  = (const float*)d_in[19];
    const float* cb    = (const float*)d_in[20];
    const float* Wd1   = (const float*)d_in[21];
    const float* bd1   = (const float*)d_in[22];
    const float* lndg  = (const float*)d_in[23];
    const float* lndb  = (const float*)d_in[24];
    const float* Wd2   = (const float*)d_in[25];
    const float* bd2   = (const float*)d_in[26];
    const float* Wd3   = (const float*)d_in[27];
    const float* bd3   = (const float*)d_in[28];
    float* outp = (float*)d_out;

    float* pH    = sym_addr<float>(g_h);
    float* pTmp  = sym_addr<float>(g_tmp);
    __nv_bfloat16* pAct0 = sym_addr<__nv_bfloat16>(g_act0);
    __nv_bfloat16* pAct1 = sym_addr<__nv_bfloat16>(g_act1);
    __nv_bfloat16* pXb   = sym_addr<__nv_bfloat16>(g_xb);
    __nv_bfloat16* pWin  = sym_addr<__nv_bfloat16>(g_winb);
    __nv_bfloat16* pWq = sym_addr<__nv_bfloat16>(g_wqkvb);
    __nv_bfloat16* pWo = sym_addr<__nv_bfloat16>(g_wob);
    __nv_bfloat16* pW1 = sym_addr<__nv_bfloat16>(g_w1b);
    __nv_bfloat16* pW2 = sym_addr<__nv_bfloat16>(g_w2b);

    cudaFuncSetAttribute(bfgemm_k<0>, cudaFuncAttributeMaxDynamicSharedMemorySize, SMEM_DYN);
    cudaFuncSetAttribute(bfgemm_k<1>, cudaFuncAttributeMaxDynamicSharedMemorySize, SMEM_DYN);
    cudaFuncSetAttribute(bfgemm_k<2>, cudaFuncAttributeMaxDynamicSharedMemorySize, SMEM_DYN);
    cudaFuncSetAttribute(bfgemm_k<3>, cudaFuncAttributeMaxDynamicSharedMemorySize, SMEM_DYN);

    convw_k<<<1024, 256>>>(Wqkv, Wo, W1, W2);                       // 1
    prep_k<<<2048, 256>>>(x, W_in, cls);                            // 2
    bfgemm_k<3><<<dim3(Dm / 128, MIN0 / 128), 256, SMEM_DYN>>>(
        pXb, PLX, pWin, (size_t)Dm * KIN, b_in, nullptr, MIN0, Dm, KIN); // 3

    for (int i = 0; i < NL; i++) {
        bfgemm_k<2><<<dim3(768 / 128, MTOK / 128), 256, SMEM_DYN>>>(
            pAct0, PL0, pWq + (size_t)i * 2 * WQKV_SZ, (size_t)WQKV_SZ,
            bqkv + (size_t)i * 3 * Dm, nullptr, MTOK, 3 * Dm, Dm);  // 4 on i=0
        attn_k<<<Bsz * NH, 256>>>();
        bfgemm_k<0><<<dim3(Dm / 128, MTOK / 128), 256, SMEM_DYN>>>(
            pAct0, PL0, pWo + (size_t)i * 2 * WO_SZ, (size_t)WO_SZ,
            bo + (size_t)i * Dm, pTmp, MTOK, Dm, Dm);
        add_ln_k<<<MTOK / 4, 256>>>(pH, pTmp, ln1g + (size_t)i * Dm, ln1b + (size_t)i * Dm);
        bfgemm_k<1><<<dim3(FFd / 128, MTOK / 128), 256, SMEM_DYN>>>(
            pAct0, PL0, pW1 + (size_t)i * 2 * W1_SZ, (size_t)W1_SZ,
            b1 + (size_t)i * FFd, nullptr, MTOK, FFd, Dm);
        bfgemm_k<0><<<dim3(Dm / 128, MTOK / 128), 256, SMEM_DYN>>>(
            pAct1, PL1, pW2 + (size_t)i * 2 * W2_SZ, (size_t)W2_SZ,
            b2 + (size_t)i * Dm, pTmp, MTOK, Dm, FFd);
        add_ln_k<<<MTOK / 4, 256>>>(pH, pTmp, ln2g + (size_t)i * Dm, ln2b + (size_t)i * Dm);
    }

    cnorm_k<<<Kcb, 128>>>(cb);
    final_head_k<<<Bsz, 256>>>(lnfg, lnfb, Wout, bout);
    vq_k<<<Bsz, 256>>>(cb);
    decoder_k<<<Bsz, 256>>>(cb, Wd1, bd1, lndg, lndb, Wd2, bd2, Wd3, bd3, outp);
    scalars_k<<<1, 1024>>>(outp);
}